// round 7
// baseline (speedup 1.0000x reference)
#include <cuda_runtime.h>
#include <cuda_bf16.h>
#include <math.h>
#include <stdint.h>

// ---------------- problem constants ----------------
#define CB   2
#define CS   4096
#define CH   12
#define CD   64
#define CW   256
#define CDM  768
#define CDFF 3072
#define CNB  16
#define CL   2
#define CNEG (-1000000000.0f)
#define CSCALE 0.125f

#define MROWS (CB*CS)    // 8192
#define QKV_S 2304
#define GKV_S 1536

// ---------------- scratch ----------------
__device__ float g_x   [MROWS*CDM];
__device__ float g_y   [MROWS*CDM];
__device__ float g_attn[MROWS*CDM];
__device__ float g_qkv [(size_t)MROWS*QKV_S];
__device__ float g_gkv [(size_t)MROWS*GKV_S];
__device__ float g_qg  [CB*CDM];
__device__ float g_bias[QKV_S];
__device__ __nv_bfloat16 g_xb[(size_t)MROWS*3*CDM];
__device__ __nv_bfloat16 g_hb[(size_t)MROWS*3*CDFF];
__device__ __nv_bfloat16 g_wb[(size_t)3*CDFF*CDM];

// ---------------- helpers ----------------
__device__ __forceinline__ float gelu_tanh(float x) {
    float x3 = x * x * x;
    return 0.5f * x * (1.0f + tanhf(0.7978845608028654f * (x + 0.044715f * x3)));
}
__device__ __forceinline__ uint32_t smem_u32(const void* p) {
    uint32_t a;
    asm("{ .reg .u64 t; cvta.to.shared.u64 t, %1; cvt.u32.u64 %0, t; }" : "=r"(a) : "l"(p));
    return a;
}
__device__ __forceinline__ void split_write(__nv_bfloat16* dst, size_t ro, int K, int k, float v) {
    __nv_bfloat16 hi = __float2bfloat16_rn(v);
    __nv_bfloat16 lo = __float2bfloat16_rn(v - __bfloat162float(hi));
    dst[ro + k] = hi;
    dst[ro + K + k] = lo;
    dst[ro + 2 * K + k] = hi;
}

// ================= split/convert kernels =================
__global__ void split_act_kernel(const float* __restrict__ A,
                                 __nv_bfloat16* __restrict__ Ap, int K) {
    int idx = blockIdx.x * 256 + threadIdx.x;
    int m = idx / K, k = idx - m * K;
    split_write(Ap, (size_t)m * (3 * K), K, k, A[idx]);
}

__global__ void split_wt_kernel(const float* __restrict__ W,
                                __nv_bfloat16* __restrict__ Wt, int K, int N) {
    __shared__ float t[32][33];
    int n0 = blockIdx.x * 32, k0 = blockIdx.y * 32;
    int tx = threadIdx.x, ty = threadIdx.y;   // 32 x 8
    #pragma unroll
    for (int r = 0; r < 4; r++) {
        int k = k0 + ty + r * 8;
        t[ty + r * 8][tx] = W[(size_t)k * N + n0 + tx];
    }
    __syncthreads();
    #pragma unroll
    for (int r = 0; r < 4; r++) {
        int n = n0 + ty + r * 8;
        int k = k0 + tx;
        float a = t[tx][ty + r * 8];
        __nv_bfloat16 hi = __float2bfloat16_rn(a);
        __nv_bfloat16 lo = __float2bfloat16_rn(a - __bfloat162float(hi));
        size_t ro = (size_t)n * (3 * K);
        Wt[ro + k] = hi;
        Wt[ro + K + k] = hi;
        Wt[ro + 2 * K + k] = lo;
    }
}

__global__ void pack_bias_kernel(float* __restrict__ dst,
                                 const float* __restrict__ s0,
                                 const float* __restrict__ s1,
                                 const float* __restrict__ s2) {
    int i = blockIdx.x * 256 + threadIdx.x;
    int s = i / 768, r = i - s * 768;
    const float* p = (s == 0) ? s0 : (s == 1 ? s1 : s2);
    dst[i] = p[r];
}

// ================= warp-MMA bf16 GEMM =================
// CTA tile 128(M) x 256(N), 8 warps 2x4, warp tile 64x64, BK=32,
// 4-stage cp.async. SMEM stage: A 128x80B + B 256x80B = 30720B.
#define A_BYTES 10240           // 128 * 80
#define B_BYTES 20480           // 256 * 80
#define STG_BYTES (A_BYTES + B_BYTES)
#define GSM_TOT (4*STG_BYTES)   // 122880

__device__ __forceinline__ void ldm_x4(uint32_t addr, uint32_t& r0, uint32_t& r1,
                                       uint32_t& r2, uint32_t& r3) {
    asm volatile("ldmatrix.sync.aligned.m8n8.x4.shared.b16 {%0,%1,%2,%3}, [%4];"
        : "=r"(r0), "=r"(r1), "=r"(r2), "=r"(r3) : "r"(addr));
}
__device__ __forceinline__ void mma_bf16(float* c, const uint32_t* a, const uint32_t* b) {
    asm volatile("mma.sync.aligned.m16n8k16.row.col.f32.bf16.bf16.f32 "
        "{%0,%1,%2,%3}, {%4,%5,%6,%7}, {%8,%9}, {%0,%1,%2,%3};"
        : "+f"(c[0]), "+f"(c[1]), "+f"(c[2]), "+f"(c[3])
        : "r"(a[0]), "r"(a[1]), "r"(a[2]), "r"(a[3]), "r"(b[0]), "r"(b[1]));
}

// mode 0: Cf = acc+bias ; mode 1: +GELU ; mode 2: Cb = bf16-split(gelu), [row][3N]
__global__ __launch_bounds__(256)
void gemm_mma_kernel(const __nv_bfloat16* __restrict__ A,
                     const __nv_bfloat16* __restrict__ Bt,
                     const float* __restrict__ bias,
                     float* __restrict__ Cf,
                     __nv_bfloat16* __restrict__ Cb,
                     int Kp, int N, int mode) {
    extern __shared__ __align__(1024) char smem[];
    uint32_t sb = smem_u32(smem);
    int tid = threadIdx.x;
    int wid = tid >> 5, lane = tid & 31;
    int m0 = blockIdx.y * 128, n0 = blockIdx.x * 256;
    int warp_m = (wid & 1) * 64;
    int warp_n = (wid >> 1) * 64;
    int NC = Kp / 32;

    const __nv_bfloat16* Ag = A  + (size_t)m0 * Kp;
    const __nv_bfloat16* Bg = Bt + (size_t)n0 * Kp;

    float acc[4][8][4];
    #pragma unroll
    for (int i = 0; i < 4; i++)
        #pragma unroll
        for (int j = 0; j < 8; j++)
            #pragma unroll
            for (int r = 0; r < 4; r++) acc[i][j][r] = 0.f;

    // per-chunk: A 512 16B-chunks, B 1024 chunks; 6 per thread
    auto load_tile = [&](int c, int bf) {
        uint32_t abase = sb + bf * STG_BYTES;
        uint32_t bbase = abase + A_BYTES;
        const __nv_bfloat16* Ac = Ag + (size_t)c * 32;
        const __nv_bfloat16* Bc = Bg + (size_t)c * 32;
        #pragma unroll
        for (int i = 0; i < 2; i++) {
            int ch = i * 256 + tid;           // 0..511 -> A
            int r = ch >> 2, c8 = (ch & 3) * 8;
            uint32_t ad = abase + r * 80 + c8 * 2;
            const void* as = Ac + (size_t)r * Kp + c8;
            asm volatile("cp.async.cg.shared.global [%0], [%1], 16;" :: "r"(ad), "l"(as));
        }
        #pragma unroll
        for (int i = 0; i < 4; i++) {
            int ch = i * 256 + tid;           // 0..1023 -> B
            int r = ch >> 2, c8 = (ch & 3) * 8;
            uint32_t bd = bbase + r * 80 + c8 * 2;
            const void* bs = Bc + (size_t)r * Kp + c8;
            asm volatile("cp.async.cg.shared.global [%0], [%1], 16;" :: "r"(bd), "l"(bs));
        }
    };

    load_tile(0, 0);
    asm volatile("cp.async.commit_group;" ::: "memory");
    load_tile(1, 1);
    asm volatile("cp.async.commit_group;" ::: "memory");
    load_tile(2, 2);
    asm volatile("cp.async.commit_group;" ::: "memory");

    int rsel = lane & 15, hsel = (lane >> 4) * 16;
    int bf = 0;
    for (int c = 0; c < NC; c++) {
        asm volatile("cp.async.wait_group 2;" ::: "memory");
        __syncthreads();
        if (c + 3 < NC) load_tile(c + 3, (bf + 3) & 3);
        asm volatile("cp.async.commit_group;" ::: "memory");

        uint32_t abase = sb + bf * STG_BYTES;
        uint32_t bbase = abase + A_BYTES;

        #pragma unroll
        for (int ks = 0; ks < 2; ks++) {
            uint32_t a[4][4], b[8][2];
            #pragma unroll
            for (int mi = 0; mi < 4; mi++) {
                uint32_t ad = abase + (warp_m + mi * 16 + rsel) * 80 + ks * 32 + hsel;
                ldm_x4(ad, a[mi][0], a[mi][1], a[mi][2], a[mi][3]);
            }
            #pragma unroll
            for (int np = 0; np < 4; np++) {
                uint32_t r0, r1, r2, r3;
                uint32_t bd = bbase + (warp_n + np * 16 + rsel) * 80 + ks * 32 + hsel;
                ldm_x4(bd, r0, r1, r2, r3);
                b[np * 2 + 0][0] = r0; b[np * 2 + 0][1] = r2;
                b[np * 2 + 1][0] = r1; b[np * 2 + 1][1] = r3;
            }
            #pragma unroll
            for (int mi = 0; mi < 4; mi++)
                #pragma unroll
                for (int nj = 0; nj < 8; nj++)
                    mma_bf16(acc[mi][nj], a[mi], b[nj]);
        }
        bf = (bf + 1) & 3;
    }

    // epilogue
    int g = lane >> 2, t = lane & 3;
    #pragma unroll
    for (int mi = 0; mi < 4; mi++) {
        int row0 = m0 + warp_m + mi * 16 + g;
        #pragma unroll
        for (int nj = 0; nj < 8; nj++) {
            int col = n0 + warp_n + nj * 8 + t * 2;
            float bx = bias[col], by = bias[col + 1];
            float v0 = acc[mi][nj][0] + bx, v1 = acc[mi][nj][1] + by;
            float v2 = acc[mi][nj][2] + bx, v3 = acc[mi][nj][3] + by;
            if (mode >= 1) { v0 = gelu_tanh(v0); v1 = gelu_tanh(v1); v2 = gelu_tanh(v2); v3 = gelu_tanh(v3); }
            if (mode == 2) {
                #pragma unroll
                for (int rr = 0; rr < 2; rr++) {
                    int row = row0 + rr * 8;
                    float a0 = rr ? v2 : v0, a1 = rr ? v3 : v1;
                    __nv_bfloat16 h0 = __float2bfloat16_rn(a0);
                    __nv_bfloat16 l0 = __float2bfloat16_rn(a0 - __bfloat162float(h0));
                    __nv_bfloat16 h1 = __float2bfloat16_rn(a1);
                    __nv_bfloat16 l1 = __float2bfloat16_rn(a1 - __bfloat162float(h1));
                    size_t ro = (size_t)row * (3 * N);
                    *(__nv_bfloat162*)&Cb[ro + col]         = __halves2bfloat162(h0, h1);
                    *(__nv_bfloat162*)&Cb[ro + N + col]     = __halves2bfloat162(l0, l1);
                    *(__nv_bfloat162*)&Cb[ro + 2 * N + col] = __halves2bfloat162(h0, h1);
                }
            } else {
                *(float2*)&Cf[(size_t)row0 * N + col]       = make_float2(v0, v1);
                *(float2*)&Cf[(size_t)(row0 + 8) * N + col] = make_float2(v2, v3);
            }
        }
    }
}

// ================= fused flash band attention =================
#define FS_Q  0
#define FS_K  4096
#define FS_V  8192
#define FS_P  12288      // Ps[64][72]
#define FS_K0 16896
#define FS_V0 16960
#define FS_TOT ((16960 + 64) * 4)

__global__ __launch_bounds__(256)
void flash_band_kernel(const float* __restrict__ qkv,
                       const int* __restrict__ am,
                       float* __restrict__ out) {
    extern __shared__ float fsm[];
    int z = blockIdx.y;
    int n = z % CNB;
    int h = (z / CNB) % CH;
    int b = z / (CNB * CH);
    int qt = blockIdx.x;
    int tid = threadIdx.x;
    int tx = tid & 15, ty = tid >> 4;

    int base_s    = n * CW + qt * 64;
    int base_kpos = n * CW - CW;

    #pragma unroll
    for (int i = 0; i < 4; i++) {
        int sid = tid + i * 256;
        int r = sid >> 4, c4 = (sid & 15) << 2;
        float4 vq = *(const float4*)&qkv[((size_t)(b * CS + base_s + r)) * QKV_S + h * 64 + c4];
        fsm[FS_Q + (c4 + 0) * 64 + r] = vq.x * CSCALE;
        fsm[FS_Q + (c4 + 1) * 64 + r] = vq.y * CSCALE;
        fsm[FS_Q + (c4 + 2) * 64 + r] = vq.z * CSCALE;
        fsm[FS_Q + (c4 + 3) * 64 + r] = vq.w * CSCALE;
    }
    if (tid < 64) {
        fsm[FS_K0 + tid] = qkv[((size_t)(b * CS)) * QKV_S + 768 + h * 64 + tid];
        fsm[FS_V0 + tid] = qkv[((size_t)(b * CS)) * QKV_S + 1536 + h * 64 + tid];
    }

    float mst[4], lst[4], acc[4][4];
    #pragma unroll
    for (int i = 0; i < 4; i++) {
        mst[i] = -1e30f; lst[i] = 0.f;
        #pragma unroll
        for (int j = 0; j < 4; j++) acc[i][j] = 0.f;
    }
    int am0 = am[b * CS];

    for (int kc = 0; kc < 12; kc++) {
        __syncthreads();
        #pragma unroll
        for (int i = 0; i < 4; i++) {
            int sid = tid + i * 256;
            int r = sid >> 4, c4 = (sid & 15) << 2;
            int kpos = base_kpos + kc * 64 + r;
            float4 vk = make_float4(0.f, 0.f, 0.f, 0.f);
            float4 vv = make_float4(0.f, 0.f, 0.f, 0.f);
            if (kpos >= 0 && kpos < CS) {
                size_t rb = ((size_t)(b * CS + kpos)) * QKV_S + h * 64 + c4;
                vk = *(const float4*)&qkv[rb + 768];
                vv = *(const float4*)&qkv[rb + 1536];
            }
            fsm[FS_K + (c4 + 0) * 64 + r] = vk.x;
            fsm[FS_K + (c4 + 1) * 64 + r] = vk.y;
            fsm[FS_K + (c4 + 2) * 64 + r] = vk.z;
            fsm[FS_K + (c4 + 3) * 64 + r] = vk.w;
            *(float4*)&fsm[FS_V + r * 64 + c4] = vv;
        }
        __syncthreads();

        float s[4][4];
        #pragma unroll
        for (int i = 0; i < 4; i++)
            #pragma unroll
            for (int j = 0; j < 4; j++) s[i][j] = 0.f;
        #pragma unroll 8
        for (int kk = 0; kk < 64; kk++) {
            float a[4], bb[4];
            *(float4*)a  = *(const float4*)&fsm[FS_Q + kk * 64 + ty * 4];
            *(float4*)bb = *(const float4*)&fsm[FS_K + kk * 64 + tx * 4];
            #pragma unroll
            for (int i = 0; i < 4; i++)
                #pragma unroll
                for (int j = 0; j < 4; j++)
                    s[i][j] += a[i] * bb[j];
        }

        #pragma unroll
        for (int i = 0; i < 4; i++) {
            int qi = qt * 64 + ty * 4 + i;
            #pragma unroll
            for (int j = 0; j < 4; j++) {
                int kj = kc * 64 + tx * 4 + j;
                int kpos = base_kpos + kj;
                bool ok = (kj >= qi) && (kj <= qi + 2 * CW) &&
                          (kpos >= 0) && (kpos < CS) && (kpos != 0) &&
                          (am[b * CS + (kpos & (CS - 1))] > 0);
                if (!ok) s[i][j] = CNEG;
            }
        }

        #pragma unroll
        for (int i = 0; i < 4; i++) {
            float cm = fmaxf(fmaxf(s[i][0], s[i][1]), fmaxf(s[i][2], s[i][3]));
            #pragma unroll
            for (int o = 1; o < 16; o <<= 1)
                cm = fmaxf(cm, __shfl_xor_sync(0xffffffffu, cm, o));
            float nm = fmaxf(mst[i], cm);
            float alpha = __expf(mst[i] - nm);
            mst[i] = nm;
            float rs = 0.f;
            #pragma unroll
            for (int j = 0; j < 4; j++) {
                s[i][j] = __expf(s[i][j] - nm);
                rs += s[i][j];
            }
            #pragma unroll
            for (int o = 1; o < 16; o <<= 1)
                rs += __shfl_xor_sync(0xffffffffu, rs, o);
            lst[i] = lst[i] * alpha + rs;
            #pragma unroll
            for (int j = 0; j < 4; j++) acc[i][j] *= alpha;
            int qi = ty * 4 + i;
            *(float4*)&fsm[FS_P + qi * 72 + tx * 4] = make_float4(s[i][0], s[i][1], s[i][2], s[i][3]);
        }
        __syncthreads();

        #pragma unroll 4
        for (int kk = 0; kk < 64; kk++) {
            float bb[4];
            *(float4*)bb = *(const float4*)&fsm[FS_V + kk * 64 + tx * 4];
            #pragma unroll
            for (int i = 0; i < 4; i++) {
                float a = fsm[FS_P + (ty * 4 + i) * 72 + kk];
                #pragma unroll
                for (int j = 0; j < 4; j++) acc[i][j] += a * bb[j];
            }
        }
    }

    #pragma unroll
    for (int i = 0; i < 4; i++) {
        int row = ty * 4 + i;
        float sg = 0.f;
        #pragma unroll
        for (int e = 0; e < 4; e++) {
            int d = tx * 4 + e;
            sg += fsm[FS_Q + d * 64 + row] * fsm[FS_K0 + d];
        }
        #pragma unroll
        for (int o = 1; o < 16; o <<= 1)
            sg += __shfl_xor_sync(0xffffffffu, sg, o);
        if (am0 <= 0) sg = CNEG;
        float nm = fmaxf(mst[i], sg);
        float alpha = __expf(mst[i] - nm);
        float pg = __expf(sg - nm);
        float l = lst[i] * alpha + pg;
        float inv = 1.0f / l;
        int sgl = base_s + row;
        float o4[4];
        #pragma unroll
        for (int j = 0; j < 4; j++) {
            int d = tx * 4 + j;
            o4[j] = (acc[i][j] * alpha + pg * fsm[FS_V0 + d]) * inv;
        }
        *(float4*)&out[((size_t)(b * CS + sgl)) * CDM + h * 64 + tx * 4] =
            make_float4(o4[0], o4[1], o4[2], o4[3]);
    }
}

// ================= small kernels =================
__device__ __forceinline__ float block_reduce_sum256(float v, float* red) {
    int tid = threadIdx.x;
    red[tid] = v; __syncthreads();
    #pragma unroll
    for (int o = 128; o > 0; o >>= 1) {
        if (tid < o) red[tid] += red[tid + o];
        __syncthreads();
    }
    float r = red[0]; __syncthreads();
    return r;
}

__global__ void embed_ln_kernel(const int* __restrict__ ids,
                                const float* __restrict__ we,
                                const float* __restrict__ pe,
                                const float* __restrict__ gam,
                                const float* __restrict__ bet,
                                float* __restrict__ x,
                                __nv_bfloat16* __restrict__ xb) {
    __shared__ float red[256];
    int row = blockIdx.x;
    int s = row % CS;
    int id = ids[row];
    int tid = threadIdx.x;
    const float* wp = we + (size_t)id * CDM;
    const float* pp = pe + (size_t)s * CDM;
    float e[3];
    float sm = 0.f;
    #pragma unroll
    for (int i = 0; i < 3; i++) { int d = tid + i * 256; e[i] = wp[d] + pp[d]; sm += e[i]; }
    float mean = block_reduce_sum256(sm, red) * (1.0f / CDM);
    float vs = 0.f;
    #pragma unroll
    for (int i = 0; i < 3; i++) { float t = e[i] - mean; vs += t * t; }
    float var = block_reduce_sum256(vs, red) * (1.0f / CDM);
    float inv = rsqrtf(var + 1e-5f);
    float* xr = x + (size_t)row * CDM;
    size_t ro = (size_t)row * (3 * CDM);
    #pragma unroll
    for (int i = 0; i < 3; i++) {
        int d = tid + i * 256;
        float val = (e[i] - mean) * inv * gam[d] + bet[d];
        xr[d] = val;
        split_write(xb, ro, CDM, d, val);
    }
}

__global__ void add_ln_kernel(float* __restrict__ x,
                              const float* __restrict__ y,
                              const float* __restrict__ gam,
                              const float* __restrict__ bet,
                              __nv_bfloat16* __restrict__ xb) {
    __shared__ float red[256];
    int row = blockIdx.x;
    int tid = threadIdx.x;
    float* xr = x + (size_t)row * CDM;
    const float* yr = y + (size_t)row * CDM;
    float e[3];
    float sm = 0.f;
    #pragma unroll
    for (int i = 0; i < 3; i++) { int d = tid + i * 256; e[i] = xr[d] + yr[d]; sm += e[i]; }
    float mean = block_reduce_sum256(sm, red) * (1.0f / CDM);
    float vs = 0.f;
    #pragma unroll
    for (int i = 0; i < 3; i++) { float t = e[i] - mean; vs += t * t; }
    float var = block_reduce_sum256(vs, red) * (1.0f / CDM);
    float inv = rsqrtf(var + 1e-5f);
    size_t ro = (size_t)row * (3 * CDM);
    #pragma unroll
    for (int i = 0; i < 3; i++) {
        int d = tid + i * 256;
        float val = (e[i] - mean) * inv * gam[d] + bet[d];
        xr[d] = val;
        split_write(xb, ro, CDM, d, val);
    }
}

__global__ void qg_kernel(const float* __restrict__ x,
                          const float* __restrict__ Wqg,
                          const float* __restrict__ bqg,
                          float* __restrict__ qg) {
    int nidx = blockIdx.x * 256 + threadIdx.x;
    int b = blockIdx.y;
    const float* xr = x + (size_t)(b * CS) * CDM;
    float acc = bqg[nidx];
    for (int kk = 0; kk < CDM; kk++)
        acc += xr[kk] * Wqg[(size_t)kk * CDM + nidx];
    qg[b * CDM + nidx] = acc * CSCALE;
}

__global__ void global_attn_kernel(const float* __restrict__ qg,
                                   const float* __restrict__ gkv,
                                   const int* __restrict__ am,
                                   float* __restrict__ out) {
    __shared__ float scs[CS];
    __shared__ float red[256];
    __shared__ float qs[64];
    int h = blockIdx.x, b = blockIdx.y;
    int tid = threadIdx.x;
    if (tid < 64) qs[tid] = qg[b * CDM + h * 64 + tid];
    __syncthreads();

    float mx = -1e30f;
    for (int s = tid; s < CS; s += 256) {
        const float* kp = &gkv[((size_t)(b * CS + s)) * GKV_S + h * 64];
        float dd = 0.f;
        #pragma unroll
        for (int e = 0; e < 64; e++) dd += qs[e] * kp[e];
        if (am[b * CS + s] <= 0) dd = CNEG;
        scs[s] = dd;
        mx = fmaxf(mx, dd);
    }
    red[tid] = mx; __syncthreads();
    #pragma unroll
    for (int o = 128; o > 0; o >>= 1) {
        if (tid < o) red[tid] = fmaxf(red[tid], red[tid + o]);
        __syncthreads();
    }
    mx = red[0]; __syncthreads();

    float sm = 0.f;
    for (int s = tid; s < CS; s += 256) {
        float e = __expf(scs[s] - mx);
        scs[s] = e; sm += e;
    }
    float tot = block_reduce_sum256(sm, red);
    float inv = 1.0f / tot;
    __syncthreads();

    int d = tid & 63, sl = tid >> 6;
    float acc = 0.f;
    for (int s = sl * 1024; s < (sl + 1) * 1024; s++)
        acc += scs[s] * gkv[((size_t)(b * CS + s)) * GKV_S + 768 + h * 64 + d];
    red[tid] = acc; __syncthreads();
    if (sl == 0) {
        float t = red[d] + red[64 + d] + red[128 + d] + red[192 + d];
        out[((size_t)(b * CS)) * CDM + h * 64 + d] = t * inv;
    }
}

__global__ void cls_kernel(const float* __restrict__ x,
                           const float* __restrict__ Wc,
                           const float* __restrict__ bc,
                           float* __restrict__ out) {
    __shared__ float red[256];
    int b = blockIdx.x >> 1, c = blockIdx.x & 1;
    int tid = threadIdx.x;
    const float* xr = x + (size_t)(b * CS) * CDM;
    float acc = 0.f;
    for (int d = tid; d < CDM; d += 256) acc += xr[d] * Wc[d * 2 + c];
    float tot = block_reduce_sum256(acc, red);
    if (tid == 0) out[b * 2 + c] = tot + bc[c];
}

// ================= launch =================
extern "C" void kernel_launch(void* const* d_in, const int* in_sizes, int n_in,
                              void* d_out, int out_size) {
    const int*   ids  = (const int*)d_in[0];
    const int*   am   = (const int*)d_in[1];
    const float* we   = (const float*)d_in[2];
    const float* pe   = (const float*)d_in[3];
    const float* lnes = (const float*)d_in[4];
    const float* lneb = (const float*)d_in[5];
    const float* Wq   = (const float*)d_in[6];
    const float* bq   = (const float*)d_in[7];
    const float* Wk   = (const float*)d_in[8];
    const float* bk   = (const float*)d_in[9];
    const float* Wv   = (const float*)d_in[10];
    const float* bv   = (const float*)d_in[11];
    const float* Wqg  = (const float*)d_in[12];
    const float* bqg  = (const float*)d_in[13];
    const float* Wkg  = (const float*)d_in[14];
    const float* bkg  = (const float*)d_in[15];
    const float* Wvg  = (const float*)d_in[16];
    const float* bvg  = (const float*)d_in[17];
    const float* Wo   = (const float*)d_in[18];
    const float* bo   = (const float*)d_in[19];
    const float* ln1s = (const float*)d_in[20];
    const float* ln1b = (const float*)d_in[21];
    const float* W1   = (const float*)d_in[22];
    const float* b1   = (const float*)d_in[23];
    const float* W2   = (const float*)d_in[24];
    const float* b2   = (const float*)d_in[25];
    const float* ln2s = (const float*)d_in[26];
    const float* ln2b = (const float*)d_in[27];
    const float* Wcls = (const float*)d_in[28];
    const float* bcls = (const float*)d_in[29];
    float* out = (float*)d_out;

    float *xp, *yp, *ap, *qkvp, *gkvp, *qgp, *biasp;
    __nv_bfloat16 *xbp, *hbp, *wbp;
    cudaGetSymbolAddress((void**)&xp,   g_x);
    cudaGetSymbolAddress((void**)&yp,   g_y);
    cudaGetSymbolAddress((void**)&ap,   g_attn);
    cudaGetSymbolAddress((void**)&qkvp, g_qkv);
    cudaGetSymbolAddress((void**)&gkvp, g_gkv);
    cudaGetSymbolAddress((void**)&qgp,  g_qg);
    cudaGetSymbolAddress((void**)&biasp, g_bias);
    cudaGetSymbolAddress((void**)&xbp,  g_xb);
    cudaGetSymbolAddress((void**)&hbp,  g_hb);
    cudaGetSymbolAddress((void**)&wbp,  g_wb);

    cudaFuncSetAttribute(gemm_mma_kernel, cudaFuncAttributeMaxDynamicSharedMemorySize, GSM_TOT);
    cudaFuncSetAttribute(flash_band_kernel, cudaFuncAttributeMaxDynamicSharedMemorySize, FS_TOT);

    embed_ln_kernel<<<MROWS, 256>>>(ids, we, pe, lnes, lneb, xp, xbp);

    dim3 wt_dm(CDM / 32, CDM / 32);
    dim3 wt_b(32, 8);
    size_t wseg = (size_t)CDM * 3 * CDM;
    int actK = MROWS * CDM / 256;

    for (int l = 0; l < CL; l++) {
        size_t woff = (size_t)l * CDM * CDM;
        size_t boff = (size_t)l * CDM;
        size_t w1off = (size_t)l * CDM * CDFF;
        size_t b1off = (size_t)l * CDFF;
        size_t w2off = (size_t)l * CDFF * CDM;

        // --- fused QKV ---
        split_wt_kernel<<<wt_dm, wt_b>>>(Wq + woff, wbp,            CDM, CDM);
        split_wt_kernel<<<wt_dm, wt_b>>>(Wk + woff, wbp + wseg,     CDM, CDM);
        split_wt_kernel<<<wt_dm, wt_b>>>(Wv + woff, wbp + 2 * wseg, CDM, CDM);
        pack_bias_kernel<<<9, 256>>>(biasp, bq + boff, bk + boff, bv + boff);
        gemm_mma_kernel<<<dim3(QKV_S / 256, MROWS / 128), 256, GSM_TOT>>>(
            xbp, wbp, biasp, qkvp, nullptr, 3 * CDM, QKV_S, 0);

        flash_band_kernel<<<dim3(4, CB * CH * CNB), 256, FS_TOT>>>(qkvp, am, ap);

        // --- fused Kg/Vg + global attention ---
        qg_kernel<<<dim3(CDM / 256, CB), 256>>>(xp, Wqg + woff, bqg + boff, qgp);
        split_wt_kernel<<<wt_dm, wt_b>>>(Wkg + woff, wbp,        CDM, CDM);
        split_wt_kernel<<<wt_dm, wt_b>>>(Wvg + woff, wbp + wseg, CDM, CDM);
        pack_bias_kernel<<<6, 256>>>(biasp, bkg + boff, bvg + boff, bvg + boff);
        gemm_mma_kernel<<<dim3(GKV_S / 256, MROWS / 128), 256, GSM_TOT>>>(
            xbp, wbp, biasp, gkvp, nullptr, 3 * CDM, GKV_S, 0);
        global_attn_kernel<<<dim3(CH, CB), 256>>>(qgp, gkvp, am, ap);

        // --- Wo projection + LN1 ---
        split_act_kernel<<<actK, 256>>>(ap, xbp, CDM);
        split_wt_kernel<<<wt_dm, wt_b>>>(Wo + woff, wbp, CDM, CDM);
        gemm_mma_kernel<<<dim3(CDM / 256, MROWS / 128), 256, GSM_TOT>>>(
            xbp, wbp, bo + boff, yp, nullptr, 3 * CDM, CDM, 0);
        add_ln_kernel<<<MROWS, 256>>>(xp, yp, ln1s + boff, ln1b + boff, xbp);

        // --- FFN ---
        split_wt_kernel<<<dim3(CDFF / 32, CDM / 32), wt_b>>>(W1 + w1off, wbp, CDM, CDFF);
        gemm_mma_kernel<<<dim3(CDFF / 256, MROWS / 128), 256, GSM_TOT>>>(
            xbp, wbp, b1 + b1off, nullptr, hbp, 3 * CDM, CDFF, 2);

        split_wt_kernel<<<dim3(CDM / 32, CDFF / 32), wt_b>>>(W2 + w2off, wbp, CDFF, CDM);
        gemm_mma_kernel<<<dim3(CDM / 256, MROWS / 128), 256, GSM_TOT>>>(
            hbp, wbp, b2 + boff, yp, nullptr, 3 * CDFF, CDM, 0);
        add_ln_kernel<<<MROWS, 256>>>(xp, yp, ln2s + boff, ln2b + boff, xbp);
    }

    cls_kernel<<<4, 256>>>(xp, Wcls, bcls, out);
}

// round 8
// speedup vs baseline: 1.1177x; 1.1177x over previous
#include <cuda_runtime.h>
#include <cuda_bf16.h>
#include <math.h>
#include <stdint.h>

// ---------------- problem constants ----------------
#define CB   2
#define CS   4096
#define CH   12
#define CD   64
#define CW   256
#define CDM  768
#define CDFF 3072
#define CNB  16
#define CL   2
#define CNEG (-1000000000.0f)
#define CSCALE 0.125f

#define MROWS (CB*CS)    // 8192
#define QKV_S 2304
#define GKV_S 1536

// ---------------- scratch ----------------
__device__ float g_x   [MROWS*CDM];
__device__ float g_y   [MROWS*CDM];
__device__ float g_attn[MROWS*CDM];
__device__ float g_qkv [(size_t)MROWS*QKV_S];
__device__ float g_gkv [(size_t)MROWS*GKV_S];
__device__ float g_qg  [CB*CDM];
__device__ float g_bias[QKV_S];
// hi/lo bf16 operand buffers
__device__ __nv_bfloat16 g_xbh[(size_t)MROWS*CDM];
__device__ __nv_bfloat16 g_xbl[(size_t)MROWS*CDM];
__device__ __nv_bfloat16 g_hbh[(size_t)MROWS*CDFF];
__device__ __nv_bfloat16 g_hbl[(size_t)MROWS*CDFF];
__device__ __nv_bfloat16 g_wbh[(size_t)CDFF*CDM];   // transposed weights [N][K]
__device__ __nv_bfloat16 g_wbl[(size_t)CDFF*CDM];

// ---------------- helpers ----------------
__device__ __forceinline__ float gelu_tanh(float x) {
    float x3 = x * x * x;
    return 0.5f * x * (1.0f + tanhf(0.7978845608028654f * (x + 0.044715f * x3)));
}
__device__ __forceinline__ uint32_t smem_u32(const void* p) {
    uint32_t a;
    asm("{ .reg .u64 t; cvta.to.shared.u64 t, %1; cvt.u32.u64 %0, t; }" : "=r"(a) : "l"(p));
    return a;
}
__device__ __forceinline__ void hilo(float v, __nv_bfloat16& h, __nv_bfloat16& l) {
    h = __float2bfloat16_rn(v);
    l = __float2bfloat16_rn(v - __bfloat162float(h));
}

// ================= split/convert kernels =================
__global__ void split_act_kernel(const float* __restrict__ A,
                                 __nv_bfloat16* __restrict__ Ah,
                                 __nv_bfloat16* __restrict__ Al) {
    int idx = blockIdx.x * 256 + threadIdx.x;
    __nv_bfloat16 h, l;
    hilo(A[idx], h, l);
    Ah[idx] = h; Al[idx] = l;
}

__global__ void split_wt_kernel(const float* __restrict__ W,
                                __nv_bfloat16* __restrict__ Wth,
                                __nv_bfloat16* __restrict__ Wtl, int K, int N) {
    __shared__ float t[32][33];
    int n0 = blockIdx.x * 32, k0 = blockIdx.y * 32;
    int tx = threadIdx.x, ty = threadIdx.y;   // 32 x 8
    #pragma unroll
    for (int r = 0; r < 4; r++) {
        int k = k0 + ty + r * 8;
        t[ty + r * 8][tx] = W[(size_t)k * N + n0 + tx];
    }
    __syncthreads();
    #pragma unroll
    for (int r = 0; r < 4; r++) {
        int n = n0 + ty + r * 8;
        int k = k0 + tx;
        __nv_bfloat16 h, l;
        hilo(t[tx][ty + r * 8], h, l);
        size_t ro = (size_t)n * K + k;
        Wth[ro] = h;
        Wtl[ro] = l;
    }
}

__global__ void pack_bias_kernel(float* __restrict__ dst,
                                 const float* __restrict__ s0,
                                 const float* __restrict__ s1,
                                 const float* __restrict__ s2) {
    int i = blockIdx.x * 256 + threadIdx.x;
    int s = i / 768, r = i - s * 768;
    const float* p = (s == 0) ? s0 : (s == 1 ? s1 : s2);
    dst[i] = p[r];
}

// ================= warp-MMA bf16 GEMM (hi/lo fragment reuse) =================
// CTA tile 128x128, 8 warps 2x4, warp tile 64x32, BK=32 real K.
// Per (a,b) fragment pair: 3 MMAs (ah*bh, al*bh, ah*bl).
// Stage: Ah|Al|Bh|Bl each 128 rows x 80B = 40960B; 3 stages.
#define MAT_B 10240
#define STG_BYTES (4*MAT_B)
#define GSM_TOT (3*STG_BYTES)   // 122880

__device__ __forceinline__ void ldm_x4(uint32_t addr, uint32_t& r0, uint32_t& r1,
                                       uint32_t& r2, uint32_t& r3) {
    asm volatile("ldmatrix.sync.aligned.m8n8.x4.shared.b16 {%0,%1,%2,%3}, [%4];"
        : "=r"(r0), "=r"(r1), "=r"(r2), "=r"(r3) : "r"(addr));
}
__device__ __forceinline__ void mma_bf16(float* c, const uint32_t* a, const uint32_t* b) {
    asm volatile("mma.sync.aligned.m16n8k16.row.col.f32.bf16.bf16.f32 "
        "{%0,%1,%2,%3}, {%4,%5,%6,%7}, {%8,%9}, {%0,%1,%2,%3};"
        : "+f"(c[0]), "+f"(c[1]), "+f"(c[2]), "+f"(c[3])
        : "r"(a[0]), "r"(a[1]), "r"(a[2]), "r"(a[3]), "r"(b[0]), "r"(b[1]));
}

// mode 0: Cf = acc+bias ; mode 1: +GELU ; mode 2: hi/lo bf16(gelu) -> Cbh/Cbl
__global__ __launch_bounds__(256)
void gemm_mma_kernel(const __nv_bfloat16* __restrict__ Ah,
                     const __nv_bfloat16* __restrict__ Al,
                     const __nv_bfloat16* __restrict__ Bh,
                     const __nv_bfloat16* __restrict__ Bl,
                     const float* __restrict__ bias,
                     float* __restrict__ Cf,
                     __nv_bfloat16* __restrict__ Cbh,
                     __nv_bfloat16* __restrict__ Cbl,
                     int Kp, int N, int mode) {
    extern __shared__ __align__(1024) char smem[];
    uint32_t sb = smem_u32(smem);
    int tid = threadIdx.x;
    int wid = tid >> 5, lane = tid & 31;
    int m0 = blockIdx.y * 128, n0 = blockIdx.x * 128;
    int warp_m = (wid & 1) * 64;
    int warp_n = (wid >> 1) * 32;
    int NC = Kp / 32;

    const __nv_bfloat16* Agh = Ah + (size_t)m0 * Kp;
    const __nv_bfloat16* Agl = Al + (size_t)m0 * Kp;
    const __nv_bfloat16* Bgh = Bh + (size_t)n0 * Kp;
    const __nv_bfloat16* Bgl = Bl + (size_t)n0 * Kp;

    float acc[4][4][4];
    #pragma unroll
    for (int i = 0; i < 4; i++)
        #pragma unroll
        for (int j = 0; j < 4; j++)
            #pragma unroll
            for (int r = 0; r < 4; r++) acc[i][j][r] = 0.f;

    // one stage = 4 matrices x 512 16B-chunks = 2048 chunks; 8 per thread
    auto load_tile = [&](int c, int bf) {
        uint32_t base = sb + bf * STG_BYTES;
        const __nv_bfloat16* srcs[4] = {
            Agh + (size_t)c * 32, Agl + (size_t)c * 32,
            Bgh + (size_t)c * 32, Bgl + (size_t)c * 32 };
        #pragma unroll
        for (int m = 0; m < 4; m++) {
            const __nv_bfloat16* S = srcs[m];
            uint32_t mb = base + m * MAT_B;
            #pragma unroll
            for (int i = 0; i < 2; i++) {
                int ch = i * 256 + tid;           // 0..511
                int r = ch >> 2, c8 = (ch & 3) * 8;
                uint32_t d = mb + r * 80 + c8 * 2;
                const void* s = S + (size_t)r * Kp + c8;
                asm volatile("cp.async.cg.shared.global [%0], [%1], 16;" :: "r"(d), "l"(s));
            }
        }
    };

    load_tile(0, 0);
    asm volatile("cp.async.commit_group;" ::: "memory");
    load_tile(1, 1);
    asm volatile("cp.async.commit_group;" ::: "memory");

    int rsel = lane & 15, hsel = (lane >> 4) * 16;
    int bf = 0;
    for (int c = 0; c < NC; c++) {
        asm volatile("cp.async.wait_group 1;" ::: "memory");
        __syncthreads();
        int nbf = bf + 2; if (nbf >= 3) nbf -= 3;
        if (c + 2 < NC) load_tile(c + 2, nbf);
        asm volatile("cp.async.commit_group;" ::: "memory");

        uint32_t ahb = sb + bf * STG_BYTES;
        uint32_t alb = ahb + MAT_B;
        uint32_t bhb = ahb + 2 * MAT_B;
        uint32_t blb = ahb + 3 * MAT_B;

        #pragma unroll
        for (int ks = 0; ks < 2; ks++) {
            uint32_t ah[4][4], al[4][4], bh[4][2], bl[4][2];
            #pragma unroll
            for (int mi = 0; mi < 4; mi++) {
                uint32_t off = (warp_m + mi * 16 + rsel) * 80 + ks * 32 + hsel;
                ldm_x4(ahb + off, ah[mi][0], ah[mi][1], ah[mi][2], ah[mi][3]);
                ldm_x4(alb + off, al[mi][0], al[mi][1], al[mi][2], al[mi][3]);
            }
            #pragma unroll
            for (int np = 0; np < 2; np++) {
                uint32_t off = (warp_n + np * 16 + rsel) * 80 + ks * 32 + hsel;
                uint32_t r0, r1, r2, r3;
                ldm_x4(bhb + off, r0, r1, r2, r3);
                bh[np * 2 + 0][0] = r0; bh[np * 2 + 0][1] = r2;
                bh[np * 2 + 1][0] = r1; bh[np * 2 + 1][1] = r3;
                ldm_x4(blb + off, r0, r1, r2, r3);
                bl[np * 2 + 0][0] = r0; bl[np * 2 + 0][1] = r2;
                bl[np * 2 + 1][0] = r1; bl[np * 2 + 1][1] = r3;
            }
            // term 1: ah*bh (16 independent mmas)
            #pragma unroll
            for (int mi = 0; mi < 4; mi++)
                #pragma unroll
                for (int nj = 0; nj < 4; nj++)
                    mma_bf16(acc[mi][nj], ah[mi], bh[nj]);
            // term 2: al*bh
            #pragma unroll
            for (int mi = 0; mi < 4; mi++)
                #pragma unroll
                for (int nj = 0; nj < 4; nj++)
                    mma_bf16(acc[mi][nj], al[mi], bh[nj]);
            // term 3: ah*bl
            #pragma unroll
            for (int mi = 0; mi < 4; mi++)
                #pragma unroll
                for (int nj = 0; nj < 4; nj++)
                    mma_bf16(acc[mi][nj], ah[mi], bl[nj]);
        }
        bf++; if (bf >= 3) bf = 0;
    }

    // epilogue
    int g = lane >> 2, t = lane & 3;
    #pragma unroll
    for (int mi = 0; mi < 4; mi++) {
        int row0 = m0 + warp_m + mi * 16 + g;
        #pragma unroll
        for (int nj = 0; nj < 4; nj++) {
            int col = n0 + warp_n + nj * 8 + t * 2;
            float bx = bias[col], by = bias[col + 1];
            float v0 = acc[mi][nj][0] + bx, v1 = acc[mi][nj][1] + by;
            float v2 = acc[mi][nj][2] + bx, v3 = acc[mi][nj][3] + by;
            if (mode >= 1) { v0 = gelu_tanh(v0); v1 = gelu_tanh(v1); v2 = gelu_tanh(v2); v3 = gelu_tanh(v3); }
            if (mode == 2) {
                #pragma unroll
                for (int rr = 0; rr < 2; rr++) {
                    int row = row0 + rr * 8;
                    float a0 = rr ? v2 : v0, a1 = rr ? v3 : v1;
                    __nv_bfloat16 h0, l0, h1, l1;
                    hilo(a0, h0, l0);
                    hilo(a1, h1, l1);
                    size_t ro = (size_t)row * N + col;
                    *(__nv_bfloat162*)&Cbh[ro] = __halves2bfloat162(h0, h1);
                    *(__nv_bfloat162*)&Cbl[ro] = __halves2bfloat162(l0, l1);
                }
            } else {
                *(float2*)&Cf[(size_t)row0 * N + col]       = make_float2(v0, v1);
                *(float2*)&Cf[(size_t)(row0 + 8) * N + col] = make_float2(v2, v3);
            }
        }
    }
}

// ================= fused flash band attention =================
#define FS_Q  0
#define FS_K  4096
#define FS_V  8192
#define FS_P  12288      // Ps[64][72]
#define FS_K0 16896
#define FS_V0 16960
#define FS_TOT ((16960 + 64) * 4)

__global__ __launch_bounds__(256)
void flash_band_kernel(const float* __restrict__ qkv,
                       const int* __restrict__ am,
                       float* __restrict__ out) {
    extern __shared__ float fsm[];
    int z = blockIdx.y;
    int n = z % CNB;
    int h = (z / CNB) % CH;
    int b = z / (CNB * CH);
    int qt = blockIdx.x;
    int tid = threadIdx.x;
    int tx = tid & 15, ty = tid >> 4;

    int base_s    = n * CW + qt * 64;
    int base_kpos = n * CW - CW;

    #pragma unroll
    for (int i = 0; i < 4; i++) {
        int sid = tid + i * 256;
        int r = sid >> 4, c4 = (sid & 15) << 2;
        float4 vq = *(const float4*)&qkv[((size_t)(b * CS + base_s + r)) * QKV_S + h * 64 + c4];
        fsm[FS_Q + (c4 + 0) * 64 + r] = vq.x * CSCALE;
        fsm[FS_Q + (c4 + 1) * 64 + r] = vq.y * CSCALE;
        fsm[FS_Q + (c4 + 2) * 64 + r] = vq.z * CSCALE;
        fsm[FS_Q + (c4 + 3) * 64 + r] = vq.w * CSCALE;
    }
    if (tid < 64) {
        fsm[FS_K0 + tid] = qkv[((size_t)(b * CS)) * QKV_S + 768 + h * 64 + tid];
        fsm[FS_V0 + tid] = qkv[((size_t)(b * CS)) * QKV_S + 1536 + h * 64 + tid];
    }

    float mst[4], lst[4], acc[4][4];
    #pragma unroll
    for (int i = 0; i < 4; i++) {
        mst[i] = -1e30f; lst[i] = 0.f;
        #pragma unroll
        for (int j = 0; j < 4; j++) acc[i][j] = 0.f;
    }
    int am0 = am[b * CS];

    for (int kc = 0; kc < 12; kc++) {
        __syncthreads();
        #pragma unroll
        for (int i = 0; i < 4; i++) {
            int sid = tid + i * 256;
            int r = sid >> 4, c4 = (sid & 15) << 2;
            int kpos = base_kpos + kc * 64 + r;
            float4 vk = make_float4(0.f, 0.f, 0.f, 0.f);
            float4 vv = make_float4(0.f, 0.f, 0.f, 0.f);
            if (kpos >= 0 && kpos < CS) {
                size_t rb = ((size_t)(b * CS + kpos)) * QKV_S + h * 64 + c4;
                vk = *(const float4*)&qkv[rb + 768];
                vv = *(const float4*)&qkv[rb + 1536];
            }
            fsm[FS_K + (c4 + 0) * 64 + r] = vk.x;
            fsm[FS_K + (c4 + 1) * 64 + r] = vk.y;
            fsm[FS_K + (c4 + 2) * 64 + r] = vk.z;
            fsm[FS_K + (c4 + 3) * 64 + r] = vk.w;
            *(float4*)&fsm[FS_V + r * 64 + c4] = vv;
        }
        __syncthreads();

        float s[4][4];
        #pragma unroll
        for (int i = 0; i < 4; i++)
            #pragma unroll
            for (int j = 0; j < 4; j++) s[i][j] = 0.f;
        #pragma unroll 8
        for (int kk = 0; kk < 64; kk++) {
            float a[4], bb[4];
            *(float4*)a  = *(const float4*)&fsm[FS_Q + kk * 64 + ty * 4];
            *(float4*)bb = *(const float4*)&fsm[FS_K + kk * 64 + tx * 4];
            #pragma unroll
            for (int i = 0; i < 4; i++)
                #pragma unroll
                for (int j = 0; j < 4; j++)
                    s[i][j] += a[i] * bb[j];
        }

        #pragma unroll
        for (int i = 0; i < 4; i++) {
            int qi = qt * 64 + ty * 4 + i;
            #pragma unroll
            for (int j = 0; j < 4; j++) {
                int kj = kc * 64 + tx * 4 + j;
                int kpos = base_kpos + kj;
                bool ok = (kj >= qi) && (kj <= qi + 2 * CW) &&
                          (kpos >= 0) && (kpos < CS) && (kpos != 0) &&
                          (am[b * CS + (kpos & (CS - 1))] > 0);
                if (!ok) s[i][j] = CNEG;
            }
        }

        #pragma unroll
        for (int i = 0; i < 4; i++) {
            float cm = fmaxf(fmaxf(s[i][0], s[i][1]), fmaxf(s[i][2], s[i][3]));
            #pragma unroll
            for (int o = 1; o < 16; o <<= 1)
                cm = fmaxf(cm, __shfl_xor_sync(0xffffffffu, cm, o));
            float nm = fmaxf(mst[i], cm);
            float alpha = __expf(mst[i] - nm);
            mst[i] = nm;
            float rs = 0.f;
            #pragma unroll
            for (int j = 0; j < 4; j++) {
                s[i][j] = __expf(s[i][j] - nm);
                rs += s[i][j];
            }
            #pragma unroll
            for (int o = 1; o < 16; o <<= 1)
                rs += __shfl_xor_sync(0xffffffffu, rs, o);
            lst[i] = lst[i] * alpha + rs;
            #pragma unroll
            for (int j = 0; j < 4; j++) acc[i][j] *= alpha;
            int qi = ty * 4 + i;
            *(float4*)&fsm[FS_P + qi * 72 + tx * 4] = make_float4(s[i][0], s[i][1], s[i][2], s[i][3]);
        }
        __syncthreads();

        #pragma unroll 4
        for (int kk = 0; kk < 64; kk++) {
            float bb[4];
            *(float4*)bb = *(const float4*)&fsm[FS_V + kk * 64 + tx * 4];
            #pragma unroll
            for (int i = 0; i < 4; i++) {
                float a = fsm[FS_P + (ty * 4 + i) * 72 + kk];
                #pragma unroll
                for (int j = 0; j < 4; j++) acc[i][j] += a * bb[j];
            }
        }
    }

    #pragma unroll
    for (int i = 0; i < 4; i++) {
        int row = ty * 4 + i;
        float sg = 0.f;
        #pragma unroll
        for (int e = 0; e < 4; e++) {
            int d = tx * 4 + e;
            sg += fsm[FS_Q + d * 64 + row] * fsm[FS_K0 + d];
        }
        #pragma unroll
        for (int o = 1; o < 16; o <<= 1)
            sg += __shfl_xor_sync(0xffffffffu, sg, o);
        if (am0 <= 0) sg = CNEG;
        float nm = fmaxf(mst[i], sg);
        float alpha = __expf(mst[i] - nm);
        float pg = __expf(sg - nm);
        float l = lst[i] * alpha + pg;
        float inv = 1.0f / l;
        int sgl = base_s + row;
        float o4[4];
        #pragma unroll
        for (int j = 0; j < 4; j++) {
            int d = tx * 4 + j;
            o4[j] = (acc[i][j] * alpha + pg * fsm[FS_V0 + d]) * inv;
        }
        *(float4*)&out[((size_t)(b * CS + sgl)) * CDM + h * 64 + tx * 4] =
            make_float4(o4[0], o4[1], o4[2], o4[3]);
    }
}

// ================= small kernels =================
__device__ __forceinline__ float block_reduce_sum256(float v, float* red) {
    int tid = threadIdx.x;
    red[tid] = v; __syncthreads();
    #pragma unroll
    for (int o = 128; o > 0; o >>= 1) {
        if (tid < o) red[tid] += red[tid + o];
        __syncthreads();
    }
    float r = red[0]; __syncthreads();
    return r;
}

__global__ void embed_ln_kernel(const int* __restrict__ ids,
                                const float* __restrict__ we,
                                const float* __restrict__ pe,
                                const float* __restrict__ gam,
                                const float* __restrict__ bet,
                                float* __restrict__ x,
                                __nv_bfloat16* __restrict__ xh,
                                __nv_bfloat16* __restrict__ xl) {
    __shared__ float red[256];
    int row = blockIdx.x;
    int s = row % CS;
    int id = ids[row];
    int tid = threadIdx.x;
    const float* wp = we + (size_t)id * CDM;
    const float* pp = pe + (size_t)s * CDM;
    float e[3];
    float sm = 0.f;
    #pragma unroll
    for (int i = 0; i < 3; i++) { int d = tid + i * 256; e[i] = wp[d] + pp[d]; sm += e[i]; }
    float mean = block_reduce_sum256(sm, red) * (1.0f / CDM);
    float vs = 0.f;
    #pragma unroll
    for (int i = 0; i < 3; i++) { float t = e[i] - mean; vs += t * t; }
    float var = block_reduce_sum256(vs, red) * (1.0f / CDM);
    float inv = rsqrtf(var + 1e-5f);
    float* xr = x + (size_t)row * CDM;
    size_t ro = (size_t)row * CDM;
    #pragma unroll
    for (int i = 0; i < 3; i++) {
        int d = tid + i * 256;
        float val = (e[i] - mean) * inv * gam[d] + bet[d];
        xr[d] = val;
        __nv_bfloat16 h, l;
        hilo(val, h, l);
        xh[ro + d] = h; xl[ro + d] = l;
    }
}

__global__ void add_ln_kernel(float* __restrict__ x,
                              const float* __restrict__ y,
                              const float* __restrict__ gam,
                              const float* __restrict__ bet,
                              __nv_bfloat16* __restrict__ xh,
                              __nv_bfloat16* __restrict__ xl) {
    __shared__ float red[256];
    int row = blockIdx.x;
    int tid = threadIdx.x;
    float* xr = x + (size_t)row * CDM;
    const float* yr = y + (size_t)row * CDM;
    float e[3];
    float sm = 0.f;
    #pragma unroll
    for (int i = 0; i < 3; i++) { int d = tid + i * 256; e[i] = xr[d] + yr[d]; sm += e[i]; }
    float mean = block_reduce_sum256(sm, red) * (1.0f / CDM);
    float vs = 0.f;
    #pragma unroll
    for (int i = 0; i < 3; i++) { float t = e[i] - mean; vs += t * t; }
    float var = block_reduce_sum256(vs, red) * (1.0f / CDM);
    float inv = rsqrtf(var + 1e-5f);
    size_t ro = (size_t)row * CDM;
    #pragma unroll
    for (int i = 0; i < 3; i++) {
        int d = tid + i * 256;
        float val = (e[i] - mean) * inv * gam[d] + bet[d];
        xr[d] = val;
        __nv_bfloat16 h, l;
        hilo(val, h, l);
        xh[ro + d] = h; xl[ro + d] = l;
    }
}

__global__ void qg_kernel(const float* __restrict__ x,
                          const float* __restrict__ Wqg,
                          const float* __restrict__ bqg,
                          float* __restrict__ qg) {
    int nidx = blockIdx.x * 256 + threadIdx.x;
    int b = blockIdx.y;
    const float* xr = x + (size_t)(b * CS) * CDM;
    float acc = bqg[nidx];
    for (int kk = 0; kk < CDM; kk++)
        acc += xr[kk] * Wqg[(size_t)kk * CDM + nidx];
    qg[b * CDM + nidx] = acc * CSCALE;
}

__global__ void global_attn_kernel(const float* __restrict__ qg,
                                   const float* __restrict__ gkv,
                                   const int* __restrict__ am,
                                   float* __restrict__ out) {
    __shared__ float scs[CS];
    __shared__ float red[256];
    __shared__ float qs[64];
    int h = blockIdx.x, b = blockIdx.y;
    int tid = threadIdx.x;
    if (tid < 64) qs[tid] = qg[b * CDM + h * 64 + tid];
    __syncthreads();

    float mx = -1e30f;
    for (int s = tid; s < CS; s += 256) {
        const float* kp = &gkv[((size_t)(b * CS + s)) * GKV_S + h * 64];
        float dd = 0.f;
        #pragma unroll
        for (int e = 0; e < 64; e++) dd += qs[e] * kp[e];
        if (am[b * CS + s] <= 0) dd = CNEG;
        scs[s] = dd;
        mx = fmaxf(mx, dd);
    }
    red[tid] = mx; __syncthreads();
    #pragma unroll
    for (int o = 128; o > 0; o >>= 1) {
        if (tid < o) red[tid] = fmaxf(red[tid], red[tid + o]);
        __syncthreads();
    }
    mx = red[0]; __syncthreads();

    float sm = 0.f;
    for (int s = tid; s < CS; s += 256) {
        float e = __expf(scs[s] - mx);
        scs[s] = e; sm += e;
    }
    float tot = block_reduce_sum256(sm, red);
    float inv = 1.0f / tot;
    __syncthreads();

    int d = tid & 63, sl = tid >> 6;
    float acc = 0.f;
    for (int s = sl * 1024; s < (sl + 1) * 1024; s++)
        acc += scs[s] * gkv[((size_t)(b * CS + s)) * GKV_S + 768 + h * 64 + d];
    red[tid] = acc; __syncthreads();
    if (sl == 0) {
        float t = red[d] + red[64 + d] + red[128 + d] + red[192 + d];
        out[((size_t)(b * CS)) * CDM + h * 64 + d] = t * inv;
    }
}

__global__ void cls_kernel(const float* __restrict__ x,
                           const float* __restrict__ Wc,
                           const float* __restrict__ bc,
                           float* __restrict__ out) {
    __shared__ float red[256];
    int b = blockIdx.x >> 1, c = blockIdx.x & 1;
    int tid = threadIdx.x;
    const float* xr = x + (size_t)(b * CS) * CDM;
    float acc = 0.f;
    for (int d = tid; d < CDM; d += 256) acc += xr[d] * Wc[d * 2 + c];
    float tot = block_reduce_sum256(acc, red);
    if (tid == 0) out[b * 2 + c] = tot + bc[c];
}

// ================= launch =================
extern "C" void kernel_launch(void* const* d_in, const int* in_sizes, int n_in,
                              void* d_out, int out_size) {
    const int*   ids  = (const int*)d_in[0];
    const int*   am   = (const int*)d_in[1];
    const float* we   = (const float*)d_in[2];
    const float* pe   = (const float*)d_in[3];
    const float* lnes = (const float*)d_in[4];
    const float* lneb = (const float*)d_in[5];
    const float* Wq   = (const float*)d_in[6];
    const float* bq   = (const float*)d_in[7];
    const float* Wk   = (const float*)d_in[8];
    const float* bk   = (const float*)d_in[9];
    const float* Wv   = (const float*)d_in[10];
    const float* bv   = (const float*)d_in[11];
    const float* Wqg  = (const float*)d_in[12];
    const float* bqg  = (const float*)d_in[13];
    const float* Wkg  = (const float*)d_in[14];
    const float* bkg  = (const float*)d_in[15];
    const float* Wvg  = (const float*)d_in[16];
    const float* bvg  = (const float*)d_in[17];
    const float* Wo   = (const float*)d_in[18];
    const float* bo   = (const float*)d_in[19];
    const float* ln1s = (const float*)d_in[20];
    const float* ln1b = (const float*)d_in[21];
    const float* W1   = (const float*)d_in[22];
    const float* b1   = (const float*)d_in[23];
    const float* W2   = (const float*)d_in[24];
    const float* b2   = (const float*)d_in[25];
    const float* ln2s = (const float*)d_in[26];
    const float* ln2b = (const float*)d_in[27];
    const float* Wcls = (const float*)d_in[28];
    const float* bcls = (const float*)d_in[29];
    float* out = (float*)d_out;

    float *xp, *yp, *ap, *qkvp, *gkvp, *qgp, *biasp;
    __nv_bfloat16 *xhp, *xlp, *hhp, *hlp, *whp, *wlp;
    cudaGetSymbolAddress((void**)&xp,   g_x);
    cudaGetSymbolAddress((void**)&yp,   g_y);
    cudaGetSymbolAddress((void**)&ap,   g_attn);
    cudaGetSymbolAddress((void**)&qkvp, g_qkv);
    cudaGetSymbolAddress((void**)&gkvp, g_gkv);
    cudaGetSymbolAddress((void**)&qgp,  g_qg);
    cudaGetSymbolAddress((void**)&biasp, g_bias);
    cudaGetSymbolAddress((void**)&xhp,  g_xbh);
    cudaGetSymbolAddress((void**)&xlp,  g_xbl);
    cudaGetSymbolAddress((void**)&hhp,  g_hbh);
    cudaGetSymbolAddress((void**)&hlp,  g_hbl);
    cudaGetSymbolAddress((void**)&whp,  g_wbh);
    cudaGetSymbolAddress((void**)&wlp,  g_wbl);

    cudaFuncSetAttribute(gemm_mma_kernel, cudaFuncAttributeMaxDynamicSharedMemorySize, GSM_TOT);
    cudaFuncSetAttribute(flash_band_kernel, cudaFuncAttributeMaxDynamicSharedMemorySize, FS_TOT);

    embed_ln_kernel<<<MROWS, 256>>>(ids, we, pe, lnes, lneb, xp, xhp, xlp);

    dim3 wt_dm(CDM / 32, CDM / 32);
    dim3 wt_b(32, 8);
    size_t wseg = (size_t)CDM * CDM;      // one transposed weight block (768x768)
    int actK = MROWS * CDM / 256;

    for (int l = 0; l < CL; l++) {
        size_t woff = (size_t)l * CDM * CDM;
        size_t boff = (size_t)l * CDM;
        size_t w1off = (size_t)l * CDM * CDFF;
        size_t b1off = (size_t)l * CDFF;
        size_t w2off = (size_t)l * CDFF * CDM;

        // --- fused QKV ---
        split_wt_kernel<<<wt_dm, wt_b>>>(Wq + woff, whp,            wlp,            CDM, CDM);
        split_wt_kernel<<<wt_dm, wt_b>>>(Wk + woff, whp + wseg,     wlp + wseg,     CDM, CDM);
        split_wt_kernel<<<wt_dm, wt_b>>>(Wv + woff, whp + 2 * wseg, wlp + 2 * wseg, CDM, CDM);
        pack_bias_kernel<<<9, 256>>>(biasp, bq + boff, bk + boff, bv + boff);
        gemm_mma_kernel<<<dim3(QKV_S / 128, MROWS / 128), 256, GSM_TOT>>>(
            xhp, xlp, whp, wlp, biasp, qkvp, nullptr, nullptr, CDM, QKV_S, 0);

        flash_band_kernel<<<dim3(4, CB * CH * CNB), 256, FS_TOT>>>(qkvp, am, ap);

        // --- fused Kg/Vg + global attention ---
        qg_kernel<<<dim3(CDM / 256, CB), 256>>>(xp, Wqg + woff, bqg + boff, qgp);
        split_wt_kernel<<<wt_dm, wt_b>>>(Wkg + woff, whp,        wlp,        CDM, CDM);
        split_wt_kernel<<<wt_dm, wt_b>>>(Wvg + woff, whp + wseg, wlp + wseg, CDM, CDM);
        pack_bias_kernel<<<6, 256>>>(biasp, bkg + boff, bvg + boff, bvg + boff);
        gemm_mma_kernel<<<dim3(GKV_S / 128, MROWS / 128), 256, GSM_TOT>>>(
            xhp, xlp, whp, wlp, biasp, gkvp, nullptr, nullptr, CDM, GKV_S, 0);
        global_attn_kernel<<<dim3(CH, CB), 256>>>(qgp, gkvp, am, ap);

        // --- Wo projection + LN1 ---
        split_act_kernel<<<actK, 256>>>(ap, xhp, xlp);
        split_wt_kernel<<<wt_dm, wt_b>>>(Wo + woff, whp, wlp, CDM, CDM);
        gemm_mma_kernel<<<dim3(CDM / 128, MROWS / 128), 256, GSM_TOT>>>(
            xhp, xlp, whp, wlp, bo + boff, yp, nullptr, nullptr, CDM, CDM, 0);
        add_ln_kernel<<<MROWS, 256>>>(xp, yp, ln1s + boff, ln1b + boff, xhp, xlp);

        // --- FFN ---
        split_wt_kernel<<<dim3(CDFF / 32, CDM / 32), wt_b>>>(W1 + w1off, whp, wlp, CDM, CDFF);
        gemm_mma_kernel<<<dim3(CDFF / 128, MROWS / 128), 256, GSM_TOT>>>(
            xhp, xlp, whp, wlp, b1 + b1off, nullptr, hhp, hlp, CDM, CDFF, 2);

        split_wt_kernel<<<dim3(CDM / 32, CDFF / 32), wt_b>>>(W2 + w2off, whp, wlp, CDFF, CDM);
        gemm_mma_kernel<<<dim3(CDM / 128, MROWS / 128), 256, GSM_TOT>>>(
            hhp, hlp, whp, wlp, b2 + boff, yp, nullptr, nullptr, CDFF, CDM, 0);
        add_ln_kernel<<<MROWS, 256>>>(xp, yp, ln2s + boff, ln2b + boff, xhp, xlp);
    }

    cls_kernel<<<4, 256>>>(xp, Wcls, bcls, out);
}

// round 9
// speedup vs baseline: 1.3490x; 1.2069x over previous
#include <cuda_runtime.h>
#include <cuda_bf16.h>
#include <math.h>
#include <stdint.h>

// ---------------- problem constants ----------------
#define CB   2
#define CS   4096
#define CH   12
#define CD   64
#define CW   256
#define CDM  768
#define CDFF 3072
#define CNB  16
#define CL   2
#define CNEG (-1000000000.0f)
#define CSCALE 0.125f

#define MROWS (CB*CS)    // 8192
#define QKV_S 2304
#define GKV_S 1536

// ---------------- scratch ----------------
__device__ float g_x   [MROWS*CDM];
__device__ float g_y   [MROWS*CDM];
__device__ float g_attn[MROWS*CDM];
__device__ float g_qkv [(size_t)MROWS*QKV_S];
__device__ float g_gkv [(size_t)MROWS*GKV_S];
__device__ float g_qg  [CB*CDM];
__device__ float g_bias[QKV_S];
// hi/lo bf16 operand buffers
__device__ __nv_bfloat16 g_xbh[(size_t)MROWS*CDM];
__device__ __nv_bfloat16 g_xbl[(size_t)MROWS*CDM];
__device__ __nv_bfloat16 g_hbh[(size_t)MROWS*CDFF];
__device__ __nv_bfloat16 g_hbl[(size_t)MROWS*CDFF];
__device__ __nv_bfloat16 g_wbh[(size_t)CDFF*CDM];   // transposed weights [N][K]
__device__ __nv_bfloat16 g_wbl[(size_t)CDFF*CDM];

// ---------------- helpers ----------------
__device__ __forceinline__ float gelu_tanh(float x) {
    float x3 = x * x * x;
    return 0.5f * x * (1.0f + tanhf(0.7978845608028654f * (x + 0.044715f * x3)));
}
__device__ __forceinline__ uint32_t smem_u32(const void* p) {
    uint32_t a;
    asm("{ .reg .u64 t; cvta.to.shared.u64 t, %1; cvt.u32.u64 %0, t; }" : "=r"(a) : "l"(p));
    return a;
}
__device__ __forceinline__ void hilo(float v, __nv_bfloat16& h, __nv_bfloat16& l) {
    h = __float2bfloat16_rn(v);
    l = __float2bfloat16_rn(v - __bfloat162float(h));
}
// pack two floats into bf16x2 hi + residual lo
__device__ __forceinline__ void hilo2(float a, float b, uint32_t& h, uint32_t& l) {
    __nv_bfloat16 ha, la, hb, lb;
    hilo(a, ha, la);
    hilo(b, hb, lb);
    __nv_bfloat162 hh = __halves2bfloat162(ha, hb);
    __nv_bfloat162 ll = __halves2bfloat162(la, lb);
    h = *(uint32_t*)&hh;
    l = *(uint32_t*)&ll;
}

// ================= split/convert kernels =================
__global__ void split_act_kernel(const float* __restrict__ A,
                                 __nv_bfloat16* __restrict__ Ah,
                                 __nv_bfloat16* __restrict__ Al) {
    int idx = blockIdx.x * 256 + threadIdx.x;
    __nv_bfloat16 h, l;
    hilo(A[idx], h, l);
    Ah[idx] = h; Al[idx] = l;
}

__global__ void split_wt_kernel(const float* __restrict__ W,
                                __nv_bfloat16* __restrict__ Wth,
                                __nv_bfloat16* __restrict__ Wtl, int K, int N) {
    __shared__ float t[32][33];
    int n0 = blockIdx.x * 32, k0 = blockIdx.y * 32;
    int tx = threadIdx.x, ty = threadIdx.y;   // 32 x 8
    #pragma unroll
    for (int r = 0; r < 4; r++) {
        int k = k0 + ty + r * 8;
        t[ty + r * 8][tx] = W[(size_t)k * N + n0 + tx];
    }
    __syncthreads();
    #pragma unroll
    for (int r = 0; r < 4; r++) {
        int n = n0 + ty + r * 8;
        int k = k0 + tx;
        __nv_bfloat16 h, l;
        hilo(t[tx][ty + r * 8], h, l);
        size_t ro = (size_t)n * K + k;
        Wth[ro] = h;
        Wtl[ro] = l;
    }
}

__global__ void pack_bias_kernel(float* __restrict__ dst,
                                 const float* __restrict__ s0,
                                 const float* __restrict__ s1,
                                 const float* __restrict__ s2) {
    int i = blockIdx.x * 256 + threadIdx.x;
    int s = i / 768, r = i - s * 768;
    const float* p = (s == 0) ? s0 : (s == 1 ? s1 : s2);
    dst[i] = p[r];
}

// ================= warp-MMA bf16 GEMM (hi/lo fragment reuse) =================
#define MAT_B 10240
#define STG_BYTES (4*MAT_B)
#define GSM_TOT (3*STG_BYTES)   // 122880

__device__ __forceinline__ void ldm_x4(uint32_t addr, uint32_t& r0, uint32_t& r1,
                                       uint32_t& r2, uint32_t& r3) {
    asm volatile("ldmatrix.sync.aligned.m8n8.x4.shared.b16 {%0,%1,%2,%3}, [%4];"
        : "=r"(r0), "=r"(r1), "=r"(r2), "=r"(r3) : "r"(addr));
}
__device__ __forceinline__ void ldm_x4t(uint32_t addr, uint32_t& r0, uint32_t& r1,
                                        uint32_t& r2, uint32_t& r3) {
    asm volatile("ldmatrix.sync.aligned.m8n8.x4.trans.shared.b16 {%0,%1,%2,%3}, [%4];"
        : "=r"(r0), "=r"(r1), "=r"(r2), "=r"(r3) : "r"(addr));
}
__device__ __forceinline__ void mma_bf16(float* c, const uint32_t* a, const uint32_t* b) {
    asm volatile("mma.sync.aligned.m16n8k16.row.col.f32.bf16.bf16.f32 "
        "{%0,%1,%2,%3}, {%4,%5,%6,%7}, {%8,%9}, {%0,%1,%2,%3};"
        : "+f"(c[0]), "+f"(c[1]), "+f"(c[2]), "+f"(c[3])
        : "r"(a[0]), "r"(a[1]), "r"(a[2]), "r"(a[3]), "r"(b[0]), "r"(b[1]));
}

// mode 0: Cf = acc+bias ; mode 1: +GELU ; mode 2: hi/lo bf16(gelu) -> Cbh/Cbl
__global__ __launch_bounds__(256)
void gemm_mma_kernel(const __nv_bfloat16* __restrict__ Ah,
                     const __nv_bfloat16* __restrict__ Al,
                     const __nv_bfloat16* __restrict__ Bh,
                     const __nv_bfloat16* __restrict__ Bl,
                     const float* __restrict__ bias,
                     float* __restrict__ Cf,
                     __nv_bfloat16* __restrict__ Cbh,
                     __nv_bfloat16* __restrict__ Cbl,
                     int Kp, int N, int mode) {
    extern __shared__ __align__(1024) char smem[];
    uint32_t sb = smem_u32(smem);
    int tid = threadIdx.x;
    int wid = tid >> 5, lane = tid & 31;
    int m0 = blockIdx.y * 128, n0 = blockIdx.x * 128;
    int warp_m = (wid & 1) * 64;
    int warp_n = (wid >> 1) * 32;
    int NC = Kp / 32;

    const __nv_bfloat16* Agh = Ah + (size_t)m0 * Kp;
    const __nv_bfloat16* Agl = Al + (size_t)m0 * Kp;
    const __nv_bfloat16* Bgh = Bh + (size_t)n0 * Kp;
    const __nv_bfloat16* Bgl = Bl + (size_t)n0 * Kp;

    float acc[4][4][4];
    #pragma unroll
    for (int i = 0; i < 4; i++)
        #pragma unroll
        for (int j = 0; j < 4; j++)
            #pragma unroll
            for (int r = 0; r < 4; r++) acc[i][j][r] = 0.f;

    auto load_tile = [&](int c, int bf) {
        uint32_t base = sb + bf * STG_BYTES;
        const __nv_bfloat16* srcs[4] = {
            Agh + (size_t)c * 32, Agl + (size_t)c * 32,
            Bgh + (size_t)c * 32, Bgl + (size_t)c * 32 };
        #pragma unroll
        for (int m = 0; m < 4; m++) {
            const __nv_bfloat16* S = srcs[m];
            uint32_t mb = base + m * MAT_B;
            #pragma unroll
            for (int i = 0; i < 2; i++) {
                int ch = i * 256 + tid;
                int r = ch >> 2, c8 = (ch & 3) * 8;
                uint32_t d = mb + r * 80 + c8 * 2;
                const void* s = S + (size_t)r * Kp + c8;
                asm volatile("cp.async.cg.shared.global [%0], [%1], 16;" :: "r"(d), "l"(s));
            }
        }
    };

    load_tile(0, 0);
    asm volatile("cp.async.commit_group;" ::: "memory");
    load_tile(1, 1);
    asm volatile("cp.async.commit_group;" ::: "memory");

    int rsel = lane & 15, hsel = (lane >> 4) * 16;
    int bf = 0;
    for (int c = 0; c < NC; c++) {
        asm volatile("cp.async.wait_group 1;" ::: "memory");
        __syncthreads();
        int nbf = bf + 2; if (nbf >= 3) nbf -= 3;
        if (c + 2 < NC) load_tile(c + 2, nbf);
        asm volatile("cp.async.commit_group;" ::: "memory");

        uint32_t ahb = sb + bf * STG_BYTES;
        uint32_t alb = ahb + MAT_B;
        uint32_t bhb = ahb + 2 * MAT_B;
        uint32_t blb = ahb + 3 * MAT_B;

        #pragma unroll
        for (int ks = 0; ks < 2; ks++) {
            uint32_t ah[4][4], al[4][4], bh[4][2], bl[4][2];
            #pragma unroll
            for (int mi = 0; mi < 4; mi++) {
                uint32_t off = (warp_m + mi * 16 + rsel) * 80 + ks * 32 + hsel;
                ldm_x4(ahb + off, ah[mi][0], ah[mi][1], ah[mi][2], ah[mi][3]);
                ldm_x4(alb + off, al[mi][0], al[mi][1], al[mi][2], al[mi][3]);
            }
            #pragma unroll
            for (int np = 0; np < 2; np++) {
                uint32_t off = (warp_n + np * 16 + rsel) * 80 + ks * 32 + hsel;
                uint32_t r0, r1, r2, r3;
                ldm_x4(bhb + off, r0, r1, r2, r3);
                bh[np * 2 + 0][0] = r0; bh[np * 2 + 0][1] = r2;
                bh[np * 2 + 1][0] = r1; bh[np * 2 + 1][1] = r3;
                ldm_x4(blb + off, r0, r1, r2, r3);
                bl[np * 2 + 0][0] = r0; bl[np * 2 + 0][1] = r2;
                bl[np * 2 + 1][0] = r1; bl[np * 2 + 1][1] = r3;
            }
            #pragma unroll
            for (int mi = 0; mi < 4; mi++)
                #pragma unroll
                for (int nj = 0; nj < 4; nj++)
                    mma_bf16(acc[mi][nj], ah[mi], bh[nj]);
            #pragma unroll
            for (int mi = 0; mi < 4; mi++)
                #pragma unroll
                for (int nj = 0; nj < 4; nj++)
                    mma_bf16(acc[mi][nj], al[mi], bh[nj]);
            #pragma unroll
            for (int mi = 0; mi < 4; mi++)
                #pragma unroll
                for (int nj = 0; nj < 4; nj++)
                    mma_bf16(acc[mi][nj], ah[mi], bl[nj]);
        }
        bf++; if (bf >= 3) bf = 0;
    }

    int g = lane >> 2, t = lane & 3;
    #pragma unroll
    for (int mi = 0; mi < 4; mi++) {
        int row0 = m0 + warp_m + mi * 16 + g;
        #pragma unroll
        for (int nj = 0; nj < 4; nj++) {
            int col = n0 + warp_n + nj * 8 + t * 2;
            float bx = bias[col], by = bias[col + 1];
            float v0 = acc[mi][nj][0] + bx, v1 = acc[mi][nj][1] + by;
            float v2 = acc[mi][nj][2] + bx, v3 = acc[mi][nj][3] + by;
            if (mode >= 1) { v0 = gelu_tanh(v0); v1 = gelu_tanh(v1); v2 = gelu_tanh(v2); v3 = gelu_tanh(v3); }
            if (mode == 2) {
                #pragma unroll
                for (int rr = 0; rr < 2; rr++) {
                    int row = row0 + rr * 8;
                    float a0 = rr ? v2 : v0, a1 = rr ? v3 : v1;
                    uint32_t h2, l2;
                    hilo2(a0, a1, h2, l2);
                    size_t ro = (size_t)row * N + col;
                    *(uint32_t*)&Cbh[ro] = h2;
                    *(uint32_t*)&Cbl[ro] = l2;
                }
            } else {
                *(float2*)&Cf[(size_t)row0 * N + col]       = make_float2(v0, v1);
                *(float2*)&Cf[(size_t)(row0 + 8) * N + col] = make_float2(v2, v3);
            }
        }
    }
}

// ================= fused flash band attention (tensor-core hi/lo) ==========
// 128 threads = 4 warps; warp w owns q-rows 16w..16w+15 (all 64 band cols).
// Row stride in smem: 72 bf16 = 144 bytes.
#define FB_ROWB 144
#define FB_QH 0
#define FB_QL (FB_QH + 64*FB_ROWB)       // 9216
#define FB_KH (FB_QL + 64*FB_ROWB)
#define FB_KL (FB_KH + 64*FB_ROWB)
#define FB_VH (FB_KL + 64*FB_ROWB)
#define FB_VL (FB_VH + 64*FB_ROWB)
#define FB_SG (FB_VL + 64*FB_ROWB)       // 64 floats
#define FB_V0 (FB_SG + 256)
#define FB_CM (FB_V0 + 256)
#define FB_TOT (FB_CM + 256 + 64)

__global__ __launch_bounds__(128)
void flash_band_kernel(const float* __restrict__ qkv,
                       const int* __restrict__ am,
                       float* __restrict__ out) {
    extern __shared__ char fsmc[];
    float* fp = (float*)fsmc;
    uint32_t sb = smem_u32(fsmc);
    int z = blockIdx.y;
    int n = z % CNB;
    int h = (z / CNB) % CH;
    int b = z / (CNB * CH);
    int qt = blockIdx.x;
    int tid = threadIdx.x;
    int w = tid >> 5, lane = tid & 31;
    int rsel = lane & 15, hsel = (lane >> 4) * 16;
    int t2 = (lane & 3) * 2;

    int base_s    = n * CW + qt * 64;
    int base_kpos = n * CW - CW;
    int am0 = am[b * CS];

    // ---- load Q (scaled) as hi/lo bf16, plus V0 ----
    #pragma unroll
    for (int i = 0; i < 8; i++) {
        int sid = i * 128 + tid;            // 0..1023
        int r = sid >> 4, c4 = (sid & 15) * 4;
        float4 vq = *(const float4*)&qkv[((size_t)(b * CS + base_s + r)) * QKV_S + h * 64 + c4];
        vq.x *= CSCALE; vq.y *= CSCALE; vq.z *= CSCALE; vq.w *= CSCALE;
        uint32_t h0, l0, h1, l1;
        hilo2(vq.x, vq.y, h0, l0);
        hilo2(vq.z, vq.w, h1, l1);
        *(uint2*)(fsmc + FB_QH + r * FB_ROWB + c4 * 2) = make_uint2(h0, h1);
        *(uint2*)(fsmc + FB_QL + r * FB_ROWB + c4 * 2) = make_uint2(l0, l1);
    }
    if (tid < 64)
        fp[FB_V0 / 4 + tid] = qkv[((size_t)(b * CS)) * QKV_S + 1536 + h * 64 + tid];
    __syncthreads();

    // ---- sg (global key column) per q-row, from hi+lo Q ----
    {
        int row = tid >> 1, half = tid & 1;
        const __nv_bfloat16* qh = (const __nv_bfloat16*)(fsmc + FB_QH + row * FB_ROWB);
        const __nv_bfloat16* ql = (const __nv_bfloat16*)(fsmc + FB_QL + row * FB_ROWB);
        const float* k0p = &qkv[((size_t)(b * CS)) * QKV_S + 768 + h * 64];
        float sgv = 0.f;
        #pragma unroll
        for (int d = 0; d < 32; d++) {
            int dd = half * 32 + d;
            sgv += (__bfloat162float(qh[dd]) + __bfloat162float(ql[dd])) * k0p[dd];
        }
        sgv += __shfl_xor_sync(0xffffffffu, sgv, 1);
        if (half == 0) fp[FB_SG / 4 + row] = sgv;
    }

    // ---- preload Q A-fragments ----
    uint32_t qh[4][4], ql[4][4];
    #pragma unroll
    for (int dk = 0; dk < 4; dk++) {
        uint32_t off = (16 * w + rsel) * FB_ROWB + dk * 32 + hsel;
        ldm_x4(sb + FB_QH + off, qh[dk][0], qh[dk][1], qh[dk][2], qh[dk][3]);
        ldm_x4(sb + FB_QL + off, ql[dk][0], ql[dk][1], ql[dk][2], ql[dk][3]);
    }

    float o[8][4];
    #pragma unroll
    for (int nn = 0; nn < 8; nn++)
        #pragma unroll
        for (int e = 0; e < 4; e++) o[nn][e] = 0.f;
    float mst0 = -1e30f, mst1 = -1e30f, lst0 = 0.f, lst1 = 0.f;

    int qi0 = qt * 64 + 16 * w + (lane >> 2);
    int qi1 = qi0 + 8;

    for (int kc = 0; kc < 12; kc++) {
        __syncthreads();
        // load K/V chunk as hi/lo bf16 + column mask
        #pragma unroll
        for (int i = 0; i < 8; i++) {
            int sid = i * 128 + tid;
            int r = sid >> 4, c4 = (sid & 15) * 4;
            int kpos = base_kpos + kc * 64 + r;
            float4 vk = make_float4(0.f, 0.f, 0.f, 0.f);
            float4 vv = make_float4(0.f, 0.f, 0.f, 0.f);
            if (kpos >= 0 && kpos < CS) {
                size_t rb = ((size_t)(b * CS + kpos)) * QKV_S + h * 64 + c4;
                vk = *(const float4*)&qkv[rb + 768];
                vv = *(const float4*)&qkv[rb + 1536];
            }
            uint32_t h0, l0, h1, l1;
            hilo2(vk.x, vk.y, h0, l0);
            hilo2(vk.z, vk.w, h1, l1);
            *(uint2*)(fsmc + FB_KH + r * FB_ROWB + c4 * 2) = make_uint2(h0, h1);
            *(uint2*)(fsmc + FB_KL + r * FB_ROWB + c4 * 2) = make_uint2(l0, l1);
            hilo2(vv.x, vv.y, h0, l0);
            hilo2(vv.z, vv.w, h1, l1);
            *(uint2*)(fsmc + FB_VH + r * FB_ROWB + c4 * 2) = make_uint2(h0, h1);
            *(uint2*)(fsmc + FB_VL + r * FB_ROWB + c4 * 2) = make_uint2(l0, l1);
        }
        if (tid < 64) {
            int kpos = base_kpos + kc * 64 + tid;
            bool ok = (kpos >= 0) && (kpos < CS) && (kpos != 0);
            if (ok) ok = am[b * CS + kpos] > 0;
            fp[FB_CM / 4 + tid] = ok ? 1.f : 0.f;
        }
        __syncthreads();

        // ---- S = Q K^T (3-term bf16) ----
        float s[8][4];
        #pragma unroll
        for (int nn = 0; nn < 8; nn++)
            #pragma unroll
            for (int e = 0; e < 4; e++) s[nn][e] = 0.f;
        #pragma unroll
        for (int dk = 0; dk < 4; dk++) {
            #pragma unroll
            for (int np = 0; np < 4; np++) {
                uint32_t off = (np * 16 + rsel) * FB_ROWB + dk * 32 + hsel;
                uint32_t r0, r1, r2, r3;
                uint32_t kha[2], khb[2], kla[2], klb[2];
                ldm_x4(sb + FB_KH + off, r0, r1, r2, r3);
                kha[0] = r0; kha[1] = r2; khb[0] = r1; khb[1] = r3;
                ldm_x4(sb + FB_KL + off, r0, r1, r2, r3);
                kla[0] = r0; kla[1] = r2; klb[0] = r1; klb[1] = r3;
                mma_bf16(s[2 * np],     qh[dk], kha);
                mma_bf16(s[2 * np + 1], qh[dk], khb);
                mma_bf16(s[2 * np],     ql[dk], kha);
                mma_bf16(s[2 * np + 1], ql[dk], khb);
                mma_bf16(s[2 * np],     qh[dk], kla);
                mma_bf16(s[2 * np + 1], qh[dk], klb);
            }
        }

        // ---- mask ----
        #pragma unroll
        for (int nn = 0; nn < 8; nn++) {
            #pragma unroll
            for (int e = 0; e < 2; e++) {
                int kj = kc * 64 + 8 * nn + t2 + e;
                float cm = fp[FB_CM / 4 + 8 * nn + t2 + e];
                bool b0 = (kj >= qi0) && (kj <= qi0 + 2 * CW) && (cm > 0.f);
                bool b1 = (kj >= qi1) && (kj <= qi1 + 2 * CW) && (cm > 0.f);
                if (!b0) s[nn][e] = CNEG;
                if (!b1) s[nn][2 + e] = CNEG;
            }
        }

        // ---- online softmax (rows warp-local; quad shfl) ----
        float mx0 = -1e30f, mx1 = -1e30f;
        #pragma unroll
        for (int nn = 0; nn < 8; nn++) {
            mx0 = fmaxf(mx0, fmaxf(s[nn][0], s[nn][1]));
            mx1 = fmaxf(mx1, fmaxf(s[nn][2], s[nn][3]));
        }
        mx0 = fmaxf(mx0, __shfl_xor_sync(0xffffffffu, mx0, 1));
        mx0 = fmaxf(mx0, __shfl_xor_sync(0xffffffffu, mx0, 2));
        mx1 = fmaxf(mx1, __shfl_xor_sync(0xffffffffu, mx1, 1));
        mx1 = fmaxf(mx1, __shfl_xor_sync(0xffffffffu, mx1, 2));
        float nm0 = fmaxf(mst0, mx0), nm1 = fmaxf(mst1, mx1);
        float a0 = __expf(mst0 - nm0), a1 = __expf(mst1 - nm1);
        mst0 = nm0; mst1 = nm1;
        float rs0 = 0.f, rs1 = 0.f;
        #pragma unroll
        for (int nn = 0; nn < 8; nn++) {
            s[nn][0] = __expf(s[nn][0] - nm0); rs0 += s[nn][0];
            s[nn][1] = __expf(s[nn][1] - nm0); rs0 += s[nn][1];
            s[nn][2] = __expf(s[nn][2] - nm1); rs1 += s[nn][2];
            s[nn][3] = __expf(s[nn][3] - nm1); rs1 += s[nn][3];
        }
        rs0 += __shfl_xor_sync(0xffffffffu, rs0, 1);
        rs0 += __shfl_xor_sync(0xffffffffu, rs0, 2);
        rs1 += __shfl_xor_sync(0xffffffffu, rs1, 1);
        rs1 += __shfl_xor_sync(0xffffffffu, rs1, 2);
        lst0 = lst0 * a0 + rs0;
        lst1 = lst1 * a1 + rs1;
        #pragma unroll
        for (int nn = 0; nn < 8; nn++) {
            o[nn][0] *= a0; o[nn][1] *= a0;
            o[nn][2] *= a1; o[nn][3] *= a1;
        }

        // ---- P fragments (registers; C m16n16 == A m16k16) ----
        uint32_t ph[4][4], pl[4][4];
        #pragma unroll
        for (int qf = 0; qf < 4; qf++) {
            hilo2(s[2 * qf][0],     s[2 * qf][1],     ph[qf][0], pl[qf][0]);
            hilo2(s[2 * qf][2],     s[2 * qf][3],     ph[qf][1], pl[qf][1]);
            hilo2(s[2 * qf + 1][0], s[2 * qf + 1][1], ph[qf][2], pl[qf][2]);
            hilo2(s[2 * qf + 1][2], s[2 * qf + 1][3], ph[qf][3], pl[qf][3]);
        }

        // ---- O += P V (3-term bf16; V via trans ldmatrix) ----
        #pragma unroll
        for (int qf = 0; qf < 4; qf++) {
            #pragma unroll
            for (int dp = 0; dp < 4; dp++) {
                uint32_t off = (qf * 16 + rsel) * FB_ROWB + dp * 32 + hsel;
                uint32_t r0, r1, r2, r3;
                uint32_t vha[2], vhb[2], vla[2], vlb[2];
                ldm_x4t(sb + FB_VH + off, r0, r1, r2, r3);
                vha[0] = r0; vha[1] = r1; vhb[0] = r2; vhb[1] = r3;
                ldm_x4t(sb + FB_VL + off, r0, r1, r2, r3);
                vla[0] = r0; vla[1] = r1; vlb[0] = r2; vlb[1] = r3;
                mma_bf16(o[2 * dp],     ph[qf], vha);
                mma_bf16(o[2 * dp + 1], ph[qf], vhb);
                mma_bf16(o[2 * dp],     pl[qf], vha);
                mma_bf16(o[2 * dp + 1], pl[qf], vhb);
                mma_bf16(o[2 * dp],     ph[qf], vla);
                mma_bf16(o[2 * dp + 1], ph[qf], vlb);
            }
        }
    }

    // ---- epilogue: fold in global column, normalize, store ----
    #pragma unroll
    for (int rr = 0; rr < 2; rr++) {
        int row = 16 * w + (lane >> 2) + 8 * rr;
        float mst = rr ? mst1 : mst0;
        float lst = rr ? lst1 : lst0;
        float sg = fp[FB_SG / 4 + row];
        if (am0 <= 0) sg = CNEG;
        float nm = fmaxf(mst, sg);
        float alpha = __expf(mst - nm);
        float pg = __expf(sg - nm);
        float l = lst * alpha + pg;
        float inv = 1.0f / l;
        int srow = base_s + row;
        float* orow = &out[((size_t)(b * CS + srow)) * CDM + h * 64];
        #pragma unroll
        for (int nn = 0; nn < 8; nn++) {
            int d = 8 * nn + t2;
            float v0 = (o[nn][2 * rr + 0] * alpha + pg * fp[FB_V0 / 4 + d])     * inv;
            float v1 = (o[nn][2 * rr + 1] * alpha + pg * fp[FB_V0 / 4 + d + 1]) * inv;
            *(float2*)&orow[d] = make_float2(v0, v1);
        }
    }
}

// ================= small kernels =================
__device__ __forceinline__ float block_reduce_sum256(float v, float* red) {
    int tid = threadIdx.x;
    red[tid] = v; __syncthreads();
    #pragma unroll
    for (int o = 128; o > 0; o >>= 1) {
        if (tid < o) red[tid] += red[tid + o];
        __syncthreads();
    }
    float r = red[0]; __syncthreads();
    return r;
}

__global__ void embed_ln_kernel(const int* __restrict__ ids,
                                const float* __restrict__ we,
                                const float* __restrict__ pe,
                                const float* __restrict__ gam,
                                const float* __restrict__ bet,
                                float* __restrict__ x,
                                __nv_bfloat16* __restrict__ xh,
                                __nv_bfloat16* __restrict__ xl) {
    __shared__ float red[256];
    int row = blockIdx.x;
    int s = row % CS;
    int id = ids[row];
    int tid = threadIdx.x;
    const float* wp = we + (size_t)id * CDM;
    const float* pp = pe + (size_t)s * CDM;
    float e[3];
    float sm = 0.f;
    #pragma unroll
    for (int i = 0; i < 3; i++) { int d = tid + i * 256; e[i] = wp[d] + pp[d]; sm += e[i]; }
    float mean = block_reduce_sum256(sm, red) * (1.0f / CDM);
    float vs = 0.f;
    #pragma unroll
    for (int i = 0; i < 3; i++) { float t = e[i] - mean; vs += t * t; }
    float var = block_reduce_sum256(vs, red) * (1.0f / CDM);
    float inv = rsqrtf(var + 1e-5f);
    float* xr = x + (size_t)row * CDM;
    size_t ro = (size_t)row * CDM;
    #pragma unroll
    for (int i = 0; i < 3; i++) {
        int d = tid + i * 256;
        float val = (e[i] - mean) * inv * gam[d] + bet[d];
        xr[d] = val;
        __nv_bfloat16 h, l;
        hilo(val, h, l);
        xh[ro + d] = h; xl[ro + d] = l;
    }
}

__global__ void add_ln_kernel(float* __restrict__ x,
                              const float* __restrict__ y,
                              const float* __restrict__ gam,
                              const float* __restrict__ bet,
                              __nv_bfloat16* __restrict__ xh,
                              __nv_bfloat16* __restrict__ xl) {
    __shared__ float red[256];
    int row = blockIdx.x;
    int tid = threadIdx.x;
    float* xr = x + (size_t)row * CDM;
    const float* yr = y + (size_t)row * CDM;
    float e[3];
    float sm = 0.f;
    #pragma unroll
    for (int i = 0; i < 3; i++) { int d = tid + i * 256; e[i] = xr[d] + yr[d]; sm += e[i]; }
    float mean = block_reduce_sum256(sm, red) * (1.0f / CDM);
    float vs = 0.f;
    #pragma unroll
    for (int i = 0; i < 3; i++) { float t = e[i] - mean; vs += t * t; }
    float var = block_reduce_sum256(vs, red) * (1.0f / CDM);
    float inv = rsqrtf(var + 1e-5f);
    size_t ro = (size_t)row * CDM;
    #pragma unroll
    for (int i = 0; i < 3; i++) {
        int d = tid + i * 256;
        float val = (e[i] - mean) * inv * gam[d] + bet[d];
        xr[d] = val;
        __nv_bfloat16 h, l;
        hilo(val, h, l);
        xh[ro + d] = h; xl[ro + d] = l;
    }
}

__global__ void qg_kernel(const float* __restrict__ x,
                          const float* __restrict__ Wqg,
                          const float* __restrict__ bqg,
                          float* __restrict__ qg) {
    int nidx = blockIdx.x * 256 + threadIdx.x;
    int b = blockIdx.y;
    const float* xr = x + (size_t)(b * CS) * CDM;
    float acc = bqg[nidx];
    for (int kk = 0; kk < CDM; kk++)
        acc += xr[kk] * Wqg[(size_t)kk * CDM + nidx];
    qg[b * CDM + nidx] = acc * CSCALE;
}

__global__ void global_attn_kernel(const float* __restrict__ qg,
                                   const float* __restrict__ gkv,
                                   const int* __restrict__ am,
                                   float* __restrict__ out) {
    __shared__ float scs[CS];
    __shared__ float red[256];
    __shared__ float qs[64];
    int h = blockIdx.x, b = blockIdx.y;
    int tid = threadIdx.x;
    if (tid < 64) qs[tid] = qg[b * CDM + h * 64 + tid];
    __syncthreads();

    float mx = -1e30f;
    for (int s = tid; s < CS; s += 256) {
        const float* kp = &gkv[((size_t)(b * CS + s)) * GKV_S + h * 64];
        float dd = 0.f;
        #pragma unroll
        for (int e = 0; e < 64; e++) dd += qs[e] * kp[e];
        if (am[b * CS + s] <= 0) dd = CNEG;
        scs[s] = dd;
        mx = fmaxf(mx, dd);
    }
    red[tid] = mx; __syncthreads();
    #pragma unroll
    for (int o = 128; o > 0; o >>= 1) {
        if (tid < o) red[tid] = fmaxf(red[tid], red[tid + o]);
        __syncthreads();
    }
    mx = red[0]; __syncthreads();

    float sm = 0.f;
    for (int s = tid; s < CS; s += 256) {
        float e = __expf(scs[s] - mx);
        scs[s] = e; sm += e;
    }
    float tot = block_reduce_sum256(sm, red);
    float inv = 1.0f / tot;
    __syncthreads();

    int d = tid & 63, sl = tid >> 6;
    float acc = 0.f;
    for (int s = sl * 1024; s < (sl + 1) * 1024; s++)
        acc += scs[s] * gkv[((size_t)(b * CS + s)) * GKV_S + 768 + h * 64 + d];
    red[tid] = acc; __syncthreads();
    if (sl == 0) {
        float t = red[d] + red[64 + d] + red[128 + d] + red[192 + d];
        out[((size_t)(b * CS)) * CDM + h * 64 + d] = t * inv;
    }
}

__global__ void cls_kernel(const float* __restrict__ x,
                           const float* __restrict__ Wc,
                           const float* __restrict__ bc,
                           float* __restrict__ out) {
    __shared__ float red[256];
    int b = blockIdx.x >> 1, c = blockIdx.x & 1;
    int tid = threadIdx.x;
    const float* xr = x + (size_t)(b * CS) * CDM;
    float acc = 0.f;
    for (int d = tid; d < CDM; d += 256) acc += xr[d] * Wc[d * 2 + c];
    float tot = block_reduce_sum256(acc, red);
    if (tid == 0) out[b * 2 + c] = tot + bc[c];
}

// ================= launch =================
extern "C" void kernel_launch(void* const* d_in, const int* in_sizes, int n_in,
                              void* d_out, int out_size) {
    const int*   ids  = (const int*)d_in[0];
    const int*   am   = (const int*)d_in[1];
    const float* we   = (const float*)d_in[2];
    const float* pe   = (const float*)d_in[3];
    const float* lnes = (const float*)d_in[4];
    const float* lneb = (const float*)d_in[5];
    const float* Wq   = (const float*)d_in[6];
    const float* bq   = (const float*)d_in[7];
    const float* Wk   = (const float*)d_in[8];
    const float* bk   = (const float*)d_in[9];
    const float* Wv   = (const float*)d_in[10];
    const float* bv   = (const float*)d_in[11];
    const float* Wqg  = (const float*)d_in[12];
    const float* bqg  = (const float*)d_in[13];
    const float* Wkg  = (const float*)d_in[14];
    const float* bkg  = (const float*)d_in[15];
    const float* Wvg  = (const float*)d_in[16];
    const float* bvg  = (const float*)d_in[17];
    const float* Wo   = (const float*)d_in[18];
    const float* bo   = (const float*)d_in[19];
    const float* ln1s = (const float*)d_in[20];
    const float* ln1b = (const float*)d_in[21];
    const float* W1   = (const float*)d_in[22];
    const float* b1   = (const float*)d_in[23];
    const float* W2   = (const float*)d_in[24];
    const float* b2   = (const float*)d_in[25];
    const float* ln2s = (const float*)d_in[26];
    const float* ln2b = (const float*)d_in[27];
    const float* Wcls = (const float*)d_in[28];
    const float* bcls = (const float*)d_in[29];
    float* out = (float*)d_out;

    float *xp, *yp, *ap, *qkvp, *gkvp, *qgp, *biasp;
    __nv_bfloat16 *xhp, *xlp, *hhp, *hlp, *whp, *wlp;
    cudaGetSymbolAddress((void**)&xp,   g_x);
    cudaGetSymbolAddress((void**)&yp,   g_y);
    cudaGetSymbolAddress((void**)&ap,   g_attn);
    cudaGetSymbolAddress((void**)&qkvp, g_qkv);
    cudaGetSymbolAddress((void**)&gkvp, g_gkv);
    cudaGetSymbolAddress((void**)&qgp,  g_qg);
    cudaGetSymbolAddress((void**)&biasp, g_bias);
    cudaGetSymbolAddress((void**)&xhp,  g_xbh);
    cudaGetSymbolAddress((void**)&xlp,  g_xbl);
    cudaGetSymbolAddress((void**)&hhp,  g_hbh);
    cudaGetSymbolAddress((void**)&hlp,  g_hbl);
    cudaGetSymbolAddress((void**)&whp,  g_wbh);
    cudaGetSymbolAddress((void**)&wlp,  g_wbl);

    cudaFuncSetAttribute(gemm_mma_kernel, cudaFuncAttributeMaxDynamicSharedMemorySize, GSM_TOT);
    cudaFuncSetAttribute(flash_band_kernel, cudaFuncAttributeMaxDynamicSharedMemorySize, FB_TOT);

    embed_ln_kernel<<<MROWS, 256>>>(ids, we, pe, lnes, lneb, xp, xhp, xlp);

    dim3 wt_dm(CDM / 32, CDM / 32);
    dim3 wt_b(32, 8);
    size_t wseg = (size_t)CDM * CDM;
    int actK = MROWS * CDM / 256;

    for (int l = 0; l < CL; l++) {
        size_t woff = (size_t)l * CDM * CDM;
        size_t boff = (size_t)l * CDM;
        size_t w1off = (size_t)l * CDM * CDFF;
        size_t b1off = (size_t)l * CDFF;
        size_t w2off = (size_t)l * CDFF * CDM;

        // --- fused QKV ---
        split_wt_kernel<<<wt_dm, wt_b>>>(Wq + woff, whp,            wlp,            CDM, CDM);
        split_wt_kernel<<<wt_dm, wt_b>>>(Wk + woff, whp + wseg,     wlp + wseg,     CDM, CDM);
        split_wt_kernel<<<wt_dm, wt_b>>>(Wv + woff, whp + 2 * wseg, wlp + 2 * wseg, CDM, CDM);
        pack_bias_kernel<<<9, 256>>>(biasp, bq + boff, bk + boff, bv + boff);
        gemm_mma_kernel<<<dim3(QKV_S / 128, MROWS / 128), 256, GSM_TOT>>>(
            xhp, xlp, whp, wlp, biasp, qkvp, nullptr, nullptr, CDM, QKV_S, 0);

        flash_band_kernel<<<dim3(4, CB * CH * CNB), 128, FB_TOT>>>(qkvp, am, ap);

        // --- fused Kg/Vg + global attention ---
        qg_kernel<<<dim3(CDM / 256, CB), 256>>>(xp, Wqg + woff, bqg + boff, qgp);
        split_wt_kernel<<<wt_dm, wt_b>>>(Wkg + woff, whp,        wlp,        CDM, CDM);
        split_wt_kernel<<<wt_dm, wt_b>>>(Wvg + woff, whp + wseg, wlp + wseg, CDM, CDM);
        pack_bias_kernel<<<6, 256>>>(biasp, bkg + boff, bvg + boff, bvg + boff);
        gemm_mma_kernel<<<dim3(GKV_S / 128, MROWS / 128), 256, GSM_TOT>>>(
            xhp, xlp, whp, wlp, biasp, gkvp, nullptr, nullptr, CDM, GKV_S, 0);
        global_attn_kernel<<<dim3(CH, CB), 256>>>(qgp, gkvp, am, ap);

        // --- Wo projection + LN1 ---
        split_act_kernel<<<actK, 256>>>(ap, xhp, xlp);
        split_wt_kernel<<<wt_dm, wt_b>>>(Wo + woff, whp, wlp, CDM, CDM);
        gemm_mma_kernel<<<dim3(CDM / 128, MROWS / 128), 256, GSM_TOT>>>(
            xhp, xlp, whp, wlp, bo + boff, yp, nullptr, nullptr, CDM, CDM, 0);
        add_ln_kernel<<<MROWS, 256>>>(xp, yp, ln1s + boff, ln1b + boff, xhp, xlp);

        // --- FFN ---
        split_wt_kernel<<<dim3(CDFF / 32, CDM / 32), wt_b>>>(W1 + w1off, whp, wlp, CDM, CDFF);
        gemm_mma_kernel<<<dim3(CDFF / 128, MROWS / 128), 256, GSM_TOT>>>(
            xhp, xlp, whp, wlp, b1 + b1off, nullptr, hhp, hlp, CDM, CDFF, 2);

        split_wt_kernel<<<dim3(CDM / 32, CDFF / 32), wt_b>>>(W2 + w2off, whp, wlp, CDFF, CDM);
        gemm_mma_kernel<<<dim3(CDM / 128, MROWS / 128), 256, GSM_TOT>>>(
            hhp, hlp, whp, wlp, b2 + boff, yp, nullptr, nullptr, CDFF, CDM, 0);
        add_ln_kernel<<<MROWS, 256>>>(xp, yp, ln2s + boff, ln2b + boff, xhp, xlp);
    }

    cls_kernel<<<4, 256>>>(xp, Wcls, bcls, out);
}

// round 10
// speedup vs baseline: 1.4721x; 1.0912x over previous
#include <cuda_runtime.h>
#include <cuda_bf16.h>
#include <math.h>
#include <stdint.h>

// ---------------- problem constants ----------------
#define CB   2
#define CS   4096
#define CH   12
#define CD   64
#define CW   256
#define CDM  768
#define CDFF 3072
#define CNB  16
#define CL   2
#define CNEG (-1000000000.0f)
#define CSCALE 0.125f

#define MROWS (CB*CS)    // 8192
#define QKV_S 2304
#define GKV_S 1536

// ---------------- scratch ----------------
__device__ float g_x   [MROWS*CDM];
__device__ float g_y   [MROWS*CDM];
__device__ float g_qkv [(size_t)MROWS*QKV_S];
__device__ float g_gkv [(size_t)MROWS*GKV_S];
__device__ float g_qg  [CB*CDM];
__device__ float g_bias[QKV_S];
// hi/lo bf16 operand buffers
__device__ __nv_bfloat16 g_xbh[(size_t)MROWS*CDM];
__device__ __nv_bfloat16 g_xbl[(size_t)MROWS*CDM];
__device__ __nv_bfloat16 g_abh[(size_t)MROWS*CDM];   // attention output hi/lo
__device__ __nv_bfloat16 g_abl[(size_t)MROWS*CDM];
__device__ __nv_bfloat16 g_hbh[(size_t)MROWS*CDFF];
__device__ __nv_bfloat16 g_hbl[(size_t)MROWS*CDFF];
__device__ __nv_bfloat16 g_wbh[(size_t)CDFF*CDM];    // transposed weights [N][K]
__device__ __nv_bfloat16 g_wbl[(size_t)CDFF*CDM];

// ---------------- helpers ----------------
__device__ __forceinline__ float gelu_tanh(float x) {
    float x3 = x * x * x;
    return 0.5f * x * (1.0f + tanhf(0.7978845608028654f * (x + 0.044715f * x3)));
}
__device__ __forceinline__ uint32_t smem_u32(const void* p) {
    uint32_t a;
    asm("{ .reg .u64 t; cvta.to.shared.u64 t, %1; cvt.u32.u64 %0, t; }" : "=r"(a) : "l"(p));
    return a;
}
__device__ __forceinline__ void hilo(float v, __nv_bfloat16& h, __nv_bfloat16& l) {
    h = __float2bfloat16_rn(v);
    l = __float2bfloat16_rn(v - __bfloat162float(h));
}
__device__ __forceinline__ void hilo2(float a, float b, uint32_t& h, uint32_t& l) {
    __nv_bfloat16 ha, la, hb, lb;
    hilo(a, ha, la);
    hilo(b, hb, lb);
    __nv_bfloat162 hh = __halves2bfloat162(ha, hb);
    __nv_bfloat162 ll = __halves2bfloat162(la, lb);
    h = *(uint32_t*)&hh;
    l = *(uint32_t*)&ll;
}

// ================= split/convert kernels =================
__global__ void split_wt_kernel(const float* __restrict__ W,
                                __nv_bfloat16* __restrict__ Wth,
                                __nv_bfloat16* __restrict__ Wtl, int K, int N) {
    __shared__ float t[32][33];
    int n0 = blockIdx.x * 32, k0 = blockIdx.y * 32;
    int tx = threadIdx.x, ty = threadIdx.y;   // 32 x 8
    #pragma unroll
    for (int r = 0; r < 4; r++) {
        int k = k0 + ty + r * 8;
        t[ty + r * 8][tx] = W[(size_t)k * N + n0 + tx];
    }
    __syncthreads();
    #pragma unroll
    for (int r = 0; r < 4; r++) {
        int n = n0 + ty + r * 8;
        int k = k0 + tx;
        __nv_bfloat16 h, l;
        hilo(t[tx][ty + r * 8], h, l);
        size_t ro = (size_t)n * K + k;
        Wth[ro] = h;
        Wtl[ro] = l;
    }
}

__global__ void pack_bias_kernel(float* __restrict__ dst,
                                 const float* __restrict__ s0,
                                 const float* __restrict__ s1,
                                 const float* __restrict__ s2) {
    int i = blockIdx.x * 256 + threadIdx.x;
    int s = i / 768, r = i - s * 768;
    const float* p = (s == 0) ? s0 : (s == 1 ? s1 : s2);
    dst[i] = p[r];
}

// ================= warp-MMA bf16 GEMM (hi/lo fragment reuse) =================
// 2-stage pipeline, 2 CTAs/SM (80KB smem, <=128 regs).
#define MAT_B 10240
#define STG_BYTES (4*MAT_B)
#define GSM_TOT (2*STG_BYTES)   // 81920

__device__ __forceinline__ void ldm_x4(uint32_t addr, uint32_t& r0, uint32_t& r1,
                                       uint32_t& r2, uint32_t& r3) {
    asm volatile("ldmatrix.sync.aligned.m8n8.x4.shared.b16 {%0,%1,%2,%3}, [%4];"
        : "=r"(r0), "=r"(r1), "=r"(r2), "=r"(r3) : "r"(addr));
}
__device__ __forceinline__ void ldm_x4t(uint32_t addr, uint32_t& r0, uint32_t& r1,
                                        uint32_t& r2, uint32_t& r3) {
    asm volatile("ldmatrix.sync.aligned.m8n8.x4.trans.shared.b16 {%0,%1,%2,%3}, [%4];"
        : "=r"(r0), "=r"(r1), "=r"(r2), "=r"(r3) : "r"(addr));
}
__device__ __forceinline__ void mma_bf16(float* c, const uint32_t* a, const uint32_t* b) {
    asm volatile("mma.sync.aligned.m16n8k16.row.col.f32.bf16.bf16.f32 "
        "{%0,%1,%2,%3}, {%4,%5,%6,%7}, {%8,%9}, {%0,%1,%2,%3};"
        : "+f"(c[0]), "+f"(c[1]), "+f"(c[2]), "+f"(c[3])
        : "r"(a[0]), "r"(a[1]), "r"(a[2]), "r"(a[3]), "r"(b[0]), "r"(b[1]));
}

// mode 0: Cf = acc+bias ; mode 1: +GELU ; mode 2: hi/lo bf16(gelu) -> Cbh/Cbl
__global__ __launch_bounds__(256, 2)
void gemm_mma_kernel(const __nv_bfloat16* __restrict__ Ah,
                     const __nv_bfloat16* __restrict__ Al,
                     const __nv_bfloat16* __restrict__ Bh,
                     const __nv_bfloat16* __restrict__ Bl,
                     const float* __restrict__ bias,
                     float* __restrict__ Cf,
                     __nv_bfloat16* __restrict__ Cbh,
                     __nv_bfloat16* __restrict__ Cbl,
                     int Kp, int N, int mode) {
    extern __shared__ __align__(1024) char smem[];
    uint32_t sb = smem_u32(smem);
    int tid = threadIdx.x;
    int wid = tid >> 5, lane = tid & 31;
    int m0 = blockIdx.y * 128, n0 = blockIdx.x * 128;
    int warp_m = (wid & 1) * 64;
    int warp_n = (wid >> 1) * 32;
    int NC = Kp / 32;

    const __nv_bfloat16* Agh = Ah + (size_t)m0 * Kp;
    const __nv_bfloat16* Agl = Al + (size_t)m0 * Kp;
    const __nv_bfloat16* Bgh = Bh + (size_t)n0 * Kp;
    const __nv_bfloat16* Bgl = Bl + (size_t)n0 * Kp;

    float acc[4][4][4];
    #pragma unroll
    for (int i = 0; i < 4; i++)
        #pragma unroll
        for (int j = 0; j < 4; j++)
            #pragma unroll
            for (int r = 0; r < 4; r++) acc[i][j][r] = 0.f;

    auto load_tile = [&](int c, int bf) {
        uint32_t base = sb + bf * STG_BYTES;
        const __nv_bfloat16* srcs[4] = {
            Agh + (size_t)c * 32, Agl + (size_t)c * 32,
            Bgh + (size_t)c * 32, Bgl + (size_t)c * 32 };
        #pragma unroll
        for (int m = 0; m < 4; m++) {
            const __nv_bfloat16* S = srcs[m];
            uint32_t mb = base + m * MAT_B;
            #pragma unroll
            for (int i = 0; i < 2; i++) {
                int ch = i * 256 + tid;
                int r = ch >> 2, c8 = (ch & 3) * 8;
                uint32_t d = mb + r * 80 + c8 * 2;
                const void* s = S + (size_t)r * Kp + c8;
                asm volatile("cp.async.cg.shared.global [%0], [%1], 16;" :: "r"(d), "l"(s));
            }
        }
    };

    load_tile(0, 0);
    asm volatile("cp.async.commit_group;" ::: "memory");

    int rsel = lane & 15, hsel = (lane >> 4) * 16;
    for (int c = 0; c < NC; c++) {
        int bf = c & 1;
        if (c + 1 < NC) load_tile(c + 1, bf ^ 1);
        asm volatile("cp.async.commit_group;" ::: "memory");
        asm volatile("cp.async.wait_group 1;" ::: "memory");
        __syncthreads();

        uint32_t ahb = sb + bf * STG_BYTES;
        uint32_t alb = ahb + MAT_B;
        uint32_t bhb = ahb + 2 * MAT_B;
        uint32_t blb = ahb + 3 * MAT_B;

        #pragma unroll
        for (int ks = 0; ks < 2; ks++) {
            uint32_t ah[4][4], al[4][4], bh[4][2], bl[4][2];
            #pragma unroll
            for (int mi = 0; mi < 4; mi++) {
                uint32_t off = (warp_m + mi * 16 + rsel) * 80 + ks * 32 + hsel;
                ldm_x4(ahb + off, ah[mi][0], ah[mi][1], ah[mi][2], ah[mi][3]);
                ldm_x4(alb + off, al[mi][0], al[mi][1], al[mi][2], al[mi][3]);
            }
            #pragma unroll
            for (int np = 0; np < 2; np++) {
                uint32_t off = (warp_n + np * 16 + rsel) * 80 + ks * 32 + hsel;
                uint32_t r0, r1, r2, r3;
                ldm_x4(bhb + off, r0, r1, r2, r3);
                bh[np * 2 + 0][0] = r0; bh[np * 2 + 0][1] = r2;
                bh[np * 2 + 1][0] = r1; bh[np * 2 + 1][1] = r3;
                ldm_x4(blb + off, r0, r1, r2, r3);
                bl[np * 2 + 0][0] = r0; bl[np * 2 + 0][1] = r2;
                bl[np * 2 + 1][0] = r1; bl[np * 2 + 1][1] = r3;
            }
            #pragma unroll
            for (int mi = 0; mi < 4; mi++)
                #pragma unroll
                for (int nj = 0; nj < 4; nj++)
                    mma_bf16(acc[mi][nj], ah[mi], bh[nj]);
            #pragma unroll
            for (int mi = 0; mi < 4; mi++)
                #pragma unroll
                for (int nj = 0; nj < 4; nj++)
                    mma_bf16(acc[mi][nj], al[mi], bh[nj]);
            #pragma unroll
            for (int mi = 0; mi < 4; mi++)
                #pragma unroll
                for (int nj = 0; nj < 4; nj++)
                    mma_bf16(acc[mi][nj], ah[mi], bl[nj]);
        }
        __syncthreads();
    }

    int g = lane >> 2, t = lane & 3;
    #pragma unroll
    for (int mi = 0; mi < 4; mi++) {
        int row0 = m0 + warp_m + mi * 16 + g;
        #pragma unroll
        for (int nj = 0; nj < 4; nj++) {
            int col = n0 + warp_n + nj * 8 + t * 2;
            float bx = bias[col], by = bias[col + 1];
            float v0 = acc[mi][nj][0] + bx, v1 = acc[mi][nj][1] + by;
            float v2 = acc[mi][nj][2] + bx, v3 = acc[mi][nj][3] + by;
            if (mode >= 1) { v0 = gelu_tanh(v0); v1 = gelu_tanh(v1); v2 = gelu_tanh(v2); v3 = gelu_tanh(v3); }
            if (mode == 2) {
                #pragma unroll
                for (int rr = 0; rr < 2; rr++) {
                    int row = row0 + rr * 8;
                    float a0 = rr ? v2 : v0, a1 = rr ? v3 : v1;
                    uint32_t h2, l2;
                    hilo2(a0, a1, h2, l2);
                    size_t ro = (size_t)row * N + col;
                    *(uint32_t*)&Cbh[ro] = h2;
                    *(uint32_t*)&Cbl[ro] = l2;
                }
            } else {
                *(float2*)&Cf[(size_t)row0 * N + col]       = make_float2(v0, v1);
                *(float2*)&Cf[(size_t)(row0 + 8) * N + col] = make_float2(v2, v3);
            }
        }
    }
}

// ================= fused flash band attention (tensor-core hi/lo) ==========
// Epilogue writes attention output directly as hi/lo bf16 (no fp32 buffer).
#define FB_ROWB 144
#define FB_QH 0
#define FB_QL (FB_QH + 64*FB_ROWB)
#define FB_KH (FB_QL + 64*FB_ROWB)
#define FB_KL (FB_KH + 64*FB_ROWB)
#define FB_VH (FB_KL + 64*FB_ROWB)
#define FB_VL (FB_VH + 64*FB_ROWB)
#define FB_SG (FB_VL + 64*FB_ROWB)
#define FB_V0 (FB_SG + 256)
#define FB_CM (FB_V0 + 256)
#define FB_TOT (FB_CM + 256 + 64)

__global__ __launch_bounds__(128)
void flash_band_kernel(const float* __restrict__ qkv,
                       const int* __restrict__ am,
                       __nv_bfloat16* __restrict__ outh,
                       __nv_bfloat16* __restrict__ outl) {
    extern __shared__ char fsmc[];
    float* fp = (float*)fsmc;
    uint32_t sb = smem_u32(fsmc);
    int z = blockIdx.y;
    int n = z % CNB;
    int h = (z / CNB) % CH;
    int b = z / (CNB * CH);
    int qt = blockIdx.x;
    int tid = threadIdx.x;
    int w = tid >> 5, lane = tid & 31;
    int rsel = lane & 15, hsel = (lane >> 4) * 16;
    int t2 = (lane & 3) * 2;

    int base_s    = n * CW + qt * 64;
    int base_kpos = n * CW - CW;
    int am0 = am[b * CS];

    #pragma unroll
    for (int i = 0; i < 8; i++) {
        int sid = i * 128 + tid;
        int r = sid >> 4, c4 = (sid & 15) * 4;
        float4 vq = *(const float4*)&qkv[((size_t)(b * CS + base_s + r)) * QKV_S + h * 64 + c4];
        vq.x *= CSCALE; vq.y *= CSCALE; vq.z *= CSCALE; vq.w *= CSCALE;
        uint32_t h0, l0, h1, l1;
        hilo2(vq.x, vq.y, h0, l0);
        hilo2(vq.z, vq.w, h1, l1);
        *(uint2*)(fsmc + FB_QH + r * FB_ROWB + c4 * 2) = make_uint2(h0, h1);
        *(uint2*)(fsmc + FB_QL + r * FB_ROWB + c4 * 2) = make_uint2(l0, l1);
    }
    if (tid < 64)
        fp[FB_V0 / 4 + tid] = qkv[((size_t)(b * CS)) * QKV_S + 1536 + h * 64 + tid];
    __syncthreads();

    {
        int row = tid >> 1, half = tid & 1;
        const __nv_bfloat16* qh = (const __nv_bfloat16*)(fsmc + FB_QH + row * FB_ROWB);
        const __nv_bfloat16* ql = (const __nv_bfloat16*)(fsmc + FB_QL + row * FB_ROWB);
        const float* k0p = &qkv[((size_t)(b * CS)) * QKV_S + 768 + h * 64];
        float sgv = 0.f;
        #pragma unroll
        for (int d = 0; d < 32; d++) {
            int dd = half * 32 + d;
            sgv += (__bfloat162float(qh[dd]) + __bfloat162float(ql[dd])) * k0p[dd];
        }
        sgv += __shfl_xor_sync(0xffffffffu, sgv, 1);
        if (half == 0) fp[FB_SG / 4 + row] = sgv;
    }

    uint32_t qh[4][4], ql[4][4];
    #pragma unroll
    for (int dk = 0; dk < 4; dk++) {
        uint32_t off = (16 * w + rsel) * FB_ROWB + dk * 32 + hsel;
        ldm_x4(sb + FB_QH + off, qh[dk][0], qh[dk][1], qh[dk][2], qh[dk][3]);
        ldm_x4(sb + FB_QL + off, ql[dk][0], ql[dk][1], ql[dk][2], ql[dk][3]);
    }

    float o[8][4];
    #pragma unroll
    for (int nn = 0; nn < 8; nn++)
        #pragma unroll
        for (int e = 0; e < 4; e++) o[nn][e] = 0.f;
    float mst0 = -1e30f, mst1 = -1e30f, lst0 = 0.f, lst1 = 0.f;

    int qi0 = qt * 64 + 16 * w + (lane >> 2);
    int qi1 = qi0 + 8;

    for (int kc = 0; kc < 12; kc++) {
        __syncthreads();
        #pragma unroll
        for (int i = 0; i < 8; i++) {
            int sid = i * 128 + tid;
            int r = sid >> 4, c4 = (sid & 15) * 4;
            int kpos = base_kpos + kc * 64 + r;
            float4 vk = make_float4(0.f, 0.f, 0.f, 0.f);
            float4 vv = make_float4(0.f, 0.f, 0.f, 0.f);
            if (kpos >= 0 && kpos < CS) {
                size_t rb = ((size_t)(b * CS + kpos)) * QKV_S + h * 64 + c4;
                vk = *(const float4*)&qkv[rb + 768];
                vv = *(const float4*)&qkv[rb + 1536];
            }
            uint32_t h0, l0, h1, l1;
            hilo2(vk.x, vk.y, h0, l0);
            hilo2(vk.z, vk.w, h1, l1);
            *(uint2*)(fsmc + FB_KH + r * FB_ROWB + c4 * 2) = make_uint2(h0, h1);
            *(uint2*)(fsmc + FB_KL + r * FB_ROWB + c4 * 2) = make_uint2(l0, l1);
            hilo2(vv.x, vv.y, h0, l0);
            hilo2(vv.z, vv.w, h1, l1);
            *(uint2*)(fsmc + FB_VH + r * FB_ROWB + c4 * 2) = make_uint2(h0, h1);
            *(uint2*)(fsmc + FB_VL + r * FB_ROWB + c4 * 2) = make_uint2(l0, l1);
        }
        if (tid < 64) {
            int kpos = base_kpos + kc * 64 + tid;
            bool ok = (kpos >= 0) && (kpos < CS) && (kpos != 0);
            if (ok) ok = am[b * CS + kpos] > 0;
            fp[FB_CM / 4 + tid] = ok ? 1.f : 0.f;
        }
        __syncthreads();

        float s[8][4];
        #pragma unroll
        for (int nn = 0; nn < 8; nn++)
            #pragma unroll
            for (int e = 0; e < 4; e++) s[nn][e] = 0.f;
        #pragma unroll
        for (int dk = 0; dk < 4; dk++) {
            #pragma unroll
            for (int np = 0; np < 4; np++) {
                uint32_t off = (np * 16 + rsel) * FB_ROWB + dk * 32 + hsel;
                uint32_t r0, r1, r2, r3;
                uint32_t kha[2], khb[2], kla[2], klb[2];
                ldm_x4(sb + FB_KH + off, r0, r1, r2, r3);
                kha[0] = r0; kha[1] = r2; khb[0] = r1; khb[1] = r3;
                ldm_x4(sb + FB_KL + off, r0, r1, r2, r3);
                kla[0] = r0; kla[1] = r2; klb[0] = r1; klb[1] = r3;
                mma_bf16(s[2 * np],     qh[dk], kha);
                mma_bf16(s[2 * np + 1], qh[dk], khb);
                mma_bf16(s[2 * np],     ql[dk], kha);
                mma_bf16(s[2 * np + 1], ql[dk], khb);
                mma_bf16(s[2 * np],     qh[dk], kla);
                mma_bf16(s[2 * np + 1], qh[dk], klb);
            }
        }

        #pragma unroll
        for (int nn = 0; nn < 8; nn++) {
            #pragma unroll
            for (int e = 0; e < 2; e++) {
                int kj = kc * 64 + 8 * nn + t2 + e;
                float cm = fp[FB_CM / 4 + 8 * nn + t2 + e];
                bool b0 = (kj >= qi0) && (kj <= qi0 + 2 * CW) && (cm > 0.f);
                bool b1 = (kj >= qi1) && (kj <= qi1 + 2 * CW) && (cm > 0.f);
                if (!b0) s[nn][e] = CNEG;
                if (!b1) s[nn][2 + e] = CNEG;
            }
        }

        float mx0 = -1e30f, mx1 = -1e30f;
        #pragma unroll
        for (int nn = 0; nn < 8; nn++) {
            mx0 = fmaxf(mx0, fmaxf(s[nn][0], s[nn][1]));
            mx1 = fmaxf(mx1, fmaxf(s[nn][2], s[nn][3]));
        }
        mx0 = fmaxf(mx0, __shfl_xor_sync(0xffffffffu, mx0, 1));
        mx0 = fmaxf(mx0, __shfl_xor_sync(0xffffffffu, mx0, 2));
        mx1 = fmaxf(mx1, __shfl_xor_sync(0xffffffffu, mx1, 1));
        mx1 = fmaxf(mx1, __shfl_xor_sync(0xffffffffu, mx1, 2));
        float nm0 = fmaxf(mst0, mx0), nm1 = fmaxf(mst1, mx1);
        float a0 = __expf(mst0 - nm0), a1 = __expf(mst1 - nm1);
        mst0 = nm0; mst1 = nm1;
        float rs0 = 0.f, rs1 = 0.f;
        #pragma unroll
        for (int nn = 0; nn < 8; nn++) {
            s[nn][0] = __expf(s[nn][0] - nm0); rs0 += s[nn][0];
            s[nn][1] = __expf(s[nn][1] - nm0); rs0 += s[nn][1];
            s[nn][2] = __expf(s[nn][2] - nm1); rs1 += s[nn][2];
            s[nn][3] = __expf(s[nn][3] - nm1); rs1 += s[nn][3];
        }
        rs0 += __shfl_xor_sync(0xffffffffu, rs0, 1);
        rs0 += __shfl_xor_sync(0xffffffffu, rs0, 2);
        rs1 += __shfl_xor_sync(0xffffffffu, rs1, 1);
        rs1 += __shfl_xor_sync(0xffffffffu, rs1, 2);
        lst0 = lst0 * a0 + rs0;
        lst1 = lst1 * a1 + rs1;
        #pragma unroll
        for (int nn = 0; nn < 8; nn++) {
            o[nn][0] *= a0; o[nn][1] *= a0;
            o[nn][2] *= a1; o[nn][3] *= a1;
        }

        uint32_t ph[4][4], pl[4][4];
        #pragma unroll
        for (int qf = 0; qf < 4; qf++) {
            hilo2(s[2 * qf][0],     s[2 * qf][1],     ph[qf][0], pl[qf][0]);
            hilo2(s[2 * qf][2],     s[2 * qf][3],     ph[qf][1], pl[qf][1]);
            hilo2(s[2 * qf + 1][0], s[2 * qf + 1][1], ph[qf][2], pl[qf][2]);
            hilo2(s[2 * qf + 1][2], s[2 * qf + 1][3], ph[qf][3], pl[qf][3]);
        }

        #pragma unroll
        for (int qf = 0; qf < 4; qf++) {
            #pragma unroll
            for (int dp = 0; dp < 4; dp++) {
                uint32_t off = (qf * 16 + rsel) * FB_ROWB + dp * 32 + hsel;
                uint32_t r0, r1, r2, r3;
                uint32_t vha[2], vhb[2], vla[2], vlb[2];
                ldm_x4t(sb + FB_VH + off, r0, r1, r2, r3);
                vha[0] = r0; vha[1] = r1; vhb[0] = r2; vhb[1] = r3;
                ldm_x4t(sb + FB_VL + off, r0, r1, r2, r3);
                vla[0] = r0; vla[1] = r1; vlb[0] = r2; vlb[1] = r3;
                mma_bf16(o[2 * dp],     ph[qf], vha);
                mma_bf16(o[2 * dp + 1], ph[qf], vhb);
                mma_bf16(o[2 * dp],     pl[qf], vha);
                mma_bf16(o[2 * dp + 1], pl[qf], vhb);
                mma_bf16(o[2 * dp],     ph[qf], vla);
                mma_bf16(o[2 * dp + 1], ph[qf], vlb);
            }
        }
    }

    // ---- epilogue: fold in global column, normalize, write hi/lo bf16 ----
    #pragma unroll
    for (int rr = 0; rr < 2; rr++) {
        int row = 16 * w + (lane >> 2) + 8 * rr;
        float mst = rr ? mst1 : mst0;
        float lst = rr ? lst1 : lst0;
        float sg = fp[FB_SG / 4 + row];
        if (am0 <= 0) sg = CNEG;
        float nm = fmaxf(mst, sg);
        float alpha = __expf(mst - nm);
        float pg = __expf(sg - nm);
        float l = lst * alpha + pg;
        float inv = 1.0f / l;
        int srow = base_s + row;
        size_t ob = ((size_t)(b * CS + srow)) * CDM + h * 64;
        #pragma unroll
        for (int nn = 0; nn < 8; nn++) {
            int d = 8 * nn + t2;
            float v0 = (o[nn][2 * rr + 0] * alpha + pg * fp[FB_V0 / 4 + d])     * inv;
            float v1 = (o[nn][2 * rr + 1] * alpha + pg * fp[FB_V0 / 4 + d + 1]) * inv;
            uint32_t h2, l2;
            hilo2(v0, v1, h2, l2);
            *(uint32_t*)&outh[ob + d] = h2;
            *(uint32_t*)&outl[ob + d] = l2;
        }
    }
}

// ================= small kernels =================
__device__ __forceinline__ float block_reduce_sum256(float v, float* red) {
    int tid = threadIdx.x;
    red[tid] = v; __syncthreads();
    #pragma unroll
    for (int o = 128; o > 0; o >>= 1) {
        if (tid < o) red[tid] += red[tid + o];
        __syncthreads();
    }
    float r = red[0]; __syncthreads();
    return r;
}

__global__ void embed_ln_kernel(const int* __restrict__ ids,
                                const float* __restrict__ we,
                                const float* __restrict__ pe,
                                const float* __restrict__ gam,
                                const float* __restrict__ bet,
                                float* __restrict__ x,
                                __nv_bfloat16* __restrict__ xh,
                                __nv_bfloat16* __restrict__ xl) {
    __shared__ float red[256];
    int row = blockIdx.x;
    int s = row % CS;
    int id = ids[row];
    int tid = threadIdx.x;
    const float* wp = we + (size_t)id * CDM;
    const float* pp = pe + (size_t)s * CDM;
    float e[3];
    float sm = 0.f;
    #pragma unroll
    for (int i = 0; i < 3; i++) { int d = tid + i * 256; e[i] = wp[d] + pp[d]; sm += e[i]; }
    float mean = block_reduce_sum256(sm, red) * (1.0f / CDM);
    float vs = 0.f;
    #pragma unroll
    for (int i = 0; i < 3; i++) { float t = e[i] - mean; vs += t * t; }
    float var = block_reduce_sum256(vs, red) * (1.0f / CDM);
    float inv = rsqrtf(var + 1e-5f);
    float* xr = x + (size_t)row * CDM;
    size_t ro = (size_t)row * CDM;
    #pragma unroll
    for (int i = 0; i < 3; i++) {
        int d = tid + i * 256;
        float val = (e[i] - mean) * inv * gam[d] + bet[d];
        xr[d] = val;
        __nv_bfloat16 h, l;
        hilo(val, h, l);
        xh[ro + d] = h; xl[ro + d] = l;
    }
}

__global__ void add_ln_kernel(float* __restrict__ x,
                              const float* __restrict__ y,
                              const float* __restrict__ gam,
                              const float* __restrict__ bet,
                              __nv_bfloat16* __restrict__ xh,
                              __nv_bfloat16* __restrict__ xl) {
    __shared__ float red[256];
    int row = blockIdx.x;
    int tid = threadIdx.x;
    float* xr = x + (size_t)row * CDM;
    const float* yr = y + (size_t)row * CDM;
    float e[3];
    float sm = 0.f;
    #pragma unroll
    for (int i = 0; i < 3; i++) { int d = tid + i * 256; e[i] = xr[d] + yr[d]; sm += e[i]; }
    float mean = block_reduce_sum256(sm, red) * (1.0f / CDM);
    float vs = 0.f;
    #pragma unroll
    for (int i = 0; i < 3; i++) { float t = e[i] - mean; vs += t * t; }
    float var = block_reduce_sum256(vs, red) * (1.0f / CDM);
    float inv = rsqrtf(var + 1e-5f);
    size_t ro = (size_t)row * CDM;
    #pragma unroll
    for (int i = 0; i < 3; i++) {
        int d = tid + i * 256;
        float val = (e[i] - mean) * inv * gam[d] + bet[d];
        xr[d] = val;
        __nv_bfloat16 h, l;
        hilo(val, h, l);
        xh[ro + d] = h; xl[ro + d] = l;
    }
}

__global__ void qg_kernel(const float* __restrict__ x,
                          const float* __restrict__ Wqg,
                          const float* __restrict__ bqg,
                          float* __restrict__ qg) {
    int nidx = blockIdx.x * 256 + threadIdx.x;
    int b = blockIdx.y;
    const float* xr = x + (size_t)(b * CS) * CDM;
    float acc = bqg[nidx];
    for (int kk = 0; kk < CDM; kk++)
        acc += xr[kk] * Wqg[(size_t)kk * CDM + nidx];
    qg[b * CDM + nidx] = acc * CSCALE;
}

// overwrites row 0 attention output (hi/lo bf16)
__global__ void global_attn_kernel(const float* __restrict__ qg,
                                   const float* __restrict__ gkv,
                                   const int* __restrict__ am,
                                   __nv_bfloat16* __restrict__ outh,
                                   __nv_bfloat16* __restrict__ outl) {
    __shared__ float scs[CS];
    __shared__ float red[256];
    __shared__ float qs[64];
    int h = blockIdx.x, b = blockIdx.y;
    int tid = threadIdx.x;
    if (tid < 64) qs[tid] = qg[b * CDM + h * 64 + tid];
    __syncthreads();

    float mx = -1e30f;
    for (int s = tid; s < CS; s += 256) {
        const float* kp = &gkv[((size_t)(b * CS + s)) * GKV_S + h * 64];
        float dd = 0.f;
        #pragma unroll
        for (int e = 0; e < 64; e++) dd += qs[e] * kp[e];
        if (am[b * CS + s] <= 0) dd = CNEG;
        scs[s] = dd;
        mx = fmaxf(mx, dd);
    }
    red[tid] = mx; __syncthreads();
    #pragma unroll
    for (int o = 128; o > 0; o >>= 1) {
        if (tid < o) red[tid] = fmaxf(red[tid], red[tid + o]);
        __syncthreads();
    }
    mx = red[0]; __syncthreads();

    float sm = 0.f;
    for (int s = tid; s < CS; s += 256) {
        float e = __expf(scs[s] - mx);
        scs[s] = e; sm += e;
    }
    float tot = block_reduce_sum256(sm, red);
    float inv = 1.0f / tot;
    __syncthreads();

    int d = tid & 63, sl = tid >> 6;
    float acc = 0.f;
    for (int s = sl * 1024; s < (sl + 1) * 1024; s++)
        acc += scs[s] * gkv[((size_t)(b * CS + s)) * GKV_S + 768 + h * 64 + d];
    red[tid] = acc; __syncthreads();
    if (sl == 0) {
        float t = red[d] + red[64 + d] + red[128 + d] + red[192 + d];
        float val = t * inv;
        __nv_bfloat16 hh, ll;
        hilo(val, hh, ll);
        size_t ob = ((size_t)(b * CS)) * CDM + h * 64 + d;
        outh[ob] = hh;
        outl[ob] = ll;
    }
}

__global__ void cls_kernel(const float* __restrict__ x,
                           const float* __restrict__ Wc,
                           const float* __restrict__ bc,
                           float* __restrict__ out) {
    __shared__ float red[256];
    int b = blockIdx.x >> 1, c = blockIdx.x & 1;
    int tid = threadIdx.x;
    const float* xr = x + (size_t)(b * CS) * CDM;
    float acc = 0.f;
    for (int d = tid; d < CDM; d += 256) acc += xr[d] * Wc[d * 2 + c];
    float tot = block_reduce_sum256(acc, red);
    if (tid == 0) out[b * 2 + c] = tot + bc[c];
}

// ================= launch =================
extern "C" void kernel_launch(void* const* d_in, const int* in_sizes, int n_in,
                              void* d_out, int out_size) {
    const int*   ids  = (const int*)d_in[0];
    const int*   am   = (const int*)d_in[1];
    const float* we   = (const float*)d_in[2];
    const float* pe   = (const float*)d_in[3];
    const float* lnes = (const float*)d_in[4];
    const float* lneb = (const float*)d_in[5];
    const float* Wq   = (const float*)d_in[6];
    const float* bq   = (const float*)d_in[7];
    const float* Wk   = (const float*)d_in[8];
    const float* bk   = (const float*)d_in[9];
    const float* Wv   = (const float*)d_in[10];
    const float* bv   = (const float*)d_in[11];
    const float* Wqg  = (const float*)d_in[12];
    const float* bqg  = (const float*)d_in[13];
    const float* Wkg  = (const float*)d_in[14];
    const float* bkg  = (const float*)d_in[15];
    const float* Wvg  = (const float*)d_in[16];
    const float* bvg  = (const float*)d_in[17];
    const float* Wo   = (const float*)d_in[18];
    const float* bo   = (const float*)d_in[19];
    const float* ln1s = (const float*)d_in[20];
    const float* ln1b = (const float*)d_in[21];
    const float* W1   = (const float*)d_in[22];
    const float* b1   = (const float*)d_in[23];
    const float* W2   = (const float*)d_in[24];
    const float* b2   = (const float*)d_in[25];
    const float* ln2s = (const float*)d_in[26];
    const float* ln2b = (const float*)d_in[27];
    const float* Wcls = (const float*)d_in[28];
    const float* bcls = (const float*)d_in[29];
    float* out = (float*)d_out;

    float *xp, *yp, *qkvp, *gkvp, *qgp, *biasp;
    __nv_bfloat16 *xhp, *xlp, *ahp, *alp, *hhp, *hlp, *whp, *wlp;
    cudaGetSymbolAddress((void**)&xp,   g_x);
    cudaGetSymbolAddress((void**)&yp,   g_y);
    cudaGetSymbolAddress((void**)&qkvp, g_qkv);
    cudaGetSymbolAddress((void**)&gkvp, g_gkv);
    cudaGetSymbolAddress((void**)&qgp,  g_qg);
    cudaGetSymbolAddress((void**)&biasp, g_bias);
    cudaGetSymbolAddress((void**)&xhp,  g_xbh);
    cudaGetSymbolAddress((void**)&xlp,  g_xbl);
    cudaGetSymbolAddress((void**)&ahp,  g_abh);
    cudaGetSymbolAddress((void**)&alp,  g_abl);
    cudaGetSymbolAddress((void**)&hhp,  g_hbh);
    cudaGetSymbolAddress((void**)&hlp,  g_hbl);
    cudaGetSymbolAddress((void**)&whp,  g_wbh);
    cudaGetSymbolAddress((void**)&wlp,  g_wbl);

    cudaFuncSetAttribute(gemm_mma_kernel, cudaFuncAttributeMaxDynamicSharedMemorySize, GSM_TOT);
    cudaFuncSetAttribute(flash_band_kernel, cudaFuncAttributeMaxDynamicSharedMemorySize, FB_TOT);

    embed_ln_kernel<<<MROWS, 256>>>(ids, we, pe, lnes, lneb, xp, xhp, xlp);

    dim3 wt_dm(CDM / 32, CDM / 32);
    dim3 wt_b(32, 8);
    size_t wseg = (size_t)CDM * CDM;

    for (int l = 0; l < CL; l++) {
        size_t woff = (size_t)l * CDM * CDM;
        size_t boff = (size_t)l * CDM;
        size_t w1off = (size_t)l * CDM * CDFF;
        size_t b1off = (size_t)l * CDFF;
        size_t w2off = (size_t)l * CDFF * CDM;

        // --- fused QKV ---
        split_wt_kernel<<<wt_dm, wt_b>>>(Wq + woff, whp,            wlp,            CDM, CDM);
        split_wt_kernel<<<wt_dm, wt_b>>>(Wk + woff, whp + wseg,     wlp + wseg,     CDM, CDM);
        split_wt_kernel<<<wt_dm, wt_b>>>(Wv + woff, whp + 2 * wseg, wlp + 2 * wseg, CDM, CDM);
        pack_bias_kernel<<<9, 256>>>(biasp, bq + boff, bk + boff, bv + boff);
        gemm_mma_kernel<<<dim3(QKV_S / 128, MROWS / 128), 256, GSM_TOT>>>(
            xhp, xlp, whp, wlp, biasp, qkvp, nullptr, nullptr, CDM, QKV_S, 0);

        flash_band_kernel<<<dim3(4, CB * CH * CNB), 128, FB_TOT>>>(qkvp, am, ahp, alp);

        // --- fused Kg/Vg + global attention ---
        qg_kernel<<<dim3(CDM / 256, CB), 256>>>(xp, Wqg + woff, bqg + boff, qgp);
        split_wt_kernel<<<wt_dm, wt_b>>>(Wkg + woff, whp,        wlp,        CDM, CDM);
        split_wt_kernel<<<wt_dm, wt_b>>>(Wvg + woff, whp + wseg, wlp + wseg, CDM, CDM);
        pack_bias_kernel<<<6, 256>>>(biasp, bkg + boff, bvg + boff, bvg + boff);
        gemm_mma_kernel<<<dim3(GKV_S / 128, MROWS / 128), 256, GSM_TOT>>>(
            xhp, xlp, whp, wlp, biasp, gkvp, nullptr, nullptr, CDM, GKV_S, 0);
        global_attn_kernel<<<dim3(CH, CB), 256>>>(qgp, gkvp, am, ahp, alp);

        // --- Wo projection + LN1 ---
        split_wt_kernel<<<wt_dm, wt_b>>>(Wo + woff, whp, wlp, CDM, CDM);
        gemm_mma_kernel<<<dim3(CDM / 128, MROWS / 128), 256, GSM_TOT>>>(
            ahp, alp, whp, wlp, bo + boff, yp, nullptr, nullptr, CDM, CDM, 0);
        add_ln_kernel<<<MROWS, 256>>>(xp, yp, ln1s + boff, ln1b + boff, xhp, xlp);

        // --- FFN ---
        split_wt_kernel<<<dim3(CDFF / 32, CDM / 32), wt_b>>>(W1 + w1off, whp, wlp, CDM, CDFF);
        gemm_mma_kernel<<<dim3(CDFF / 128, MROWS / 128), 256, GSM_TOT>>>(
            xhp, xlp, whp, wlp, b1 + b1off, nullptr, hhp, hlp, CDM, CDFF, 2);

        split_wt_kernel<<<dim3(CDM / 32, CDFF / 32), wt_b>>>(W2 + w2off, whp, wlp, CDFF, CDM);
        gemm_mma_kernel<<<dim3(CDM / 128, MROWS / 128), 256, GSM_TOT>>>(
            hhp, hlp, whp, wlp, b2 + boff, yp, nullptr, nullptr, CDFF, CDM, 0);
        add_ln_kernel<<<MROWS, 256>>>(xp, yp, ln2s + boff, ln2b + boff, xhp, xlp);
    }

    cls_kernel<<<4, 256>>>(xp, Wcls, bcls, out);
}

// round 11
// speedup vs baseline: 1.5440x; 1.0489x over previous
#include <cuda_runtime.h>
#include <cuda_bf16.h>
#include <math.h>
#include <stdint.h>

// ---------------- problem constants ----------------
#define CB   2
#define CS   4096
#define CH   12
#define CD   64
#define CW   256
#define CDM  768
#define CDFF 3072
#define CNB  16
#define CL   2
#define CNEG (-1000000000.0f)
#define CSCALE 0.125f

#define MROWS (CB*CS)    // 8192
#define QKV_S 2304

// ---------------- scratch ----------------
__device__ float g_x   [MROWS*CDM];
__device__ float g_y   [MROWS*CDM];
__device__ float g_qkv [(size_t)MROWS*QKV_S];
__device__ float g_qg  [CB*CDM];
__device__ float g_bias[QKV_S];
__device__ float g_t   [CB*CH*CDM];
__device__ float g_p   [(size_t)CB*CH*CS];
__device__ float g_u   [CB*CH*CDM];
// hi/lo bf16 operand buffers
__device__ __nv_bfloat16 g_xbh[(size_t)MROWS*CDM];
__device__ __nv_bfloat16 g_xbl[(size_t)MROWS*CDM];
__device__ __nv_bfloat16 g_abh[(size_t)MROWS*CDM];
__device__ __nv_bfloat16 g_abl[(size_t)MROWS*CDM];
__device__ __nv_bfloat16 g_hbh[(size_t)MROWS*CDFF];
__device__ __nv_bfloat16 g_hbl[(size_t)MROWS*CDFF];
__device__ __nv_bfloat16 g_wbh[(size_t)CDFF*CDM];
__device__ __nv_bfloat16 g_wbl[(size_t)CDFF*CDM];

// ---------------- helpers ----------------
__device__ __forceinline__ float gelu_tanh(float x) {
    float x3 = x * x * x;
    return 0.5f * x * (1.0f + tanhf(0.7978845608028654f * (x + 0.044715f * x3)));
}
__device__ __forceinline__ uint32_t smem_u32(const void* p) {
    uint32_t a;
    asm("{ .reg .u64 t; cvta.to.shared.u64 t, %1; cvt.u32.u64 %0, t; }" : "=r"(a) : "l"(p));
    return a;
}
__device__ __forceinline__ void hilo(float v, __nv_bfloat16& h, __nv_bfloat16& l) {
    h = __float2bfloat16_rn(v);
    l = __float2bfloat16_rn(v - __bfloat162float(h));
}
__device__ __forceinline__ void hilo2(float a, float b, uint32_t& h, uint32_t& l) {
    __nv_bfloat16 ha, la, hb, lb;
    hilo(a, ha, la);
    hilo(b, hb, lb);
    __nv_bfloat162 hh = __halves2bfloat162(ha, hb);
    __nv_bfloat162 ll = __halves2bfloat162(la, lb);
    h = *(uint32_t*)&hh;
    l = *(uint32_t*)&ll;
}

// ================= split/convert kernels =================
__global__ void split_wt_kernel(const float* __restrict__ W,
                                __nv_bfloat16* __restrict__ Wth,
                                __nv_bfloat16* __restrict__ Wtl, int K, int N) {
    __shared__ float t[32][33];
    int n0 = blockIdx.x * 32, k0 = blockIdx.y * 32;
    int tx = threadIdx.x, ty = threadIdx.y;
    #pragma unroll
    for (int r = 0; r < 4; r++) {
        int k = k0 + ty + r * 8;
        t[ty + r * 8][tx] = W[(size_t)k * N + n0 + tx];
    }
    __syncthreads();
    #pragma unroll
    for (int r = 0; r < 4; r++) {
        int n = n0 + ty + r * 8;
        int k = k0 + tx;
        __nv_bfloat16 h, l;
        hilo(t[tx][ty + r * 8], h, l);
        size_t ro = (size_t)n * K + k;
        Wth[ro] = h;
        Wtl[ro] = l;
    }
}

__global__ void pack_bias_kernel(float* __restrict__ dst,
                                 const float* __restrict__ s0,
                                 const float* __restrict__ s1,
                                 const float* __restrict__ s2) {
    int i = blockIdx.x * 256 + threadIdx.x;
    int s = i / 768, r = i - s * 768;
    const float* p = (s == 0) ? s0 : (s == 1 ? s1 : s2);
    dst[i] = p[r];
}

// ================= warp-MMA bf16 GEMM (hi/lo fragment reuse) =================
#define MAT_B 10240
#define STG_BYTES (4*MAT_B)
#define GSM_TOT (2*STG_BYTES)   // 81920

__device__ __forceinline__ void ldm_x4(uint32_t addr, uint32_t& r0, uint32_t& r1,
                                       uint32_t& r2, uint32_t& r3) {
    asm volatile("ldmatrix.sync.aligned.m8n8.x4.shared.b16 {%0,%1,%2,%3}, [%4];"
        : "=r"(r0), "=r"(r1), "=r"(r2), "=r"(r3) : "r"(addr));
}
__device__ __forceinline__ void ldm_x4t(uint32_t addr, uint32_t& r0, uint32_t& r1,
                                        uint32_t& r2, uint32_t& r3) {
    asm volatile("ldmatrix.sync.aligned.m8n8.x4.trans.shared.b16 {%0,%1,%2,%3}, [%4];"
        : "=r"(r0), "=r"(r1), "=r"(r2), "=r"(r3) : "r"(addr));
}
__device__ __forceinline__ void mma_bf16(float* c, const uint32_t* a, const uint32_t* b) {
    asm volatile("mma.sync.aligned.m16n8k16.row.col.f32.bf16.bf16.f32 "
        "{%0,%1,%2,%3}, {%4,%5,%6,%7}, {%8,%9}, {%0,%1,%2,%3};"
        : "+f"(c[0]), "+f"(c[1]), "+f"(c[2]), "+f"(c[3])
        : "r"(a[0]), "r"(a[1]), "r"(a[2]), "r"(a[3]), "r"(b[0]), "r"(b[1]));
}

__global__ __launch_bounds__(256, 2)
void gemm_mma_kernel(const __nv_bfloat16* __restrict__ Ah,
                     const __nv_bfloat16* __restrict__ Al,
                     const __nv_bfloat16* __restrict__ Bh,
                     const __nv_bfloat16* __restrict__ Bl,
                     const float* __restrict__ bias,
                     float* __restrict__ Cf,
                     __nv_bfloat16* __restrict__ Cbh,
                     __nv_bfloat16* __restrict__ Cbl,
                     int Kp, int N, int mode) {
    extern __shared__ __align__(1024) char smem[];
    uint32_t sb = smem_u32(smem);
    int tid = threadIdx.x;
    int wid = tid >> 5, lane = tid & 31;
    int m0 = blockIdx.y * 128, n0 = blockIdx.x * 128;
    int warp_m = (wid & 1) * 64;
    int warp_n = (wid >> 1) * 32;
    int NC = Kp / 32;

    const __nv_bfloat16* Agh = Ah + (size_t)m0 * Kp;
    const __nv_bfloat16* Agl = Al + (size_t)m0 * Kp;
    const __nv_bfloat16* Bgh = Bh + (size_t)n0 * Kp;
    const __nv_bfloat16* Bgl = Bl + (size_t)n0 * Kp;

    float acc[4][4][4];
    #pragma unroll
    for (int i = 0; i < 4; i++)
        #pragma unroll
        for (int j = 0; j < 4; j++)
            #pragma unroll
            for (int r = 0; r < 4; r++) acc[i][j][r] = 0.f;

    auto load_tile = [&](int c, int bf) {
        uint32_t base = sb + bf * STG_BYTES;
        const __nv_bfloat16* srcs[4] = {
            Agh + (size_t)c * 32, Agl + (size_t)c * 32,
            Bgh + (size_t)c * 32, Bgl + (size_t)c * 32 };
        #pragma unroll
        for (int m = 0; m < 4; m++) {
            const __nv_bfloat16* S = srcs[m];
            uint32_t mb = base + m * MAT_B;
            #pragma unroll
            for (int i = 0; i < 2; i++) {
                int ch = i * 256 + tid;
                int r = ch >> 2, c8 = (ch & 3) * 8;
                uint32_t d = mb + r * 80 + c8 * 2;
                const void* s = S + (size_t)r * Kp + c8;
                asm volatile("cp.async.cg.shared.global [%0], [%1], 16;" :: "r"(d), "l"(s));
            }
        }
    };

    load_tile(0, 0);
    asm volatile("cp.async.commit_group;" ::: "memory");

    int rsel = lane & 15, hsel = (lane >> 4) * 16;
    for (int c = 0; c < NC; c++) {
        int bf = c & 1;
        if (c + 1 < NC) load_tile(c + 1, bf ^ 1);
        asm volatile("cp.async.commit_group;" ::: "memory");
        asm volatile("cp.async.wait_group 1;" ::: "memory");
        __syncthreads();

        uint32_t ahb = sb + bf * STG_BYTES;
        uint32_t alb = ahb + MAT_B;
        uint32_t bhb = ahb + 2 * MAT_B;
        uint32_t blb = ahb + 3 * MAT_B;

        #pragma unroll
        for (int ks = 0; ks < 2; ks++) {
            uint32_t ah[4][4], al[4][4], bh[4][2], bl[4][2];
            #pragma unroll
            for (int mi = 0; mi < 4; mi++) {
                uint32_t off = (warp_m + mi * 16 + rsel) * 80 + ks * 32 + hsel;
                ldm_x4(ahb + off, ah[mi][0], ah[mi][1], ah[mi][2], ah[mi][3]);
                ldm_x4(alb + off, al[mi][0], al[mi][1], al[mi][2], al[mi][3]);
            }
            #pragma unroll
            for (int np = 0; np < 2; np++) {
                uint32_t off = (warp_n + np * 16 + rsel) * 80 + ks * 32 + hsel;
                uint32_t r0, r1, r2, r3;
                ldm_x4(bhb + off, r0, r1, r2, r3);
                bh[np * 2 + 0][0] = r0; bh[np * 2 + 0][1] = r2;
                bh[np * 2 + 1][0] = r1; bh[np * 2 + 1][1] = r3;
                ldm_x4(blb + off, r0, r1, r2, r3);
                bl[np * 2 + 0][0] = r0; bl[np * 2 + 0][1] = r2;
                bl[np * 2 + 1][0] = r1; bl[np * 2 + 1][1] = r3;
            }
            #pragma unroll
            for (int mi = 0; mi < 4; mi++)
                #pragma unroll
                for (int nj = 0; nj < 4; nj++)
                    mma_bf16(acc[mi][nj], ah[mi], bh[nj]);
            #pragma unroll
            for (int mi = 0; mi < 4; mi++)
                #pragma unroll
                for (int nj = 0; nj < 4; nj++)
                    mma_bf16(acc[mi][nj], al[mi], bh[nj]);
            #pragma unroll
            for (int mi = 0; mi < 4; mi++)
                #pragma unroll
                for (int nj = 0; nj < 4; nj++)
                    mma_bf16(acc[mi][nj], ah[mi], bl[nj]);
        }
        __syncthreads();
    }

    int g = lane >> 2, t = lane & 3;
    #pragma unroll
    for (int mi = 0; mi < 4; mi++) {
        int row0 = m0 + warp_m + mi * 16 + g;
        #pragma unroll
        for (int nj = 0; nj < 4; nj++) {
            int col = n0 + warp_n + nj * 8 + t * 2;
            float bx = bias[col], by = bias[col + 1];
            float v0 = acc[mi][nj][0] + bx, v1 = acc[mi][nj][1] + by;
            float v2 = acc[mi][nj][2] + bx, v3 = acc[mi][nj][3] + by;
            if (mode >= 1) { v0 = gelu_tanh(v0); v1 = gelu_tanh(v1); v2 = gelu_tanh(v2); v3 = gelu_tanh(v3); }
            if (mode == 2) {
                #pragma unroll
                for (int rr = 0; rr < 2; rr++) {
                    int row = row0 + rr * 8;
                    float a0 = rr ? v2 : v0, a1 = rr ? v3 : v1;
                    uint32_t h2, l2;
                    hilo2(a0, a1, h2, l2);
                    size_t ro = (size_t)row * N + col;
                    *(uint32_t*)&Cbh[ro] = h2;
                    *(uint32_t*)&Cbl[ro] = l2;
                }
            } else {
                *(float2*)&Cf[(size_t)row0 * N + col]       = make_float2(v0, v1);
                *(float2*)&Cf[(size_t)(row0 + 8) * N + col] = make_float2(v2, v3);
            }
        }
    }
}

// ================= fused flash band attention (tensor-core hi/lo) ==========
#define FB_ROWB 144
#define FB_QH 0
#define FB_QL (FB_QH + 64*FB_ROWB)
#define FB_KH (FB_QL + 64*FB_ROWB)
#define FB_KL (FB_KH + 64*FB_ROWB)
#define FB_VH (FB_KL + 64*FB_ROWB)
#define FB_VL (FB_VH + 64*FB_ROWB)
#define FB_SG (FB_VL + 64*FB_ROWB)
#define FB_V0 (FB_SG + 256)
#define FB_CM (FB_V0 + 256)
#define FB_TOT (FB_CM + 256 + 64)

__global__ __launch_bounds__(128)
void flash_band_kernel(const float* __restrict__ qkv,
                       const int* __restrict__ am,
                       __nv_bfloat16* __restrict__ outh,
                       __nv_bfloat16* __restrict__ outl) {
    extern __shared__ char fsmc[];
    float* fp = (float*)fsmc;
    uint32_t sb = smem_u32(fsmc);
    int z = blockIdx.y;
    int n = z % CNB;
    int h = (z / CNB) % CH;
    int b = z / (CNB * CH);
    int qt = blockIdx.x;
    int tid = threadIdx.x;
    int w = tid >> 5, lane = tid & 31;
    int rsel = lane & 15, hsel = (lane >> 4) * 16;
    int t2 = (lane & 3) * 2;

    int base_s    = n * CW + qt * 64;
    int base_kpos = n * CW - CW;
    int am0 = am[b * CS];

    #pragma unroll
    for (int i = 0; i < 8; i++) {
        int sid = i * 128 + tid;
        int r = sid >> 4, c4 = (sid & 15) * 4;
        float4 vq = *(const float4*)&qkv[((size_t)(b * CS + base_s + r)) * QKV_S + h * 64 + c4];
        vq.x *= CSCALE; vq.y *= CSCALE; vq.z *= CSCALE; vq.w *= CSCALE;
        uint32_t h0, l0, h1, l1;
        hilo2(vq.x, vq.y, h0, l0);
        hilo2(vq.z, vq.w, h1, l1);
        *(uint2*)(fsmc + FB_QH + r * FB_ROWB + c4 * 2) = make_uint2(h0, h1);
        *(uint2*)(fsmc + FB_QL + r * FB_ROWB + c4 * 2) = make_uint2(l0, l1);
    }
    if (tid < 64)
        fp[FB_V0 / 4 + tid] = qkv[((size_t)(b * CS)) * QKV_S + 1536 + h * 64 + tid];
    __syncthreads();

    {
        int row = tid >> 1, half = tid & 1;
        const __nv_bfloat16* qh = (const __nv_bfloat16*)(fsmc + FB_QH + row * FB_ROWB);
        const __nv_bfloat16* ql = (const __nv_bfloat16*)(fsmc + FB_QL + row * FB_ROWB);
        const float* k0p = &qkv[((size_t)(b * CS)) * QKV_S + 768 + h * 64];
        float sgv = 0.f;
        #pragma unroll
        for (int d = 0; d < 32; d++) {
            int dd = half * 32 + d;
            sgv += (__bfloat162float(qh[dd]) + __bfloat162float(ql[dd])) * k0p[dd];
        }
        sgv += __shfl_xor_sync(0xffffffffu, sgv, 1);
        if (half == 0) fp[FB_SG / 4 + row] = sgv;
    }

    uint32_t qh[4][4], ql[4][4];
    #pragma unroll
    for (int dk = 0; dk < 4; dk++) {
        uint32_t off = (16 * w + rsel) * FB_ROWB + dk * 32 + hsel;
        ldm_x4(sb + FB_QH + off, qh[dk][0], qh[dk][1], qh[dk][2], qh[dk][3]);
        ldm_x4(sb + FB_QL + off, ql[dk][0], ql[dk][1], ql[dk][2], ql[dk][3]);
    }

    float o[8][4];
    #pragma unroll
    for (int nn = 0; nn < 8; nn++)
        #pragma unroll
        for (int e = 0; e < 4; e++) o[nn][e] = 0.f;
    float mst0 = -1e30f, mst1 = -1e30f, lst0 = 0.f, lst1 = 0.f;

    int qi0 = qt * 64 + 16 * w + (lane >> 2);
    int qi1 = qi0 + 8;

    for (int kc = 0; kc < 12; kc++) {
        __syncthreads();
        #pragma unroll
        for (int i = 0; i < 8; i++) {
            int sid = i * 128 + tid;
            int r = sid >> 4, c4 = (sid & 15) * 4;
            int kpos = base_kpos + kc * 64 + r;
            float4 vk = make_float4(0.f, 0.f, 0.f, 0.f);
            float4 vv = make_float4(0.f, 0.f, 0.f, 0.f);
            if (kpos >= 0 && kpos < CS) {
                size_t rb = ((size_t)(b * CS + kpos)) * QKV_S + h * 64 + c4;
                vk = *(const float4*)&qkv[rb + 768];
                vv = *(const float4*)&qkv[rb + 1536];
            }
            uint32_t h0, l0, h1, l1;
            hilo2(vk.x, vk.y, h0, l0);
            hilo2(vk.z, vk.w, h1, l1);
            *(uint2*)(fsmc + FB_KH + r * FB_ROWB + c4 * 2) = make_uint2(h0, h1);
            *(uint2*)(fsmc + FB_KL + r * FB_ROWB + c4 * 2) = make_uint2(l0, l1);
            hilo2(vv.x, vv.y, h0, l0);
            hilo2(vv.z, vv.w, h1, l1);
            *(uint2*)(fsmc + FB_VH + r * FB_ROWB + c4 * 2) = make_uint2(h0, h1);
            *(uint2*)(fsmc + FB_VL + r * FB_ROWB + c4 * 2) = make_uint2(l0, l1);
        }
        if (tid < 64) {
            int kpos = base_kpos + kc * 64 + tid;
            bool ok = (kpos >= 0) && (kpos < CS) && (kpos != 0);
            if (ok) ok = am[b * CS + kpos] > 0;
            fp[FB_CM / 4 + tid] = ok ? 1.f : 0.f;
        }
        __syncthreads();

        float s[8][4];
        #pragma unroll
        for (int nn = 0; nn < 8; nn++)
            #pragma unroll
            for (int e = 0; e < 4; e++) s[nn][e] = 0.f;
        #pragma unroll
        for (int dk = 0; dk < 4; dk++) {
            #pragma unroll
            for (int np = 0; np < 4; np++) {
                uint32_t off = (np * 16 + rsel) * FB_ROWB + dk * 32 + hsel;
                uint32_t r0, r1, r2, r3;
                uint32_t kha[2], khb[2], kla[2], klb[2];
                ldm_x4(sb + FB_KH + off, r0, r1, r2, r3);
                kha[0] = r0; kha[1] = r2; khb[0] = r1; khb[1] = r3;
                ldm_x4(sb + FB_KL + off, r0, r1, r2, r3);
                kla[0] = r0; kla[1] = r2; klb[0] = r1; klb[1] = r3;
                mma_bf16(s[2 * np],     qh[dk], kha);
                mma_bf16(s[2 * np + 1], qh[dk], khb);
                mma_bf16(s[2 * np],     ql[dk], kha);
                mma_bf16(s[2 * np + 1], ql[dk], khb);
                mma_bf16(s[2 * np],     qh[dk], kla);
                mma_bf16(s[2 * np + 1], qh[dk], klb);
            }
        }

        #pragma unroll
        for (int nn = 0; nn < 8; nn++) {
            #pragma unroll
            for (int e = 0; e < 2; e++) {
                int kj = kc * 64 + 8 * nn + t2 + e;
                float cm = fp[FB_CM / 4 + 8 * nn + t2 + e];
                bool b0 = (kj >= qi0) && (kj <= qi0 + 2 * CW) && (cm > 0.f);
                bool b1 = (kj >= qi1) && (kj <= qi1 + 2 * CW) && (cm > 0.f);
                if (!b0) s[nn][e] = CNEG;
                if (!b1) s[nn][2 + e] = CNEG;
            }
        }

        float mx0 = -1e30f, mx1 = -1e30f;
        #pragma unroll
        for (int nn = 0; nn < 8; nn++) {
            mx0 = fmaxf(mx0, fmaxf(s[nn][0], s[nn][1]));
            mx1 = fmaxf(mx1, fmaxf(s[nn][2], s[nn][3]));
        }
        mx0 = fmaxf(mx0, __shfl_xor_sync(0xffffffffu, mx0, 1));
        mx0 = fmaxf(mx0, __shfl_xor_sync(0xffffffffu, mx0, 2));
        mx1 = fmaxf(mx1, __shfl_xor_sync(0xffffffffu, mx1, 1));
        mx1 = fmaxf(mx1, __shfl_xor_sync(0xffffffffu, mx1, 2));
        float nm0 = fmaxf(mst0, mx0), nm1 = fmaxf(mst1, mx1);
        float a0 = __expf(mst0 - nm0), a1 = __expf(mst1 - nm1);
        mst0 = nm0; mst1 = nm1;
        float rs0 = 0.f, rs1 = 0.f;
        #pragma unroll
        for (int nn = 0; nn < 8; nn++) {
            s[nn][0] = __expf(s[nn][0] - nm0); rs0 += s[nn][0];
            s[nn][1] = __expf(s[nn][1] - nm0); rs0 += s[nn][1];
            s[nn][2] = __expf(s[nn][2] - nm1); rs1 += s[nn][2];
            s[nn][3] = __expf(s[nn][3] - nm1); rs1 += s[nn][3];
        }
        rs0 += __shfl_xor_sync(0xffffffffu, rs0, 1);
        rs0 += __shfl_xor_sync(0xffffffffu, rs0, 2);
        rs1 += __shfl_xor_sync(0xffffffffu, rs1, 1);
        rs1 += __shfl_xor_sync(0xffffffffu, rs1, 2);
        lst0 = lst0 * a0 + rs0;
        lst1 = lst1 * a1 + rs1;
        #pragma unroll
        for (int nn = 0; nn < 8; nn++) {
            o[nn][0] *= a0; o[nn][1] *= a0;
            o[nn][2] *= a1; o[nn][3] *= a1;
        }

        uint32_t ph[4][4], pl[4][4];
        #pragma unroll
        for (int qf = 0; qf < 4; qf++) {
            hilo2(s[2 * qf][0],     s[2 * qf][1],     ph[qf][0], pl[qf][0]);
            hilo2(s[2 * qf][2],     s[2 * qf][3],     ph[qf][1], pl[qf][1]);
            hilo2(s[2 * qf + 1][0], s[2 * qf + 1][1], ph[qf][2], pl[qf][2]);
            hilo2(s[2 * qf + 1][2], s[2 * qf + 1][3], ph[qf][3], pl[qf][3]);
        }

        #pragma unroll
        for (int qf = 0; qf < 4; qf++) {
            #pragma unroll
            for (int dp = 0; dp < 4; dp++) {
                uint32_t off = (qf * 16 + rsel) * FB_ROWB + dp * 32 + hsel;
                uint32_t r0, r1, r2, r3;
                uint32_t vha[2], vhb[2], vla[2], vlb[2];
                ldm_x4t(sb + FB_VH + off, r0, r1, r2, r3);
                vha[0] = r0; vha[1] = r1; vhb[0] = r2; vhb[1] = r3;
                ldm_x4t(sb + FB_VL + off, r0, r1, r2, r3);
                vla[0] = r0; vla[1] = r1; vlb[0] = r2; vlb[1] = r3;
                mma_bf16(o[2 * dp],     ph[qf], vha);
                mma_bf16(o[2 * dp + 1], ph[qf], vhb);
                mma_bf16(o[2 * dp],     pl[qf], vha);
                mma_bf16(o[2 * dp + 1], pl[qf], vhb);
                mma_bf16(o[2 * dp],     ph[qf], vla);
                mma_bf16(o[2 * dp + 1], ph[qf], vlb);
            }
        }
    }

    #pragma unroll
    for (int rr = 0; rr < 2; rr++) {
        int row = 16 * w + (lane >> 2) + 8 * rr;
        float mst = rr ? mst1 : mst0;
        float lst = rr ? lst1 : lst0;
        float sg = fp[FB_SG / 4 + row];
        if (am0 <= 0) sg = CNEG;
        float nm = fmaxf(mst, sg);
        float alpha = __expf(mst - nm);
        float pg = __expf(sg - nm);
        float l = lst * alpha + pg;
        float inv = 1.0f / l;
        int srow = base_s + row;
        size_t ob = ((size_t)(b * CS + srow)) * CDM + h * 64;
        #pragma unroll
        for (int nn = 0; nn < 8; nn++) {
            int d = 8 * nn + t2;
            float v0 = (o[nn][2 * rr + 0] * alpha + pg * fp[FB_V0 / 4 + d])     * inv;
            float v1 = (o[nn][2 * rr + 1] * alpha + pg * fp[FB_V0 / 4 + d + 1]) * inv;
            uint32_t h2, l2;
            hilo2(v0, v1, h2, l2);
            *(uint32_t*)&outh[ob + d] = h2;
            *(uint32_t*)&outl[ob + d] = l2;
        }
    }
}

// ================= small kernels =================
__device__ __forceinline__ float block_reduce_sum256(float v, float* red) {
    int tid = threadIdx.x;
    red[tid] = v; __syncthreads();
    #pragma unroll
    for (int o = 128; o > 0; o >>= 1) {
        if (tid < o) red[tid] += red[tid + o];
        __syncthreads();
    }
    float r = red[0]; __syncthreads();
    return r;
}

__global__ void embed_ln_kernel(const int* __restrict__ ids,
                                const float* __restrict__ we,
                                const float* __restrict__ pe,
                                const float* __restrict__ gam,
                                const float* __restrict__ bet,
                                float* __restrict__ x,
                                __nv_bfloat16* __restrict__ xh,
                                __nv_bfloat16* __restrict__ xl) {
    __shared__ float red[256];
    int row = blockIdx.x;
    int s = row % CS;
    int id = ids[row];
    int tid = threadIdx.x;
    const float* wp = we + (size_t)id * CDM;
    const float* pp = pe + (size_t)s * CDM;
    float e[3];
    float sm = 0.f;
    #pragma unroll
    for (int i = 0; i < 3; i++) { int d = tid + i * 256; e[i] = wp[d] + pp[d]; sm += e[i]; }
    float mean = block_reduce_sum256(sm, red) * (1.0f / CDM);
    float vs = 0.f;
    #pragma unroll
    for (int i = 0; i < 3; i++) { float t = e[i] - mean; vs += t * t; }
    float var = block_reduce_sum256(vs, red) * (1.0f / CDM);
    float inv = rsqrtf(var + 1e-5f);
    float* xr = x + (size_t)row * CDM;
    size_t ro = (size_t)row * CDM;
    #pragma unroll
    for (int i = 0; i < 3; i++) {
        int d = tid + i * 256;
        float val = (e[i] - mean) * inv * gam[d] + bet[d];
        xr[d] = val;
        __nv_bfloat16 h, l;
        hilo(val, h, l);
        xh[ro + d] = h; xl[ro + d] = l;
    }
}

__global__ void add_ln_kernel(float* __restrict__ x,
                              const float* __restrict__ y,
                              const float* __restrict__ gam,
                              const float* __restrict__ bet,
                              __nv_bfloat16* __restrict__ xh,
                              __nv_bfloat16* __restrict__ xl) {
    __shared__ float red[256];
    int row = blockIdx.x;
    int tid = threadIdx.x;
    float* xr = x + (size_t)row * CDM;
    const float* yr = y + (size_t)row * CDM;
    float e[3];
    float sm = 0.f;
    #pragma unroll
    for (int i = 0; i < 3; i++) { int d = tid + i * 256; e[i] = xr[d] + yr[d]; sm += e[i]; }
    float mean = block_reduce_sum256(sm, red) * (1.0f / CDM);
    float vs = 0.f;
    #pragma unroll
    for (int i = 0; i < 3; i++) { float t = e[i] - mean; vs += t * t; }
    float var = block_reduce_sum256(vs, red) * (1.0f / CDM);
    float inv = rsqrtf(var + 1e-5f);
    size_t ro = (size_t)row * CDM;
    #pragma unroll
    for (int i = 0; i < 3; i++) {
        int d = tid + i * 256;
        float val = (e[i] - mean) * inv * gam[d] + bet[d];
        xr[d] = val;
        __nv_bfloat16 h, l;
        hilo(val, h, l);
        xh[ro + d] = h; xl[ro + d] = l;
    }
}

// qg = (x[:,0] @ Wqg + bqg) * scale
__global__ void qg_kernel(const float* __restrict__ x,
                          const float* __restrict__ Wqg,
                          const float* __restrict__ bqg,
                          float* __restrict__ qg) {
    int nidx = blockIdx.x * 256 + threadIdx.x;
    int b = blockIdx.y;
    const float* xr = x + (size_t)(b * CS) * CDM;
    float acc = bqg[nidx];
    for (int kk = 0; kk < CDM; kk++)
        acc += xr[kk] * Wqg[(size_t)kk * CDM + nidx];
    qg[b * CDM + nidx] = acc * CSCALE;
}

// t[b,h,k] = sum_d Wkg[k, h*64+d] * qg[b,h,d]
__global__ void tk_kernel(const float* __restrict__ Wkg,
                          const float* __restrict__ qg,
                          float* __restrict__ t) {
    int k = blockIdx.x * 128 + threadIdx.x;
    int h = blockIdx.y, b = blockIdx.z;
    const float* W = Wkg + (size_t)k * CDM + h * 64;
    const float* q = qg + b * CDM + h * 64;
    float acc = 0.f;
    #pragma unroll
    for (int d = 0; d < 64; d++) acc += W[d] * q[d];
    t[(b * CH + h) * CDM + k] = acc;
}

// sgl[b,h,s] = x[b,s,:] . t[b,h,:]  (masked) -> p buffer (raw scores)
__global__ __launch_bounds__(256)
void sgl_kernel(const float* __restrict__ x,
                const float* __restrict__ t,
                const int* __restrict__ am,
                float* __restrict__ p) {
    __shared__ float ts[CH][CDM];     // 36 KB
    int b = blockIdx.y;
    int tid = threadIdx.x;
    for (int i = tid; i < CH * CDM; i += 256)
        ((float*)ts)[i] = t[b * CH * CDM + i];
    __syncthreads();
    int w = tid >> 5, lane = tid & 31;
    int s = blockIdx.x * 8 + w;
    const float* xr = x + ((size_t)(b * CS + s)) * CDM;
    float acc[CH];
    #pragma unroll
    for (int h = 0; h < CH; h++) acc[h] = 0.f;
    for (int k = lane; k < CDM; k += 32) {
        float xv = xr[k];
        #pragma unroll
        for (int h = 0; h < CH; h++) acc[h] += xv * ts[h][k];
    }
    #pragma unroll
    for (int h = 0; h < CH; h++) {
        #pragma unroll
        for (int o = 16; o > 0; o >>= 1)
            acc[h] += __shfl_xor_sync(0xffffffffu, acc[h], o);
    }
    bool okm = am[b * CS + s] > 0;
    if (lane < CH)
        p[((size_t)(b * CH + lane)) * CS + s] = okm ? acc[lane] : CNEG;
}

// softmax in place over s for each (b,h)
__global__ void softmax_p_kernel(float* __restrict__ p) {
    __shared__ float red[256];
    int h = blockIdx.x, b = blockIdx.y;
    int tid = threadIdx.x;
    float* pr = p + ((size_t)(b * CH + h)) * CS;
    float mx = -1e30f;
    for (int s = tid; s < CS; s += 256) mx = fmaxf(mx, pr[s]);
    red[tid] = mx; __syncthreads();
    #pragma unroll
    for (int o = 128; o > 0; o >>= 1) {
        if (tid < o) red[tid] = fmaxf(red[tid], red[tid + o]);
        __syncthreads();
    }
    mx = red[0]; __syncthreads();
    float sm = 0.f;
    for (int s = tid; s < CS; s += 256) {
        float e = __expf(pr[s] - mx);
        pr[s] = e; sm += e;
    }
    float tot = block_reduce_sum256(sm, red);
    float inv = 1.0f / tot;
    for (int s = tid; s < CS; s += 256) pr[s] *= inv;
}

// u[b,h,k] = sum_s p[b,h,s] * x[b,s,k]
__global__ __launch_bounds__(256)
void u_kernel(const float* __restrict__ p,
              const float* __restrict__ x,
              float* __restrict__ u) {
    __shared__ float xs[128][64];     // 32 KB
    __shared__ float ps[CH][128];     // 6 KB
    int kc = blockIdx.x, b = blockIdx.y;
    int k0 = kc * 64;
    int tid = threadIdx.x;
    int kl = tid & 63, h0 = tid >> 6;     // h0 in 0..3
    float acc[3] = {0.f, 0.f, 0.f};
    for (int st = 0; st < CS / 128; st++) {
        __syncthreads();
        #pragma unroll
        for (int i = 0; i < 32; i++) {
            int idx = i * 256 + tid;
            int r = idx >> 6, c = idx & 63;
            xs[r][c] = x[((size_t)(b * CS + st * 128 + r)) * CDM + k0 + c];
        }
        #pragma unroll
        for (int i = 0; i < 6; i++) {
            int idx = i * 256 + tid;
            int hh = idx >> 7, ss = idx & 127;
            ps[hh][ss] = p[((size_t)(b * CH + hh)) * CS + st * 128 + ss];
        }
        __syncthreads();
        for (int s = 0; s < 128; s++) {
            float xv = xs[s][kl];
            acc[0] += ps[h0][s] * xv;
            acc[1] += ps[h0 + 4][s] * xv;
            acc[2] += ps[h0 + 8][s] * xv;
        }
    }
    u[(b * CH + h0) * CDM + k0 + kl]       = acc[0];
    u[(b * CH + h0 + 4) * CDM + k0 + kl]   = acc[1];
    u[(b * CH + h0 + 8) * CDM + k0 + kl]   = acc[2];
}

// og[b,h,d] = u[b,h,:] . Wvg[:, h*64+d] + bvg[h*64+d] -> overwrite row 0 (hi/lo)
__global__ void og_kernel(const float* __restrict__ u,
                          const float* __restrict__ Wvg,
                          const float* __restrict__ bvg,
                          __nv_bfloat16* __restrict__ outh,
                          __nv_bfloat16* __restrict__ outl) {
    int h = blockIdx.x, b = blockIdx.y;
    int d = threadIdx.x;          // 64
    const float* up = u + (b * CH + h) * CDM;
    float acc = bvg[h * 64 + d];
    for (int k = 0; k < CDM; k++)
        acc += up[k] * Wvg[(size_t)k * CDM + h * 64 + d];
    __nv_bfloat16 hh, ll;
    hilo(acc, hh, ll);
    size_t ob = ((size_t)(b * CS)) * CDM + h * 64 + d;
    outh[ob] = hh;
    outl[ob] = ll;
}

__global__ void cls_kernel(const float* __restrict__ x,
                           const float* __restrict__ Wc,
                           const float* __restrict__ bc,
                           float* __restrict__ out) {
    __shared__ float red[256];
    int b = blockIdx.x >> 1, c = blockIdx.x & 1;
    int tid = threadIdx.x;
    const float* xr = x + (size_t)(b * CS) * CDM;
    float acc = 0.f;
    for (int d = tid; d < CDM; d += 256) acc += xr[d] * Wc[d * 2 + c];
    float tot = block_reduce_sum256(acc, red);
    if (tid == 0) out[b * 2 + c] = tot + bc[c];
}

// ================= launch =================
extern "C" void kernel_launch(void* const* d_in, const int* in_sizes, int n_in,
                              void* d_out, int out_size) {
    const int*   ids  = (const int*)d_in[0];
    const int*   am   = (const int*)d_in[1];
    const float* we   = (const float*)d_in[2];
    const float* pe   = (const float*)d_in[3];
    const float* lnes = (const float*)d_in[4];
    const float* lneb = (const float*)d_in[5];
    const float* Wq   = (const float*)d_in[6];
    const float* bq   = (const float*)d_in[7];
    const float* Wk   = (const float*)d_in[8];
    const float* bk   = (const float*)d_in[9];
    const float* Wv   = (const float*)d_in[10];
    const float* bv   = (const float*)d_in[11];
    const float* Wqg  = (const float*)d_in[12];
    const float* bqg  = (const float*)d_in[13];
    const float* Wkg  = (const float*)d_in[14];
    const float* bkg  = (const float*)d_in[15];
    const float* Wvg  = (const float*)d_in[16];
    const float* bvg  = (const float*)d_in[17];
    const float* Wo   = (const float*)d_in[18];
    const float* bo   = (const float*)d_in[19];
    const float* ln1s = (const float*)d_in[20];
    const float* ln1b = (const float*)d_in[21];
    const float* W1   = (const float*)d_in[22];
    const float* b1   = (const float*)d_in[23];
    const float* W2   = (const float*)d_in[24];
    const float* b2   = (const float*)d_in[25];
    const float* ln2s = (const float*)d_in[26];
    const float* ln2b = (const float*)d_in[27];
    const float* Wcls = (const float*)d_in[28];
    const float* bcls = (const float*)d_in[29];
    float* out = (float*)d_out;

    float *xp, *yp, *qkvp, *qgp, *biasp, *tp, *pp, *up;
    __nv_bfloat16 *xhp, *xlp, *ahp, *alp, *hhp, *hlp, *whp, *wlp;
    cudaGetSymbolAddress((void**)&xp,   g_x);
    cudaGetSymbolAddress((void**)&yp,   g_y);
    cudaGetSymbolAddress((void**)&qkvp, g_qkv);
    cudaGetSymbolAddress((void**)&qgp,  g_qg);
    cudaGetSymbolAddress((void**)&biasp, g_bias);
    cudaGetSymbolAddress((void**)&tp,   g_t);
    cudaGetSymbolAddress((void**)&pp,   g_p);
    cudaGetSymbolAddress((void**)&up,   g_u);
    cudaGetSymbolAddress((void**)&xhp,  g_xbh);
    cudaGetSymbolAddress((void**)&xlp,  g_xbl);
    cudaGetSymbolAddress((void**)&ahp,  g_abh);
    cudaGetSymbolAddress((void**)&alp,  g_abl);
    cudaGetSymbolAddress((void**)&hhp,  g_hbh);
    cudaGetSymbolAddress((void**)&hlp,  g_hbl);
    cudaGetSymbolAddress((void**)&whp,  g_wbh);
    cudaGetSymbolAddress((void**)&wlp,  g_wbl);

    cudaFuncSetAttribute(gemm_mma_kernel, cudaFuncAttributeMaxDynamicSharedMemorySize, GSM_TOT);
    cudaFuncSetAttribute(flash_band_kernel, cudaFuncAttributeMaxDynamicSharedMemorySize, FB_TOT);

    embed_ln_kernel<<<MROWS, 256>>>(ids, we, pe, lnes, lneb, xp, xhp, xlp);

    dim3 wt_dm(CDM / 32, CDM / 32);
    dim3 wt_b(32, 8);
    size_t wseg = (size_t)CDM * CDM;

    for (int l = 0; l < CL; l++) {
        size_t woff = (size_t)l * CDM * CDM;
        size_t boff = (size_t)l * CDM;
        size_t w1off = (size_t)l * CDM * CDFF;
        size_t b1off = (size_t)l * CDFF;
        size_t w2off = (size_t)l * CDFF * CDM;

        // --- fused QKV GEMM ---
        split_wt_kernel<<<wt_dm, wt_b>>>(Wq + woff, whp,            wlp,            CDM, CDM);
        split_wt_kernel<<<wt_dm, wt_b>>>(Wk + woff, whp + wseg,     wlp + wseg,     CDM, CDM);
        split_wt_kernel<<<wt_dm, wt_b>>>(Wv + woff, whp + 2 * wseg, wlp + 2 * wseg, CDM, CDM);
        pack_bias_kernel<<<9, 256>>>(biasp, bq + boff, bk + boff, bv + boff);
        gemm_mma_kernel<<<dim3(QKV_S / 128, MROWS / 128), 256, GSM_TOT>>>(
            xhp, xlp, whp, wlp, biasp, qkvp, nullptr, nullptr, CDM, QKV_S, 0);

        flash_band_kernel<<<dim3(4, CB * CH * CNB), 128, FB_TOT>>>(qkvp, am, ahp, alp);

        // --- factored global attention (fp32, no GEMM) ---
        qg_kernel<<<dim3(CDM / 256, CB), 256>>>(xp, Wqg + woff, bqg + boff, qgp);
        tk_kernel<<<dim3(CDM / 128, CH, CB), 128>>>(Wkg + woff, qgp, tp);
        sgl_kernel<<<dim3(CS / 8, CB), 256>>>(xp, tp, am, pp);
        softmax_p_kernel<<<dim3(CH, CB), 256>>>(pp);
        u_kernel<<<dim3(CDM / 64, CB), 256>>>(pp, xp, up);
        og_kernel<<<dim3(CH, CB), 64>>>(up, Wvg + woff, bvg + boff, ahp, alp);

        // --- Wo projection + LN1 ---
        split_wt_kernel<<<wt_dm, wt_b>>>(Wo + woff, whp, wlp, CDM, CDM);
        gemm_mma_kernel<<<dim3(CDM / 128, MROWS / 128), 256, GSM_TOT>>>(
            ahp, alp, whp, wlp, bo + boff, yp, nullptr, nullptr, CDM, CDM, 0);
        add_ln_kernel<<<MROWS, 256>>>(xp, yp, ln1s + boff, ln1b + boff, xhp, xlp);

        // --- FFN ---
        split_wt_kernel<<<dim3(CDFF / 32, CDM / 32), wt_b>>>(W1 + w1off, whp, wlp, CDM, CDFF);
        gemm_mma_kernel<<<dim3(CDFF / 128, MROWS / 128), 256, GSM_TOT>>>(
            xhp, xlp, whp, wlp, b1 + b1off, nullptr, hhp, hlp, CDM, CDFF, 2);

        split_wt_kernel<<<dim3(CDM / 32, CDFF / 32), wt_b>>>(W2 + w2off, whp, wlp, CDFF, CDM);
        gemm_mma_kernel<<<dim3(CDM / 128, MROWS / 128), 256, GSM_TOT>>>(
            hhp, hlp, whp, wlp, b2 + boff, yp, nullptr, nullptr, CDFF, CDM, 0);
        add_ln_kernel<<<MROWS, 256>>>(xp, yp, ln2s + boff, ln2b + boff, xhp, xlp);
    }

    cls_kernel<<<4, 256>>>(xp, Wcls, bcls, out);
}

// round 12
// speedup vs baseline: 1.7188x; 1.1132x over previous
#include <cuda_runtime.h>
#include <cuda_fp16.h>
#include <math.h>
#include <stdint.h>

// ---------------- problem constants ----------------
#define CB   2
#define CS   4096
#define CH   12
#define CD   64
#define CW   256
#define CDM  768
#define CDFF 3072
#define CNB  16
#define CL   2
#define CNEG (-1000000000.0f)
#define CSCALE 0.125f

#define MROWS (CB*CS)    // 8192
#define QKV_S 2304

// ---------------- scratch ----------------
__device__ float g_x   [MROWS*CDM];
__device__ float g_y   [MROWS*CDM];
__device__ float g_qkv [(size_t)MROWS*QKV_S];
__device__ float g_qg  [CB*CDM];
__device__ float g_bias[QKV_S];
__device__ float g_t   [CB*CH*CDM];
__device__ float g_p   [(size_t)CB*CH*CS];
__device__ float g_u   [CB*CH*CDM];
// hi/lo fp16 operand buffers
__device__ __half g_xbh[(size_t)MROWS*CDM];
__device__ __half g_xbl[(size_t)MROWS*CDM];
__device__ __half g_abh[(size_t)MROWS*CDM];
__device__ __half g_abl[(size_t)MROWS*CDM];
__device__ __half g_hbh[(size_t)MROWS*CDFF];
__device__ __half g_hbl[(size_t)MROWS*CDFF];
__device__ __half g_wbh[(size_t)CDFF*CDM];
__device__ __half g_wbl[(size_t)CDFF*CDM];

// ---------------- helpers ----------------
__device__ __forceinline__ float gelu_tanh(float x) {
    float x3 = x * x * x;
    return 0.5f * x * (1.0f + tanhf(0.7978845608028654f * (x + 0.044715f * x3)));
}
__device__ __forceinline__ uint32_t smem_u32(const void* p) {
    uint32_t a;
    asm("{ .reg .u64 t; cvta.to.shared.u64 t, %1; cvt.u32.u64 %0, t; }" : "=r"(a) : "l"(p));
    return a;
}
__device__ __forceinline__ void hilo(float v, __half& h, __half& l) {
    h = __float2half_rn(v);
    l = __float2half_rn(v - __half2float(h));
}
__device__ __forceinline__ void hilo2(float a, float b, uint32_t& h, uint32_t& l) {
    __half ha, la, hb, lb;
    hilo(a, ha, la);
    hilo(b, hb, lb);
    __half2 hh = __halves2half2(ha, hb);
    __half2 ll = __halves2half2(la, lb);
    h = *(uint32_t*)&hh;
    l = *(uint32_t*)&ll;
}

// ================= split/convert kernels =================
__global__ void split_wt_kernel(const float* __restrict__ W,
                                __half* __restrict__ Wth,
                                __half* __restrict__ Wtl, int K, int N) {
    __shared__ float t[32][33];
    int n0 = blockIdx.x * 32, k0 = blockIdx.y * 32;
    int tx = threadIdx.x, ty = threadIdx.y;
    #pragma unroll
    for (int r = 0; r < 4; r++) {
        int k = k0 + ty + r * 8;
        t[ty + r * 8][tx] = W[(size_t)k * N + n0 + tx];
    }
    __syncthreads();
    #pragma unroll
    for (int r = 0; r < 4; r++) {
        int n = n0 + ty + r * 8;
        int k = k0 + tx;
        __half h, l;
        hilo(t[tx][ty + r * 8], h, l);
        size_t ro = (size_t)n * K + k;
        Wth[ro] = h;
        Wtl[ro] = l;
    }
}

__global__ void pack_bias_kernel(float* __restrict__ dst,
                                 const float* __restrict__ s0,
                                 const float* __restrict__ s1,
                                 const float* __restrict__ s2) {
    int i = blockIdx.x * 256 + threadIdx.x;
    int s = i / 768, r = i - s * 768;
    const float* p = (s == 0) ? s0 : (s == 1 ? s1 : s2);
    dst[i] = p[r];
}

// ================= warp-MMA fp16 GEMM (hi/lo fragment reuse) =================
#define MAT_B 10240
#define STG_BYTES (4*MAT_B)
#define GSM_TOT (2*STG_BYTES)   // 81920

__device__ __forceinline__ void ldm_x4(uint32_t addr, uint32_t& r0, uint32_t& r1,
                                       uint32_t& r2, uint32_t& r3) {
    asm volatile("ldmatrix.sync.aligned.m8n8.x4.shared.b16 {%0,%1,%2,%3}, [%4];"
        : "=r"(r0), "=r"(r1), "=r"(r2), "=r"(r3) : "r"(addr));
}
__device__ __forceinline__ void ldm_x4t(uint32_t addr, uint32_t& r0, uint32_t& r1,
                                        uint32_t& r2, uint32_t& r3) {
    asm volatile("ldmatrix.sync.aligned.m8n8.x4.trans.shared.b16 {%0,%1,%2,%3}, [%4];"
        : "=r"(r0), "=r"(r1), "=r"(r2), "=r"(r3) : "r"(addr));
}
__device__ __forceinline__ void mma_f16(float* c, const uint32_t* a, const uint32_t* b) {
    asm volatile("mma.sync.aligned.m16n8k16.row.col.f32.f16.f16.f32 "
        "{%0,%1,%2,%3}, {%4,%5,%6,%7}, {%8,%9}, {%0,%1,%2,%3};"
        : "+f"(c[0]), "+f"(c[1]), "+f"(c[2]), "+f"(c[3])
        : "r"(a[0]), "r"(a[1]), "r"(a[2]), "r"(a[3]), "r"(b[0]), "r"(b[1]));
}

// mode 0: Cf = acc+bias ; mode 1: +GELU ; mode 2: hi/lo fp16(gelu) -> Cbh/Cbl
// terms: 3 = full (ah*bh + al*bh + ah*bl), 2 = drop ah*bl
__global__ __launch_bounds__(256, 2)
void gemm_mma_kernel(const __half* __restrict__ Ah,
                     const __half* __restrict__ Al,
                     const __half* __restrict__ Bh,
                     const __half* __restrict__ Bl,
                     const float* __restrict__ bias,
                     float* __restrict__ Cf,
                     __half* __restrict__ Cbh,
                     __half* __restrict__ Cbl,
                     int Kp, int N, int mode, int terms) {
    extern __shared__ __align__(1024) char smem[];
    uint32_t sb = smem_u32(smem);
    int tid = threadIdx.x;
    int wid = tid >> 5, lane = tid & 31;
    int m0 = blockIdx.y * 128, n0 = blockIdx.x * 128;
    int warp_m = (wid & 1) * 64;
    int warp_n = (wid >> 1) * 32;
    int NC = Kp / 32;

    const __half* Agh = Ah + (size_t)m0 * Kp;
    const __half* Agl = Al + (size_t)m0 * Kp;
    const __half* Bgh = Bh + (size_t)n0 * Kp;
    const __half* Bgl = Bl + (size_t)n0 * Kp;

    float acc[4][4][4];
    #pragma unroll
    for (int i = 0; i < 4; i++)
        #pragma unroll
        for (int j = 0; j < 4; j++)
            #pragma unroll
            for (int r = 0; r < 4; r++) acc[i][j][r] = 0.f;

    auto load_tile = [&](int c, int bf) {
        uint32_t base = sb + bf * STG_BYTES;
        const __half* srcs[4] = {
            Agh + (size_t)c * 32, Agl + (size_t)c * 32,
            Bgh + (size_t)c * 32, Bgl + (size_t)c * 32 };
        #pragma unroll
        for (int m = 0; m < 4; m++) {
            const __half* S = srcs[m];
            uint32_t mb = base + m * MAT_B;
            #pragma unroll
            for (int i = 0; i < 2; i++) {
                int ch = i * 256 + tid;
                int r = ch >> 2, c8 = (ch & 3) * 8;
                uint32_t d = mb + r * 80 + c8 * 2;
                const void* s = S + (size_t)r * Kp + c8;
                asm volatile("cp.async.cg.shared.global [%0], [%1], 16;" :: "r"(d), "l"(s));
            }
        }
    };

    load_tile(0, 0);
    asm volatile("cp.async.commit_group;" ::: "memory");

    int rsel = lane & 15, hsel = (lane >> 4) * 16;
    for (int c = 0; c < NC; c++) {
        int bf = c & 1;
        if (c + 1 < NC) load_tile(c + 1, bf ^ 1);
        asm volatile("cp.async.commit_group;" ::: "memory");
        asm volatile("cp.async.wait_group 1;" ::: "memory");
        __syncthreads();

        uint32_t ahb = sb + bf * STG_BYTES;
        uint32_t alb = ahb + MAT_B;
        uint32_t bhb = ahb + 2 * MAT_B;
        uint32_t blb = ahb + 3 * MAT_B;

        #pragma unroll
        for (int ks = 0; ks < 2; ks++) {
            uint32_t ah[4][4], al[4][4], bh[4][2], bl[4][2];
            #pragma unroll
            for (int mi = 0; mi < 4; mi++) {
                uint32_t off = (warp_m + mi * 16 + rsel) * 80 + ks * 32 + hsel;
                ldm_x4(ahb + off, ah[mi][0], ah[mi][1], ah[mi][2], ah[mi][3]);
                ldm_x4(alb + off, al[mi][0], al[mi][1], al[mi][2], al[mi][3]);
            }
            #pragma unroll
            for (int np = 0; np < 2; np++) {
                uint32_t off = (warp_n + np * 16 + rsel) * 80 + ks * 32 + hsel;
                uint32_t r0, r1, r2, r3;
                ldm_x4(bhb + off, r0, r1, r2, r3);
                bh[np * 2 + 0][0] = r0; bh[np * 2 + 0][1] = r2;
                bh[np * 2 + 1][0] = r1; bh[np * 2 + 1][1] = r3;
                ldm_x4(blb + off, r0, r1, r2, r3);
                bl[np * 2 + 0][0] = r0; bl[np * 2 + 0][1] = r2;
                bl[np * 2 + 1][0] = r1; bl[np * 2 + 1][1] = r3;
            }
            #pragma unroll
            for (int mi = 0; mi < 4; mi++)
                #pragma unroll
                for (int nj = 0; nj < 4; nj++)
                    mma_f16(acc[mi][nj], ah[mi], bh[nj]);
            #pragma unroll
            for (int mi = 0; mi < 4; mi++)
                #pragma unroll
                for (int nj = 0; nj < 4; nj++)
                    mma_f16(acc[mi][nj], al[mi], bh[nj]);
            if (terms == 3) {
                #pragma unroll
                for (int mi = 0; mi < 4; mi++)
                    #pragma unroll
                    for (int nj = 0; nj < 4; nj++)
                        mma_f16(acc[mi][nj], ah[mi], bl[nj]);
            }
        }
        __syncthreads();
    }

    int g = lane >> 2, t = lane & 3;
    #pragma unroll
    for (int mi = 0; mi < 4; mi++) {
        int row0 = m0 + warp_m + mi * 16 + g;
        #pragma unroll
        for (int nj = 0; nj < 4; nj++) {
            int col = n0 + warp_n + nj * 8 + t * 2;
            float bx = bias[col], by = bias[col + 1];
            float v0 = acc[mi][nj][0] + bx, v1 = acc[mi][nj][1] + by;
            float v2 = acc[mi][nj][2] + bx, v3 = acc[mi][nj][3] + by;
            if (mode >= 1) { v0 = gelu_tanh(v0); v1 = gelu_tanh(v1); v2 = gelu_tanh(v2); v3 = gelu_tanh(v3); }
            if (mode == 2) {
                #pragma unroll
                for (int rr = 0; rr < 2; rr++) {
                    int row = row0 + rr * 8;
                    float a0 = rr ? v2 : v0, a1 = rr ? v3 : v1;
                    uint32_t h2, l2;
                    hilo2(a0, a1, h2, l2);
                    size_t ro = (size_t)row * N + col;
                    *(uint32_t*)&Cbh[ro] = h2;
                    *(uint32_t*)&Cbl[ro] = l2;
                }
            } else {
                *(float2*)&Cf[(size_t)row0 * N + col]       = make_float2(v0, v1);
                *(float2*)&Cf[(size_t)(row0 + 8) * N + col] = make_float2(v2, v3);
            }
        }
    }
}

// ================= fused flash band attention (tensor-core fp16 hi/lo) =====
#define FB_ROWB 144
#define FB_QH 0
#define FB_QL (FB_QH + 64*FB_ROWB)
#define FB_KH (FB_QL + 64*FB_ROWB)
#define FB_KL (FB_KH + 64*FB_ROWB)
#define FB_VH (FB_KL + 64*FB_ROWB)
#define FB_VL (FB_VH + 64*FB_ROWB)
#define FB_SG (FB_VL + 64*FB_ROWB)
#define FB_V0 (FB_SG + 256)
#define FB_CM (FB_V0 + 256)
#define FB_TOT (FB_CM + 256 + 64)

__global__ __launch_bounds__(128)
void flash_band_kernel(const float* __restrict__ qkv,
                       const int* __restrict__ am,
                       __half* __restrict__ outh,
                       __half* __restrict__ outl) {
    extern __shared__ char fsmc[];
    float* fp = (float*)fsmc;
    uint32_t sb = smem_u32(fsmc);
    int z = blockIdx.y;
    int n = z % CNB;
    int h = (z / CNB) % CH;
    int b = z / (CNB * CH);
    int qt = blockIdx.x;
    int tid = threadIdx.x;
    int w = tid >> 5, lane = tid & 31;
    int rsel = lane & 15, hsel = (lane >> 4) * 16;
    int t2 = (lane & 3) * 2;

    int base_s    = n * CW + qt * 64;
    int base_kpos = n * CW - CW;
    int am0 = am[b * CS];

    #pragma unroll
    for (int i = 0; i < 8; i++) {
        int sid = i * 128 + tid;
        int r = sid >> 4, c4 = (sid & 15) * 4;
        float4 vq = *(const float4*)&qkv[((size_t)(b * CS + base_s + r)) * QKV_S + h * 64 + c4];
        vq.x *= CSCALE; vq.y *= CSCALE; vq.z *= CSCALE; vq.w *= CSCALE;
        uint32_t h0, l0, h1, l1;
        hilo2(vq.x, vq.y, h0, l0);
        hilo2(vq.z, vq.w, h1, l1);
        *(uint2*)(fsmc + FB_QH + r * FB_ROWB + c4 * 2) = make_uint2(h0, h1);
        *(uint2*)(fsmc + FB_QL + r * FB_ROWB + c4 * 2) = make_uint2(l0, l1);
    }
    if (tid < 64)
        fp[FB_V0 / 4 + tid] = qkv[((size_t)(b * CS)) * QKV_S + 1536 + h * 64 + tid];
    __syncthreads();

    {
        int row = tid >> 1, half = tid & 1;
        const __half* qh = (const __half*)(fsmc + FB_QH + row * FB_ROWB);
        const __half* ql = (const __half*)(fsmc + FB_QL + row * FB_ROWB);
        const float* k0p = &qkv[((size_t)(b * CS)) * QKV_S + 768 + h * 64];
        float sgv = 0.f;
        #pragma unroll
        for (int d = 0; d < 32; d++) {
            int dd = half * 32 + d;
            sgv += (__half2float(qh[dd]) + __half2float(ql[dd])) * k0p[dd];
        }
        sgv += __shfl_xor_sync(0xffffffffu, sgv, 1);
        if (half == 0) fp[FB_SG / 4 + row] = sgv;
    }

    uint32_t qh[4][4], ql[4][4];
    #pragma unroll
    for (int dk = 0; dk < 4; dk++) {
        uint32_t off = (16 * w + rsel) * FB_ROWB + dk * 32 + hsel;
        ldm_x4(sb + FB_QH + off, qh[dk][0], qh[dk][1], qh[dk][2], qh[dk][3]);
        ldm_x4(sb + FB_QL + off, ql[dk][0], ql[dk][1], ql[dk][2], ql[dk][3]);
    }

    float o[8][4];
    #pragma unroll
    for (int nn = 0; nn < 8; nn++)
        #pragma unroll
        for (int e = 0; e < 4; e++) o[nn][e] = 0.f;
    float mst0 = -1e30f, mst1 = -1e30f, lst0 = 0.f, lst1 = 0.f;

    int qi0 = qt * 64 + 16 * w + (lane >> 2);
    int qi1 = qi0 + 8;

    for (int kc = 0; kc < 12; kc++) {
        __syncthreads();
        #pragma unroll
        for (int i = 0; i < 8; i++) {
            int sid = i * 128 + tid;
            int r = sid >> 4, c4 = (sid & 15) * 4;
            int kpos = base_kpos + kc * 64 + r;
            float4 vk = make_float4(0.f, 0.f, 0.f, 0.f);
            float4 vv = make_float4(0.f, 0.f, 0.f, 0.f);
            if (kpos >= 0 && kpos < CS) {
                size_t rb = ((size_t)(b * CS + kpos)) * QKV_S + h * 64 + c4;
                vk = *(const float4*)&qkv[rb + 768];
                vv = *(const float4*)&qkv[rb + 1536];
            }
            uint32_t h0, l0, h1, l1;
            hilo2(vk.x, vk.y, h0, l0);
            hilo2(vk.z, vk.w, h1, l1);
            *(uint2*)(fsmc + FB_KH + r * FB_ROWB + c4 * 2) = make_uint2(h0, h1);
            *(uint2*)(fsmc + FB_KL + r * FB_ROWB + c4 * 2) = make_uint2(l0, l1);
            hilo2(vv.x, vv.y, h0, l0);
            hilo2(vv.z, vv.w, h1, l1);
            *(uint2*)(fsmc + FB_VH + r * FB_ROWB + c4 * 2) = make_uint2(h0, h1);
            *(uint2*)(fsmc + FB_VL + r * FB_ROWB + c4 * 2) = make_uint2(l0, l1);
        }
        if (tid < 64) {
            int kpos = base_kpos + kc * 64 + tid;
            bool ok = (kpos >= 0) && (kpos < CS) && (kpos != 0);
            if (ok) ok = am[b * CS + kpos] > 0;
            fp[FB_CM / 4 + tid] = ok ? 1.f : 0.f;
        }
        __syncthreads();

        float s[8][4];
        #pragma unroll
        for (int nn = 0; nn < 8; nn++)
            #pragma unroll
            for (int e = 0; e < 4; e++) s[nn][e] = 0.f;
        #pragma unroll
        for (int dk = 0; dk < 4; dk++) {
            #pragma unroll
            for (int np = 0; np < 4; np++) {
                uint32_t off = (np * 16 + rsel) * FB_ROWB + dk * 32 + hsel;
                uint32_t r0, r1, r2, r3;
                uint32_t kha[2], khb[2], kla[2], klb[2];
                ldm_x4(sb + FB_KH + off, r0, r1, r2, r3);
                kha[0] = r0; kha[1] = r2; khb[0] = r1; khb[1] = r3;
                ldm_x4(sb + FB_KL + off, r0, r1, r2, r3);
                kla[0] = r0; kla[1] = r2; klb[0] = r1; klb[1] = r3;
                mma_f16(s[2 * np],     qh[dk], kha);
                mma_f16(s[2 * np + 1], qh[dk], khb);
                mma_f16(s[2 * np],     ql[dk], kha);
                mma_f16(s[2 * np + 1], ql[dk], khb);
                mma_f16(s[2 * np],     qh[dk], kla);
                mma_f16(s[2 * np + 1], qh[dk], klb);
            }
        }

        #pragma unroll
        for (int nn = 0; nn < 8; nn++) {
            #pragma unroll
            for (int e = 0; e < 2; e++) {
                int kj = kc * 64 + 8 * nn + t2 + e;
                float cm = fp[FB_CM / 4 + 8 * nn + t2 + e];
                bool b0 = (kj >= qi0) && (kj <= qi0 + 2 * CW) && (cm > 0.f);
                bool b1 = (kj >= qi1) && (kj <= qi1 + 2 * CW) && (cm > 0.f);
                if (!b0) s[nn][e] = CNEG;
                if (!b1) s[nn][2 + e] = CNEG;
            }
        }

        float mx0 = -1e30f, mx1 = -1e30f;
        #pragma unroll
        for (int nn = 0; nn < 8; nn++) {
            mx0 = fmaxf(mx0, fmaxf(s[nn][0], s[nn][1]));
            mx1 = fmaxf(mx1, fmaxf(s[nn][2], s[nn][3]));
        }
        mx0 = fmaxf(mx0, __shfl_xor_sync(0xffffffffu, mx0, 1));
        mx0 = fmaxf(mx0, __shfl_xor_sync(0xffffffffu, mx0, 2));
        mx1 = fmaxf(mx1, __shfl_xor_sync(0xffffffffu, mx1, 1));
        mx1 = fmaxf(mx1, __shfl_xor_sync(0xffffffffu, mx1, 2));
        float nm0 = fmaxf(mst0, mx0), nm1 = fmaxf(mst1, mx1);
        float a0 = __expf(mst0 - nm0), a1 = __expf(mst1 - nm1);
        mst0 = nm0; mst1 = nm1;
        float rs0 = 0.f, rs1 = 0.f;
        #pragma unroll
        for (int nn = 0; nn < 8; nn++) {
            s[nn][0] = __expf(s[nn][0] - nm0); rs0 += s[nn][0];
            s[nn][1] = __expf(s[nn][1] - nm0); rs0 += s[nn][1];
            s[nn][2] = __expf(s[nn][2] - nm1); rs1 += s[nn][2];
            s[nn][3] = __expf(s[nn][3] - nm1); rs1 += s[nn][3];
        }
        rs0 += __shfl_xor_sync(0xffffffffu, rs0, 1);
        rs0 += __shfl_xor_sync(0xffffffffu, rs0, 2);
        rs1 += __shfl_xor_sync(0xffffffffu, rs1, 1);
        rs1 += __shfl_xor_sync(0xffffffffu, rs1, 2);
        lst0 = lst0 * a0 + rs0;
        lst1 = lst1 * a1 + rs1;
        #pragma unroll
        for (int nn = 0; nn < 8; nn++) {
            o[nn][0] *= a0; o[nn][1] *= a0;
            o[nn][2] *= a1; o[nn][3] *= a1;
        }

        uint32_t ph[4][4], pl[4][4];
        #pragma unroll
        for (int qf = 0; qf < 4; qf++) {
            hilo2(s[2 * qf][0],     s[2 * qf][1],     ph[qf][0], pl[qf][0]);
            hilo2(s[2 * qf][2],     s[2 * qf][3],     ph[qf][1], pl[qf][1]);
            hilo2(s[2 * qf + 1][0], s[2 * qf + 1][1], ph[qf][2], pl[qf][2]);
            hilo2(s[2 * qf + 1][2], s[2 * qf + 1][3], ph[qf][3], pl[qf][3]);
        }

        #pragma unroll
        for (int qf = 0; qf < 4; qf++) {
            #pragma unroll
            for (int dp = 0; dp < 4; dp++) {
                uint32_t off = (qf * 16 + rsel) * FB_ROWB + dp * 32 + hsel;
                uint32_t r0, r1, r2, r3;
                uint32_t vha[2], vhb[2], vla[2], vlb[2];
                ldm_x4t(sb + FB_VH + off, r0, r1, r2, r3);
                vha[0] = r0; vha[1] = r1; vhb[0] = r2; vhb[1] = r3;
                ldm_x4t(sb + FB_VL + off, r0, r1, r2, r3);
                vla[0] = r0; vla[1] = r1; vlb[0] = r2; vlb[1] = r3;
                mma_f16(o[2 * dp],     ph[qf], vha);
                mma_f16(o[2 * dp + 1], ph[qf], vhb);
                mma_f16(o[2 * dp],     pl[qf], vha);
                mma_f16(o[2 * dp + 1], pl[qf], vhb);
                mma_f16(o[2 * dp],     ph[qf], vla);
                mma_f16(o[2 * dp + 1], ph[qf], vlb);
            }
        }
    }

    #pragma unroll
    for (int rr = 0; rr < 2; rr++) {
        int row = 16 * w + (lane >> 2) + 8 * rr;
        float mst = rr ? mst1 : mst0;
        float lst = rr ? lst1 : lst0;
        float sg = fp[FB_SG / 4 + row];
        if (am0 <= 0) sg = CNEG;
        float nm = fmaxf(mst, sg);
        float alpha = __expf(mst - nm);
        float pg = __expf(sg - nm);
        float l = lst * alpha + pg;
        float inv = 1.0f / l;
        int srow = base_s + row;
        size_t ob = ((size_t)(b * CS + srow)) * CDM + h * 64;
        #pragma unroll
        for (int nn = 0; nn < 8; nn++) {
            int d = 8 * nn + t2;
            float v0 = (o[nn][2 * rr + 0] * alpha + pg * fp[FB_V0 / 4 + d])     * inv;
            float v1 = (o[nn][2 * rr + 1] * alpha + pg * fp[FB_V0 / 4 + d + 1]) * inv;
            uint32_t h2, l2;
            hilo2(v0, v1, h2, l2);
            *(uint32_t*)&outh[ob + d] = h2;
            *(uint32_t*)&outl[ob + d] = l2;
        }
    }
}

// ================= small kernels =================
__device__ __forceinline__ float block_reduce_sum256(float v, float* red) {
    int tid = threadIdx.x;
    red[tid] = v; __syncthreads();
    #pragma unroll
    for (int o = 128; o > 0; o >>= 1) {
        if (tid < o) red[tid] += red[tid + o];
        __syncthreads();
    }
    float r = red[0]; __syncthreads();
    return r;
}

__global__ void embed_ln_kernel(const int* __restrict__ ids,
                                const float* __restrict__ we,
                                const float* __restrict__ pe,
                                const float* __restrict__ gam,
                                const float* __restrict__ bet,
                                float* __restrict__ x,
                                __half* __restrict__ xh,
                                __half* __restrict__ xl) {
    __shared__ float red[256];
    int row = blockIdx.x;
    int s = row % CS;
    int id = ids[row];
    int tid = threadIdx.x;
    const float* wp = we + (size_t)id * CDM;
    const float* pp = pe + (size_t)s * CDM;
    float e[3];
    float sm = 0.f;
    #pragma unroll
    for (int i = 0; i < 3; i++) { int d = tid + i * 256; e[i] = wp[d] + pp[d]; sm += e[i]; }
    float mean = block_reduce_sum256(sm, red) * (1.0f / CDM);
    float vs = 0.f;
    #pragma unroll
    for (int i = 0; i < 3; i++) { float t = e[i] - mean; vs += t * t; }
    float var = block_reduce_sum256(vs, red) * (1.0f / CDM);
    float inv = rsqrtf(var + 1e-5f);
    float* xr = x + (size_t)row * CDM;
    size_t ro = (size_t)row * CDM;
    #pragma unroll
    for (int i = 0; i < 3; i++) {
        int d = tid + i * 256;
        float val = (e[i] - mean) * inv * gam[d] + bet[d];
        xr[d] = val;
        __half h, l;
        hilo(val, h, l);
        xh[ro + d] = h; xl[ro + d] = l;
    }
}

__global__ void add_ln_kernel(float* __restrict__ x,
                              const float* __restrict__ y,
                              const float* __restrict__ gam,
                              const float* __restrict__ bet,
                              __half* __restrict__ xh,
                              __half* __restrict__ xl) {
    __shared__ float red[256];
    int row = blockIdx.x;
    int tid = threadIdx.x;
    float* xr = x + (size_t)row * CDM;
    const float* yr = y + (size_t)row * CDM;
    float e[3];
    float sm = 0.f;
    #pragma unroll
    for (int i = 0; i < 3; i++) { int d = tid + i * 256; e[i] = xr[d] + yr[d]; sm += e[i]; }
    float mean = block_reduce_sum256(sm, red) * (1.0f / CDM);
    float vs = 0.f;
    #pragma unroll
    for (int i = 0; i < 3; i++) { float t = e[i] - mean; vs += t * t; }
    float var = block_reduce_sum256(vs, red) * (1.0f / CDM);
    float inv = rsqrtf(var + 1e-5f);
    size_t ro = (size_t)row * CDM;
    #pragma unroll
    for (int i = 0; i < 3; i++) {
        int d = tid + i * 256;
        float val = (e[i] - mean) * inv * gam[d] + bet[d];
        xr[d] = val;
        __half h, l;
        hilo(val, h, l);
        xh[ro + d] = h; xl[ro + d] = l;
    }
}

__global__ void qg_kernel(const float* __restrict__ x,
                          const float* __restrict__ Wqg,
                          const float* __restrict__ bqg,
                          float* __restrict__ qg) {
    int nidx = blockIdx.x * 256 + threadIdx.x;
    int b = blockIdx.y;
    const float* xr = x + (size_t)(b * CS) * CDM;
    float acc = bqg[nidx];
    for (int kk = 0; kk < CDM; kk++)
        acc += xr[kk] * Wqg[(size_t)kk * CDM + nidx];
    qg[b * CDM + nidx] = acc * CSCALE;
}

__global__ void tk_kernel(const float* __restrict__ Wkg,
                          const float* __restrict__ qg,
                          float* __restrict__ t) {
    int k = blockIdx.x * 128 + threadIdx.x;
    int h = blockIdx.y, b = blockIdx.z;
    const float* W = Wkg + (size_t)k * CDM + h * 64;
    const float* q = qg + b * CDM + h * 64;
    float acc = 0.f;
    #pragma unroll
    for (int d = 0; d < 64; d++) acc += W[d] * q[d];
    t[(b * CH + h) * CDM + k] = acc;
}

__global__ __launch_bounds__(256)
void sgl_kernel(const float* __restrict__ x,
                const float* __restrict__ t,
                const int* __restrict__ am,
                float* __restrict__ p) {
    __shared__ float ts[CH][CDM];
    int b = blockIdx.y;
    int tid = threadIdx.x;
    for (int i = tid; i < CH * CDM; i += 256)
        ((float*)ts)[i] = t[b * CH * CDM + i];
    __syncthreads();
    int w = tid >> 5, lane = tid & 31;
    int s = blockIdx.x * 8 + w;
    const float* xr = x + ((size_t)(b * CS + s)) * CDM;
    float acc[CH];
    #pragma unroll
    for (int h = 0; h < CH; h++) acc[h] = 0.f;
    for (int k = lane; k < CDM; k += 32) {
        float xv = xr[k];
        #pragma unroll
        for (int h = 0; h < CH; h++) acc[h] += xv * ts[h][k];
    }
    #pragma unroll
    for (int h = 0; h < CH; h++) {
        #pragma unroll
        for (int o = 16; o > 0; o >>= 1)
            acc[h] += __shfl_xor_sync(0xffffffffu, acc[h], o);
    }
    bool okm = am[b * CS + s] > 0;
    if (lane < CH)
        p[((size_t)(b * CH + lane)) * CS + s] = okm ? acc[lane] : CNEG;
}

__global__ void softmax_p_kernel(float* __restrict__ p) {
    __shared__ float red[256];
    int h = blockIdx.x, b = blockIdx.y;
    int tid = threadIdx.x;
    float* pr = p + ((size_t)(b * CH + h)) * CS;
    float mx = -1e30f;
    for (int s = tid; s < CS; s += 256) mx = fmaxf(mx, pr[s]);
    red[tid] = mx; __syncthreads();
    #pragma unroll
    for (int o = 128; o > 0; o >>= 1) {
        if (tid < o) red[tid] = fmaxf(red[tid], red[tid + o]);
        __syncthreads();
    }
    mx = red[0]; __syncthreads();
    float sm = 0.f;
    for (int s = tid; s < CS; s += 256) {
        float e = __expf(pr[s] - mx);
        pr[s] = e; sm += e;
    }
    float tot = block_reduce_sum256(sm, red);
    float inv = 1.0f / tot;
    for (int s = tid; s < CS; s += 256) pr[s] *= inv;
}

__global__ __launch_bounds__(256)
void u_kernel(const float* __restrict__ p,
              const float* __restrict__ x,
              float* __restrict__ u) {
    __shared__ float xs[128][64];
    __shared__ float ps[CH][128];
    int kc = blockIdx.x, b = blockIdx.y;
    int k0 = kc * 64;
    int tid = threadIdx.x;
    int kl = tid & 63, h0 = tid >> 6;
    float acc[3] = {0.f, 0.f, 0.f};
    for (int st = 0; st < CS / 128; st++) {
        __syncthreads();
        #pragma unroll
        for (int i = 0; i < 32; i++) {
            int idx = i * 256 + tid;
            int r = idx >> 6, c = idx & 63;
            xs[r][c] = x[((size_t)(b * CS + st * 128 + r)) * CDM + k0 + c];
        }
        #pragma unroll
        for (int i = 0; i < 6; i++) {
            int idx = i * 256 + tid;
            int hh = idx >> 7, ss = idx & 127;
            ps[hh][ss] = p[((size_t)(b * CH + hh)) * CS + st * 128 + ss];
        }
        __syncthreads();
        for (int s = 0; s < 128; s++) {
            float xv = xs[s][kl];
            acc[0] += ps[h0][s] * xv;
            acc[1] += ps[h0 + 4][s] * xv;
            acc[2] += ps[h0 + 8][s] * xv;
        }
    }
    u[(b * CH + h0) * CDM + k0 + kl]       = acc[0];
    u[(b * CH + h0 + 4) * CDM + k0 + kl]   = acc[1];
    u[(b * CH + h0 + 8) * CDM + k0 + kl]   = acc[2];
}

__global__ void og_kernel(const float* __restrict__ u,
                          const float* __restrict__ Wvg,
                          const float* __restrict__ bvg,
                          __half* __restrict__ outh,
                          __half* __restrict__ outl) {
    int h = blockIdx.x, b = blockIdx.y;
    int d = threadIdx.x;
    const float* up = u + (b * CH + h) * CDM;
    float acc = bvg[h * 64 + d];
    for (int k = 0; k < CDM; k++)
        acc += up[k] * Wvg[(size_t)k * CDM + h * 64 + d];
    __half hh, ll;
    hilo(acc, hh, ll);
    size_t ob = ((size_t)(b * CS)) * CDM + h * 64 + d;
    outh[ob] = hh;
    outl[ob] = ll;
}

__global__ void cls_kernel(const float* __restrict__ x,
                           const float* __restrict__ Wc,
                           const float* __restrict__ bc,
                           float* __restrict__ out) {
    __shared__ float red[256];
    int b = blockIdx.x >> 1, c = blockIdx.x & 1;
    int tid = threadIdx.x;
    const float* xr = x + (size_t)(b * CS) * CDM;
    float acc = 0.f;
    for (int d = tid; d < CDM; d += 256) acc += xr[d] * Wc[d * 2 + c];
    float tot = block_reduce_sum256(acc, red);
    if (tid == 0) out[b * 2 + c] = tot + bc[c];
}

// ================= launch =================
extern "C" void kernel_launch(void* const* d_in, const int* in_sizes, int n_in,
                              void* d_out, int out_size) {
    const int*   ids  = (const int*)d_in[0];
    const int*   am   = (const int*)d_in[1];
    const float* we   = (const float*)d_in[2];
    const float* pe   = (const float*)d_in[3];
    const float* lnes = (const float*)d_in[4];
    const float* lneb = (const float*)d_in[5];
    const float* Wq   = (const float*)d_in[6];
    const float* bq   = (const float*)d_in[7];
    const float* Wk   = (const float*)d_in[8];
    const float* bk   = (const float*)d_in[9];
    const float* Wv   = (const float*)d_in[10];
    const float* bv   = (const float*)d_in[11];
    const float* Wqg  = (const float*)d_in[12];
    const float* bqg  = (const float*)d_in[13];
    const float* Wkg  = (const float*)d_in[14];
    const float* bkg  = (const float*)d_in[15];
    const float* Wvg  = (const float*)d_in[16];
    const float* bvg  = (const float*)d_in[17];
    const float* Wo   = (const float*)d_in[18];
    const float* bo   = (const float*)d_in[19];
    const float* ln1s = (const float*)d_in[20];
    const float* ln1b = (const float*)d_in[21];
    const float* W1   = (const float*)d_in[22];
    const float* b1   = (const float*)d_in[23];
    const float* W2   = (const float*)d_in[24];
    const float* b2   = (const float*)d_in[25];
    const float* ln2s = (const float*)d_in[26];
    const float* ln2b = (const float*)d_in[27];
    const float* Wcls = (const float*)d_in[28];
    const float* bcls = (const float*)d_in[29];
    float* out = (float*)d_out;

    float *xp, *yp, *qkvp, *qgp, *biasp, *tp, *pp, *up;
    __half *xhp, *xlp, *ahp, *alp, *hhp, *hlp, *whp, *wlp;
    cudaGetSymbolAddress((void**)&xp,   g_x);
    cudaGetSymbolAddress((void**)&yp,   g_y);
    cudaGetSymbolAddress((void**)&qkvp, g_qkv);
    cudaGetSymbolAddress((void**)&qgp,  g_qg);
    cudaGetSymbolAddress((void**)&biasp, g_bias);
    cudaGetSymbolAddress((void**)&tp,   g_t);
    cudaGetSymbolAddress((void**)&pp,   g_p);
    cudaGetSymbolAddress((void**)&up,   g_u);
    cudaGetSymbolAddress((void**)&xhp,  g_xbh);
    cudaGetSymbolAddress((void**)&xlp,  g_xbl);
    cudaGetSymbolAddress((void**)&ahp,  g_abh);
    cudaGetSymbolAddress((void**)&alp,  g_abl);
    cudaGetSymbolAddress((void**)&hhp,  g_hbh);
    cudaGetSymbolAddress((void**)&hlp,  g_hbl);
    cudaGetSymbolAddress((void**)&whp,  g_wbh);
    cudaGetSymbolAddress((void**)&wlp,  g_wbl);

    cudaFuncSetAttribute(gemm_mma_kernel, cudaFuncAttributeMaxDynamicSharedMemorySize, GSM_TOT);
    cudaFuncSetAttribute(flash_band_kernel, cudaFuncAttributeMaxDynamicSharedMemorySize, FB_TOT);

    embed_ln_kernel<<<MROWS, 256>>>(ids, we, pe, lnes, lneb, xp, xhp, xlp);

    dim3 wt_dm(CDM / 32, CDM / 32);
    dim3 wt_b(32, 8);
    size_t wseg = (size_t)CDM * CDM;

    for (int l = 0; l < CL; l++) {
        size_t woff = (size_t)l * CDM * CDM;
        size_t boff = (size_t)l * CDM;
        size_t w1off = (size_t)l * CDM * CDFF;
        size_t b1off = (size_t)l * CDFF;
        size_t w2off = (size_t)l * CDFF * CDM;

        // --- fused QKV GEMM (3-term) ---
        split_wt_kernel<<<wt_dm, wt_b>>>(Wq + woff, whp,            wlp,            CDM, CDM);
        split_wt_kernel<<<wt_dm, wt_b>>>(Wk + woff, whp + wseg,     wlp + wseg,     CDM, CDM);
        split_wt_kernel<<<wt_dm, wt_b>>>(Wv + woff, whp + 2 * wseg, wlp + 2 * wseg, CDM, CDM);
        pack_bias_kernel<<<9, 256>>>(biasp, bq + boff, bk + boff, bv + boff);
        gemm_mma_kernel<<<dim3(QKV_S / 128, MROWS / 128), 256, GSM_TOT>>>(
            xhp, xlp, whp, wlp, biasp, qkvp, nullptr, nullptr, CDM, QKV_S, 0, 3);

        flash_band_kernel<<<dim3(4, CB * CH * CNB), 128, FB_TOT>>>(qkvp, am, ahp, alp);

        // --- factored global attention (fp32, no GEMM) ---
        qg_kernel<<<dim3(CDM / 256, CB), 256>>>(xp, Wqg + woff, bqg + boff, qgp);
        tk_kernel<<<dim3(CDM / 128, CH, CB), 128>>>(Wkg + woff, qgp, tp);
        sgl_kernel<<<dim3(CS / 8, CB), 256>>>(xp, tp, am, pp);
        softmax_p_kernel<<<dim3(CH, CB), 256>>>(pp);
        u_kernel<<<dim3(CDM / 64, CB), 256>>>(pp, xp, up);
        og_kernel<<<dim3(CH, CB), 64>>>(up, Wvg + woff, bvg + boff, ahp, alp);

        // --- Wo projection (3-term) + LN1 ---
        split_wt_kernel<<<wt_dm, wt_b>>>(Wo + woff, whp, wlp, CDM, CDM);
        gemm_mma_kernel<<<dim3(CDM / 128, MROWS / 128), 256, GSM_TOT>>>(
            ahp, alp, whp, wlp, bo + boff, yp, nullptr, nullptr, CDM, CDM, 0, 3);
        add_ln_kernel<<<MROWS, 256>>>(xp, yp, ln1s + boff, ln1b + boff, xhp, xlp);

        // --- FFN (2-term fp16) ---
        split_wt_kernel<<<dim3(CDFF / 32, CDM / 32), wt_b>>>(W1 + w1off, whp, wlp, CDM, CDFF);
        gemm_mma_kernel<<<dim3(CDFF / 128, MROWS / 128), 256, GSM_TOT>>>(
            xhp, xlp, whp, wlp, b1 + b1off, nullptr, hhp, hlp, CDM, CDFF, 2, 2);

        split_wt_kernel<<<dim3(CDM / 32, CDFF / 32), wt_b>>>(W2 + w2off, whp, wlp, CDFF, CDM);
        gemm_mma_kernel<<<dim3(CDM / 128, MROWS / 128), 256, GSM_TOT>>>(
            hhp, hlp, whp, wlp, b2 + boff, yp, nullptr, nullptr, CDFF, CDM, 0, 2);
        add_ln_kernel<<<MROWS, 256>>>(xp, yp, ln2s + boff, ln2b + boff, xhp, xlp);
    }

    cls_kernel<<<4, 256>>>(xp, Wcls, bcls, out);
}